// round 9
// baseline (speedup 1.0000x reference)
#include <cuda_runtime.h>
#include <cuda_bf16.h>
#include <cstdint>

// ---------------- problem constants ----------------
#define Hh 256
#define Ww 256
#define Bb 4
#define Cc 192
#define NHEAD 6
#define NWIN 4096
#define NTOK 64
#define TOKALL (Bb*Hh*Ww)
#define WINELEM (NTOK*Cc)

// weight-split offsets (elements)
#define OQ  0
#define OKV 36864
#define OP  110592
#define OM  147456
#define OF1 184320
#define OF2 331776
#define WTOT 479232

// ---------------- device scratch ----------------
__device__ float g_xt[(size_t)TOKALL * Cc];
__device__ float g_ft[(size_t)TOKALL * Cc];
__device__ float g_q [(size_t)NWIN * WINELEM];
__device__ float g_k [(size_t)NWIN * WINELEM];
__device__ float g_v [(size_t)NWIN * WINELEM];
__device__ float g_o [(size_t)NWIN * WINELEM];
__device__ float g_x1[(size_t)TOKALL * Cc];
__device__ float g_bias[NHEAD * NTOK * NTOK];
__device__ __align__(16) __nv_bfloat16 g_wh[WTOT];
__device__ __align__(16) __nv_bfloat16 g_wl[WTOT];

// ---------------- helpers ----------------
__device__ __forceinline__ float gelu_fast(float x) {
    float z = x * 0.7071067811865475f;
    float az = fabsf(z);
    float t = __fdividef(1.0f, fmaf(0.3275911f, az, 1.0f));
    float p = t * (0.254829592f + t * (-0.284496736f + t * (1.421413741f +
              t * (-1.453152027f + t * 1.061405429f))));
    float e = __expf(-az * az);
    float erfv = 1.0f - p * e;
    erfv = copysignf(erfv, z);
    return 0.5f * x * (1.0f + erfv);
}

__device__ __forceinline__ uint32_t smem_u32(const void* p) {
    uint32_t a;
    asm("{ .reg .u64 t; cvta.to.shared.u64 t, %1; cvt.u32.u64 %0, t; }" : "=r"(a) : "l"(p));
    return a;
}

__device__ __forceinline__ void split2(float v0, float v1, uint32_t& hp, uint32_t& lp) {
    __nv_bfloat16 h0 = __float2bfloat16(v0);
    __nv_bfloat16 h1 = __float2bfloat16(v1);
    __nv_bfloat16 l0 = __float2bfloat16(v0 - __bfloat162float(h0));
    __nv_bfloat16 l1 = __float2bfloat16(v1 - __bfloat162float(h1));
    hp = (uint32_t)__bfloat16_as_ushort(h0) | ((uint32_t)__bfloat16_as_ushort(h1) << 16);
    lp = (uint32_t)__bfloat16_as_ushort(l0) | ((uint32_t)__bfloat16_as_ushort(l1) << 16);
}

__device__ __forceinline__ void ldsm_x4(uint32_t (&r)[4], uint32_t a) {
    asm volatile("ldmatrix.sync.aligned.m8n8.x4.shared.b16 {%0,%1,%2,%3}, [%4];"
        : "=r"(r[0]), "=r"(r[1]), "=r"(r[2]), "=r"(r[3]) : "r"(a));
}

__device__ __forceinline__ void mma16816(float (&c)[4], const uint32_t (&a)[4],
                                         uint32_t b0, uint32_t b1) {
    asm volatile("mma.sync.aligned.m16n8k16.row.col.f32.bf16.bf16.f32 "
        "{%0,%1,%2,%3}, {%4,%5,%6,%7}, {%8,%9}, {%0,%1,%2,%3};"
        : "+f"(c[0]), "+f"(c[1]), "+f"(c[2]), "+f"(c[3])
        : "r"(a[0]), "r"(a[1]), "r"(a[2]), "r"(a[3]), "r"(b0), "r"(b1));
}

// Warp GEMM: C[16][NT2*16] += A[16][KS*16] @ W^T with bf16 hi/lo split (3 terms).
// All fragments for a k-step are loaded first, then MMAs are issued round-robin
// across all 2*NT2 accumulators so same-accumulator reuse distance is 2*NT2
// (>= MMA latency at NT2>=2) instead of 1. Per-accumulator FP order unchanged.
template<int KS, int NT2, int AS, int WS>
__device__ __forceinline__ void wgemm(uint32_t aH, uint32_t aL,
                                      uint32_t wH, uint32_t wL,
                                      float (*c)[4], int lane) {
    const uint32_t aoff = (uint32_t)(((lane & 15) * AS + ((lane >> 4) << 3)) * 2);
    const uint32_t woff = (uint32_t)(((((lane >> 4) << 3) + (lane & 7)) * WS + (lane & 8)) * 2);
    aH += aoff; aL += aoff; wH += woff; wL += woff;
    #pragma unroll
    for (int ks = 0; ks < KS; ++ks) {
        uint32_t ah[4], al[4];
        uint32_t bh[NT2][4], bl[NT2][4];
        ldsm_x4(ah, aH + ks * 32);
        ldsm_x4(al, aL + ks * 32);
        #pragma unroll
        for (int p = 0; p < NT2; ++p) {
            ldsm_x4(bh[p], wH + p * (16 * WS * 2) + ks * 32);
            ldsm_x4(bl[p], wL + p * (16 * WS * 2) + ks * 32);
        }
        // term 1: ah * bh   (round-robin over all accumulators)
        #pragma unroll
        for (int p = 0; p < NT2; ++p) {
            mma16816(c[2*p],   ah, bh[p][0], bh[p][1]);
            mma16816(c[2*p+1], ah, bh[p][2], bh[p][3]);
        }
        // term 2: al * bh
        #pragma unroll
        for (int p = 0; p < NT2; ++p) {
            mma16816(c[2*p],   al, bh[p][0], bh[p][1]);
            mma16816(c[2*p+1], al, bh[p][2], bh[p][3]);
        }
        // term 3: ah * bl
        #pragma unroll
        for (int p = 0; p < NT2; ++p) {
            mma16816(c[2*p],   ah, bl[p][0], bl[p][1]);
            mma16816(c[2*p+1], ah, bl[p][2], bl[p][3]);
        }
    }
}

// ---------------- cp.async helpers ----------------
__device__ __forceinline__ void cp16(uint32_t d, const void* s) {
    asm volatile("cp.async.cg.shared.global [%0], [%1], 16;" :: "r"(d), "l"(s) : "memory");
}
__device__ __forceinline__ void cp_commit() {
    asm volatile("cp.async.commit_group;" ::: "memory");
}
__device__ __forceinline__ void cp_wait0() {
    asm volatile("cp.async.wait_group 0;" ::: "memory");
}

// async-stage a pre-split weight tile (hi+lo) into smem (512-thread CTAs)
__device__ __forceinline__ void cpstageW(uint32_t dh, uint32_t dl,
        const __nv_bfloat16* sh, const __nv_bfloat16* sl,
        int rows, int ku4, int srck, int koff, int dstride, int tid) {
    int tot = rows * ku4;
    for (int i = tid; i < tot; i += 512) {
        int r = i / ku4, q = i - r * ku4;
        size_t s = (size_t)r * srck + koff + q * 8;
        uint32_t d = (uint32_t)(r * dstride + q * 8) * 2;
        cp16(dh + d, sh + s);
        cp16(dl + d, sl + s);
    }
    cp_commit();
}

// stage fp32 activations -> split bf16 hi/lo smem (stride 200), 512 threads
__device__ __forceinline__ void stage_linear(char* dh, char* dl, const float* src, int tid) {
    for (int i = tid; i < 128 * 96; i += 512) {
        int r = i / 96, cp = (i - r * 96) * 2;
        float2 v = *(const float2*)(src + (size_t)r * 192 + cp);
        uint32_t hp, lp; split2(v.x, v.y, hp, lp);
        size_t d = ((size_t)r * 200 + cp) * 2;
        *(uint32_t*)(dh + d) = hp;
        *(uint32_t*)(dl + d) = lp;
    }
}

// stage with shifted-window gather (roll -4), 2 windows per CTA, 512 threads
__device__ __forceinline__ void stage_gather(char* dh, char* dl, const float* src,
                                             int w0, int tid) {
    for (int i = tid; i < 128 * 96; i += 512) {
        int r = i / 96, cp = (i - r * 96) * 2;
        int win = w0 + (r >> 6);
        int b = win >> 10, wlr = win & 1023, wh = wlr >> 5, ww = wlr & 31;
        int n = r & 63, ii = n >> 3, jj = n & 7;
        int hh = (wh * 8 + ii + 4) & 255, wp = (ww * 8 + jj + 4) & 255;
        size_t off = (((size_t)b * 256 + hh) * 256 + wp) * 192 + cp;
        float2 v = *(const float2*)(src + off);
        uint32_t hp, lp; split2(v.x, v.y, hp, lp);
        size_t d = ((size_t)r * 200 + cp) * 2;
        *(uint32_t*)(dh + d) = hp;
        *(uint32_t*)(dl + d) = lp;
    }
}

// ---------------- kernel 0: NCHW -> NHWC ----------------
__global__ void k_transpose(const float* __restrict__ x, const float* __restrict__ f) {
    __shared__ float tile[32][33];
    int b = blockIdx.z >> 1;
    const float* src = (blockIdx.z & 1) ? f : x;
    float* dst = (blockIdx.z & 1) ? g_ft : g_xt;
    int hw0 = blockIdx.x * 32;
    int c0 = blockIdx.y * 32;
    #pragma unroll
    for (int i = threadIdx.y; i < 32; i += 8)
        tile[i][threadIdx.x] =
            src[((size_t)b * Cc + c0 + i) * (Hh * Ww) + hw0 + threadIdx.x];
    __syncthreads();
    #pragma unroll
    for (int i = threadIdx.y; i < 32; i += 8)
        dst[((size_t)b * (Hh * Ww) + hw0 + i) * Cc + c0 + threadIdx.x] =
            tile[threadIdx.x][i];
}

// ---------------- kernel 1: expand relative-position bias ----------------
__global__ void k_bias(const int* __restrict__ rel_index, const float* __restrict__ table) {
    int idx = blockIdx.x * blockDim.x + threadIdx.x;
    if (idx < NHEAD * NTOK * NTOK) {
        int h = idx / (NTOK * NTOK);
        int nm = idx % (NTOK * NTOK);
        g_bias[idx] = table[rel_index[nm] * NHEAD + h];
    }
}

// ---------------- kernel 1b: split ALL weights to bf16 hi/lo ----------------
__global__ void k_wsplit(const float* __restrict__ q_w, const float* __restrict__ kv_w,
                         const float* __restrict__ proj_w, const float* __restrict__ merge_w,
                         const float* __restrict__ fc1_w, const float* __restrict__ fc2_w) {
    int i = blockIdx.x * 256 + threadIdx.x;
    if (i >= WTOT) return;
    float v;
    if (i < OKV)       v = q_w[i];
    else if (i < OP)   v = kv_w[i - OKV];
    else if (i < OM)   v = proj_w[i - OP];
    else if (i < OF1)  v = merge_w[i - OM];
    else if (i < OF2)  v = fc1_w[i - OF1];
    else               v = fc2_w[i - OF2];
    __nv_bfloat16 h = __float2bfloat16(v);
    g_wh[i] = h;
    g_wl[i] = __float2bfloat16(v - __bfloat162float(h));
}

// ---------------- kernel 2: QKV projections (512 thr, 16 warps) ----------------
// smem: Ahi 0 Alo 51200 | WB0 hi 102400 lo 128000 | WB1 hi 153600 lo 179200
#define QKV_SMEM 204800
__global__ void __launch_bounds__(512, 1)
k_qkv_tc(const float* __restrict__ q_b, const float* __restrict__ kv_b) {
    extern __shared__ char smc[];
    const uint32_t sb = smem_u32(smc);
    char* A_HI = smc; char* A_LO = smc + 51200;
    const uint32_t WBh[2] = {sb + 102400, sb + 153600};
    const uint32_t WBl[2] = {sb + 128000, sb + 179200};
    int tid = threadIdx.x, wid = tid >> 5, lane = tid & 31;
    int rb = wid & 7, ch = wid >> 3;
    int gid = lane >> 2, tig = lane & 3;
    size_t tok0 = (size_t)blockIdx.x * 128;
    int w0 = blockIdx.x * 2;
    const uint32_t aW  = sb + (uint32_t)(rb * 6400);
    const uint32_t aWl = sb + 51200 + (uint32_t)(rb * 6400);
    const uint32_t wch = (uint32_t)(ch * 12800);   // 32 rows * 400B
    const float scale = 0.17677669529663687f;

    cpstageW(WBh[0], WBl[0], g_wh + OQ, g_wl + OQ, 64, 24, 192, 0, 200, tid);
    stage_gather(A_HI, A_LO, g_xt, w0, tid);

    for (int t = 0; t < 9; ++t) {
        cp_wait0();
        __syncthreads();
        if (t < 8) {
            int tn = t + 1;
            size_t off = (tn < 3) ? OQ + (size_t)tn * 64 * 192
                       : (tn < 6) ? OKV + (size_t)(tn - 3) * 64 * 192
                                  : OKV + 36864 + (size_t)(tn - 6) * 64 * 192;
            cpstageW(WBh[tn & 1], WBl[tn & 1], g_wh + off, g_wl + off,
                     64, 24, 192, 0, 200, tid);
        }
        if (t == 3) {
            stage_gather(A_HI, A_LO, g_ft, w0, tid);
            __syncthreads();
        }
        float c[4][4];
        #pragma unroll
        for (int i = 0; i < 4; ++i) { c[i][0]=c[i][1]=c[i][2]=c[i][3]=0.f; }
        wgemm<12, 2, 200, 200>(aW, aWl, WBh[t & 1] + wch, WBl[t & 1] + wch, c, lane);

        int g = t / 3, sub = t % 3;
        float* dst = (g == 0) ? g_q : (g == 1) ? g_k : g_v;
        const float* bias = (g == 0) ? q_b : (g == 1) ? kv_b : kv_b + 192;
        float sc = (g == 0) ? scale : 1.f;
        size_t rA = tok0 + rb * 16 + gid;
        #pragma unroll
        for (int nt = 0; nt < 4; ++nt) {
            int col = sub * 64 + ch * 32 + nt * 8 + 2 * tig;
            float2 o0 = make_float2((c[nt][0] + bias[col]) * sc, (c[nt][1] + bias[col+1]) * sc);
            float2 o1 = make_float2((c[nt][2] + bias[col]) * sc, (c[nt][3] + bias[col+1]) * sc);
            *(float2*)(dst + rA * 192 + col) = o0;
            *(float2*)(dst + (rA + 8) * 192 + col) = o1;
        }
    }
}

// ---------------- kernel 3: windowed attention (mma.sync, hi/lo split) ----------------
#define ATTN_SMEM 48128
__global__ void __launch_bounds__(128)
k_attn_tc(const float* __restrict__ mask) {
    extern __shared__ char smc[];
    const uint32_t sb = smem_u32(smc);
    char* c_QHI = smc;           char* c_QLO = smc + 5120;
    char* c_KHI = smc + 10240;   char* c_KLO = smc + 15360;
    char* c_VTH = smc + 20480;   char* c_VTL = smc + 25088;
    char* c_PHI = smc + 29696;   char* c_PLO = smc + 38912;
    int bx = blockIdx.x;
    int wi = bx & 4095;
    int h = bx >> 12;
    int wl = wi & 1023;
    int tid = threadIdx.x, wid = tid >> 5, lane = tid & 31;
    int gid = lane >> 2, tig = lane & 3;
    const size_t base = (size_t)wi * WINELEM + h * 32;

    for (int i = tid; i < 1024; i += 128) {
        int n = i >> 4, dp = (i & 15) * 2;
        float2 q2 = *(const float2*)(g_q + base + n * 192 + dp);
        float2 k2 = *(const float2*)(g_k + base + n * 192 + dp);
        uint32_t hp, lp;
        split2(q2.x, q2.y, hp, lp);
        *(uint32_t*)(c_QHI + (n * 40 + dp) * 2) = hp;
        *(uint32_t*)(c_QLO + (n * 40 + dp) * 2) = lp;
        split2(k2.x, k2.y, hp, lp);
        *(uint32_t*)(c_KHI + (n * 40 + dp) * 2) = hp;
        *(uint32_t*)(c_KLO + (n * 40 + dp) * 2) = lp;
        int key = i & 63, dq = (i >> 6) * 2;
        float2 v2 = *(const float2*)(g_v + base + key * 192 + dq);
        __nv_bfloat16 vh0 = __float2bfloat16(v2.x), vh1 = __float2bfloat16(v2.y);
        __nv_bfloat16 vl0 = __float2bfloat16(v2.x - __bfloat162float(vh0));
        __nv_bfloat16 vl1 = __float2bfloat16(v2.y - __bfloat162float(vh1));
        *(__nv_bfloat16*)(c_VTH + (dq * 72 + key) * 2) = vh0;
        *(__nv_bfloat16*)(c_VTH + ((dq + 1) * 72 + key) * 2) = vh1;
        *(__nv_bfloat16*)(c_VTL + (dq * 72 + key) * 2) = vl0;
        *(__nv_bfloat16*)(c_VTL + ((dq + 1) * 72 + key) * 2) = vl1;
    }
    __syncthreads();

    // QK^T: 16 rows per warp, all 64 keys (two NT2=2 calls, same math/mapping)
    float c[8][4];
    #pragma unroll
    for (int i = 0; i < 8; ++i) { c[i][0]=c[i][1]=c[i][2]=c[i][3]=0.f; }
    wgemm<2, 2, 40, 40>(sb + (uint32_t)(wid * 1280), sb + 5120 + (uint32_t)(wid * 1280),
                        sb + 10240, sb + 15360, c, lane);
    wgemm<2, 2, 40, 40>(sb + (uint32_t)(wid * 1280), sb + 5120 + (uint32_t)(wid * 1280),
                        sb + 10240 + 2560, sb + 15360 + 2560, c + 4, lane);

    int rA = wid * 16 + gid, rB = rA + 8;
    const float* bg = g_bias + h * 4096;
    const float* mg = mask + (size_t)wl * 4096;
    float vA[16], vB[16];
    #pragma unroll
    for (int nt = 0; nt < 8; ++nt) {
        int col = nt * 8 + 2 * tig;
        float2 b0 = *(const float2*)(bg + rA * 64 + col);
        float2 m0 = *(const float2*)(mg + rA * 64 + col);
        vA[2*nt]   = c[nt][0] + b0.x + m0.x;
        vA[2*nt+1] = c[nt][1] + b0.y + m0.y;
        float2 b1 = *(const float2*)(bg + rB * 64 + col);
        float2 m1 = *(const float2*)(mg + rB * 64 + col);
        vB[2*nt]   = c[nt][2] + b1.x + m1.x;
        vB[2*nt+1] = c[nt][3] + b1.y + m1.y;
    }
    float mxA = -1e30f, mxB = -1e30f;
    #pragma unroll
    for (int j = 0; j < 16; ++j) { mxA = fmaxf(mxA, vA[j]); mxB = fmaxf(mxB, vB[j]); }
    mxA = fmaxf(mxA, __shfl_xor_sync(0xffffffffu, mxA, 1));
    mxA = fmaxf(mxA, __shfl_xor_sync(0xffffffffu, mxA, 2));
    mxB = fmaxf(mxB, __shfl_xor_sync(0xffffffffu, mxB, 1));
    mxB = fmaxf(mxB, __shfl_xor_sync(0xffffffffu, mxB, 2));
    float sA = 0.f, sB = 0.f;
    #pragma unroll
    for (int j = 0; j < 16; ++j) {
        vA[j] = __expf(vA[j] - mxA); sA += vA[j];
        vB[j] = __expf(vB[j] - mxB); sB += vB[j];
    }
    sA += __shfl_xor_sync(0xffffffffu, sA, 1);
    sA += __shfl_xor_sync(0xffffffffu, sA, 2);
    sB += __shfl_xor_sync(0xffffffffu, sB, 1);
    sB += __shfl_xor_sync(0xffffffffu, sB, 2);
    float invA = 1.f / sA, invB = 1.f / sB;
    #pragma unroll
    for (int nt = 0; nt < 8; ++nt) {
        int col = nt * 8 + 2 * tig;
        uint32_t hp, lp;
        split2(vA[2*nt] * invA, vA[2*nt+1] * invA, hp, lp);
        *(uint32_t*)(c_PHI + (rA * 72 + col) * 2) = hp;
        *(uint32_t*)(c_PLO + (rA * 72 + col) * 2) = lp;
        split2(vB[2*nt] * invB, vB[2*nt+1] * invB, hp, lp);
        *(uint32_t*)(c_PHI + (rB * 72 + col) * 2) = hp;
        *(uint32_t*)(c_PLO + (rB * 72 + col) * 2) = lp;
    }
    __syncwarp();

    float o[4][4];
    #pragma unroll
    for (int i = 0; i < 4; ++i) { o[i][0]=o[i][1]=o[i][2]=o[i][3]=0.f; }
    wgemm<4, 2, 72, 72>(sb + 29696 + (uint32_t)(wid * 2304), sb + 38912 + (uint32_t)(wid * 2304),
                        sb + 20480, sb + 25088, o, lane);

    #pragma unroll
    for (int nt = 0; nt < 4; ++nt) {
        int col = nt * 8 + 2 * tig;
        *(float2*)(g_o + base + (size_t)rA * 192 + col) = make_float2(o[nt][0], o[nt][1]);
        *(float2*)(g_o + base + (size_t)rB * 192 + col) = make_float2(o[nt][2], o[nt][3]);
    }
}

// ---------------- kernel 4: proj -> merge -> LN -> residual (512 thr) ----------------
#define PM_SMEM 204800
__global__ void __launch_bounds__(512, 1)
k_projmerge_tc(const float* __restrict__ proj_b,
               const float* __restrict__ g1, const float* __restrict__ b1) {
    extern __shared__ char smc[];
    const uint32_t sb = smem_u32(smc);
    char* A_HI = smc; char* A_LO = smc + 51200;
    const uint32_t WBh[2] = {sb + 102400, sb + 153600};
    const uint32_t WBl[2] = {sb + 128000, sb + 179200};
    int tid = threadIdx.x, wid = tid >> 5, lane = tid & 31;
    int rb = wid & 7, ch = wid >> 3;
    int gid = lane >> 2, tig = lane & 3;
    size_t tok0 = (size_t)blockIdx.x * 128;
    const uint32_t aW  = sb + (uint32_t)(rb * 6400);
    const uint32_t aWl = sb + 51200 + (uint32_t)(rb * 6400);
    const uint32_t wch = (uint32_t)(ch * 12800);
    int lrA = rb * 16 + gid, lrB = lrA + 8;

    cpstageW(WBh[0], WBl[0], g_wh + OP, g_wl + OP, 64, 24, 192, 0, 200, tid);
    stage_linear(A_HI, A_LO, g_o + tok0 * 192, tid);

    float c1[12][4], c2[12][4];
    #pragma unroll
    for (int i = 0; i < 12; ++i) { c1[i][0]=c1[i][1]=c1[i][2]=c1[i][3]=0.f;
                                   c2[i][0]=c2[i][1]=c2[i][2]=c2[i][3]=0.f; }

    for (int t = 0; t < 6; ++t) {
        cp_wait0();
        __syncthreads();
        if (t < 5) {
            int tn = t + 1;
            size_t off = (tn < 3) ? OP + (size_t)tn * 64 * 192
                                  : OM + (size_t)(tn - 3) * 64 * 192;
            cpstageW(WBh[tn & 1], WBl[tn & 1], g_wh + off, g_wl + off,
                     64, 24, 192, 0, 200, tid);
        }
        if (t == 3) {
            // A <- split(Y): warp writes its rows x its 96 cols
            #pragma unroll
            for (int tt = 0; tt < 3; ++tt)
                #pragma unroll
                for (int nt = 0; nt < 4; ++nt) {
                    int col = tt * 64 + ch * 32 + nt * 8 + 2 * tig;
                    int i = tt * 4 + nt;
                    uint32_t hp, lp;
                    split2(c1[i][0] + proj_b[col], c1[i][1] + proj_b[col+1], hp, lp);
                    size_t dA = ((size_t)lrA * 200 + col) * 2;
                    *(uint32_t*)(A_HI + dA) = hp; *(uint32_t*)(A_LO + dA) = lp;
                    split2(c1[i][2] + proj_b[col], c1[i][3] + proj_b[col+1], hp, lp);
                    size_t dB = ((size_t)lrB * 200 + col) * 2;
                    *(uint32_t*)(A_HI + dB) = hp; *(uint32_t*)(A_LO + dB) = lp;
                }
            __syncthreads();   // partner warp's cols must land before merge GEMM
        }
        float (*cc)[4] = (t < 3) ? (c1 + t * 4) : (c2 + (t - 3) * 4);
        wgemm<12, 2, 200, 200>(aW, aWl, WBh[t & 1] + wch, WBl[t & 1] + wch, cc, lane);
    }

    // LN: cross-warp-pair partial reduce via smem (reuse dead W region)
    float sA = 0.f, qA = 0.f, sB = 0.f, qB = 0.f;
    #pragma unroll
    for (int i = 0; i < 12; ++i) {
        sA += c2[i][0] + c2[i][1];
        qA += c2[i][0]*c2[i][0] + c2[i][1]*c2[i][1];
        sB += c2[i][2] + c2[i][3];
        qB += c2[i][2]*c2[i][2] + c2[i][3]*c2[i][3];
    }
    #pragma unroll
    for (int d = 1; d <= 2; d <<= 1) {
        sA += __shfl_xor_sync(0xffffffffu, sA, d);
        qA += __shfl_xor_sync(0xffffffffu, qA, d);
        sB += __shfl_xor_sync(0xffffffffu, sB, d);
        qB += __shfl_xor_sync(0xffffffffu, qB, d);
    }
    float2* red = (float2*)(smc + 102400);  // [ch][row] -> (s,q)
    __syncthreads();
    if (tig == 0) {
        red[ch * 128 + lrA] = make_float2(sA, qA);
        red[ch * 128 + lrB] = make_float2(sB, qB);
    }
    __syncthreads();
    float2 pA0 = red[lrA], pA1 = red[128 + lrA];
    float2 pB0 = red[lrB], pB1 = red[128 + lrB];
    float muA = (pA0.x + pA1.x) * (1.f/192.f);
    float rsA = rsqrtf((pA0.y + pA1.y) * (1.f/192.f) - muA*muA + 1e-5f);
    float muB = (pB0.x + pB1.x) * (1.f/192.f);
    float rsB = rsqrtf((pB0.y + pB1.y) * (1.f/192.f) - muB*muB + 1e-5f);

    auto rowoff = [&](int lr) -> size_t {
        int win = blockIdx.x * 2 + (lr >> 6);
        int b = win >> 10, wlr = win & 1023, wh = wlr >> 5, ww = wlr & 31;
        int n = lr & 63, ii = n >> 3, jj = n & 7;
        int hf = (wh * 8 + ii + 4) & 255, wf = (ww * 8 + jj + 4) & 255;
        return (((size_t)b * 256 + hf) * 256 + wf) * 192;
    };
    size_t roA = rowoff(lrA), roB = rowoff(lrB);

    #pragma unroll
    for (int tt = 0; tt < 3; ++tt)
        #pragma unroll
        for (int nt = 0; nt < 4; ++nt) {
            int col = tt * 64 + ch * 32 + nt * 8 + 2 * tig;
            int i = tt * 4 + nt;
            float2 xa = *(const float2*)(g_xt + roA + col);
            float2 za;
            za.x = xa.x + (c2[i][0] - muA) * rsA * g1[col]   + b1[col];
            za.y = xa.y + (c2[i][1] - muA) * rsA * g1[col+1] + b1[col+1];
            *(float2*)(g_x1 + roA + col) = za;
            float2 xb = *(const float2*)(g_xt + roB + col);
            float2 zb;
            zb.x = xb.x + (c2[i][2] - muB) * rsB * g1[col]   + b1[col];
            zb.y = xb.y + (c2[i][3] - muB) * rsB * g1[col+1] + b1[col+1];
            *(float2*)(g_x1 + roB + col) = zb;
        }
}

// ---------------- kernel 5: MLP + LN + residual (512 thr, 4-phase pipeline) ----------------
// smem: Ahi 0 Alo 51200 | Hhi 102400 Hlo 120832 |
//       WB0 hi 139264 lo 153088 | WB1 hi 166912 lo 180736   (slot hi cap 13824)
#define MLP_SMEM 194560
__global__ void __launch_bounds__(512, 1)
k_mlp_tc(const float* __restrict__ fc1_b, const float* __restrict__ fc2_b,
         const float* __restrict__ g2, const float* __restrict__ b2,
         float* __restrict__ out) {
    extern __shared__ char smc[];
    const uint32_t sb = smem_u32(smc);
    char* A_HI = smc; char* A_LO = smc + 51200;
    char* H_HI = smc + 102400; char* H_LO = smc + 120832;
    const uint32_t WBh[2] = {sb + 139264, sb + 166912};
    const uint32_t WBl[2] = {sb + 153088, sb + 180736};
    int tid = threadIdx.x, wid = tid >> 5, lane = tid & 31;
    int rb = wid & 7, ch = wid >> 3;
    int gid = lane >> 2, tig = lane & 3;
    size_t tok0 = (size_t)blockIdx.x * 128;
    const uint32_t aW  = sb + (uint32_t)(rb * 6400);
    const uint32_t aWl = sb + 51200 + (uint32_t)(rb * 6400);
    const uint32_t hW  = sb + 102400 + (uint32_t)(rb * 16 * 144);
    const uint32_t hWl = sb + 120832 + (uint32_t)(rb * 16 * 144);
    const uint32_t w1ch = (uint32_t)(ch * 6656);   // 32 rows * 208B
    const uint32_t w2ch = (uint32_t)(ch * 6912);   // 48 rows * 144B
    int lrA = rb * 16 + gid, lrB = lrA + 8;

    cpstageW(WBh[0], WBl[0], g_wh + OF1, g_wl + OF1, 64, 12, 192, 0, 104, tid);
    stage_linear(A_HI, A_LO, g_x1 + tok0 * 192, tid);

    float cf2[12][4];
    #pragma unroll
    for (int i = 0; i < 12; ++i) { cf2[i][0]=cf2[i][1]=cf2[i][2]=cf2[i][3]=0.f; }
    float c1[4][4];

    for (int pidx = 0; pidx < 48; ++pidx) {
        int ck = pidx >> 2, ph = pidx & 3;
        cp_wait0();
        __syncthreads();
        int np = pidx + 1, nck = np >> 2, nph = np & 3;
        if (nck < 12) {
            int par = np & 1;
            if (nph < 2)
                cpstageW(WBh[par], WBl[par],
                         g_wh + OF1 + (size_t)nck * 64 * 192,
                         g_wl + OF1 + (size_t)nck * 64 * 192,
                         64, 12, 192, nph * 96, 104, tid);
            else
                cpstageW(WBh[par], WBl[par],
                         g_wh + OF2 + (size_t)(nph - 2) * 96 * 768,
                         g_wl + OF2 + (size_t)(nph - 2) * 96 * 768,
                         96, 8, 768, nck * 64, 72, tid);
        }
        int par = pidx & 1;
        if (ph < 2) {
            if (ph == 0) {
                #pragma unroll
                for (int i = 0; i < 4; ++i) { c1[i][0]=c1[i][1]=c1[i][2]=c1[i][3]=0.f; }
            }
            // fc1 K-half: A k-offset ph*96 elems (192B), W1 tile 64x96 @ stride 104
            wgemm<6, 2, 200, 104>(aW + ph * 192, aWl + ph * 192,
                                  WBh[par] + w1ch, WBl[par] + w1ch, c1, lane);
            if (ph == 1) {
                #pragma unroll
                for (int nt = 0; nt < 4; ++nt) {
                    int col = ch * 32 + nt * 8 + 2 * tig;
                    int bc = ck * 64 + col;
                    uint32_t hp, lp;
                    split2(gelu_fast(c1[nt][0] + fc1_b[bc]),
                           gelu_fast(c1[nt][1] + fc1_b[bc+1]), hp, lp);
                    size_t dA = ((size_t)lrA * 72 + col) * 2;
                    *(uint32_t*)(H_HI + dA) = hp; *(uint32_t*)(H_LO + dA) = lp;
                    split2(gelu_fast(c1[nt][2] + fc1_b[bc]),
                           gelu_fast(c1[nt][3] + fc1_b[bc+1]), hp, lp);
                    size_t dB = ((size_t)lrB * 72 + col) * 2;
                    *(uint32_t*)(H_HI + dB) = hp; *(uint32_t*)(H_LO + dB) = lp;
                }
            }
        } else {
            // fc2 tile (96 output rows): warp covers ch*48..+48 within tile
            wgemm<4, 3, 72, 72>(hW, hWl, WBh[par] + w2ch, WBl[par] + w2ch,
                                cf2 + (ph - 2) * 6, lane);
        }
    }

    // LN + residual (cross-warp-pair reduce via smem)
    float sA = 0.f, qA = 0.f, sB = 0.f, qB = 0.f;
    float zr[12][4];
    #pragma unroll
    for (int p = 0; p < 2; ++p)
        #pragma unroll
        for (int nt = 0; nt < 6; ++nt) {
            int col = p * 96 + ch * 48 + nt * 8 + 2 * tig;
            int i = p * 6 + nt;
            zr[i][0] = cf2[i][0] + fc2_b[col];
            zr[i][1] = cf2[i][1] + fc2_b[col+1];
            zr[i][2] = cf2[i][2] + fc2_b[col];
            zr[i][3] = cf2[i][3] + fc2_b[col+1];
            sA += zr[i][0] + zr[i][1]; qA += zr[i][0]*zr[i][0] + zr[i][1]*zr[i][1];
            sB += zr[i][2] + zr[i][3]; qB += zr[i][2]*zr[i][2] + zr[i][3]*zr[i][3];
        }
    #pragma unroll
    for (int d = 1; d <= 2; d <<= 1) {
        sA += __shfl_xor_sync(0xffffffffu, sA, d);
        qA += __shfl_xor_sync(0xffffffffu, qA, d);
        sB += __shfl_xor_sync(0xffffffffu, sB, d);
        qB += __shfl_xor_sync(0xffffffffu, qB, d);
    }
    float2* red = (float2*)(smc + 139264);
    __syncthreads();
    if (tig == 0) {
        red[ch * 128 + lrA] = make_float2(sA, qA);
        red[ch * 128 + lrB] = make_float2(sB, qB);
    }
    __syncthreads();
    float2 pA0 = red[lrA], pA1 = red[128 + lrA];
    float2 pB0 = red[lrB], pB1 = red[128 + lrB];
    float muA = (pA0.x + pA1.x) * (1.f/192.f);
    float rsA = rsqrtf((pA0.y + pA1.y) * (1.f/192.f) - muA*muA + 1e-5f);
    float muB = (pB0.x + pB1.x) * (1.f/192.f);
    float rsB = rsqrtf((pB0.y + pB1.y) * (1.f/192.f) - muB*muB + 1e-5f);

    size_t grA = (tok0 + lrA) * 192, grB = (tok0 + lrB) * 192;
    #pragma unroll
    for (int p = 0; p < 2; ++p)
        #pragma unroll
        for (int nt = 0; nt < 6; ++nt) {
            int col = p * 96 + ch * 48 + nt * 8 + 2 * tig;
            int i = p * 6 + nt;
            float2 xa = *(const float2*)(g_x1 + grA + col);
            float2 oa;
            oa.x = xa.x + (zr[i][0] - muA) * rsA * g2[col]   + b2[col];
            oa.y = xa.y + (zr[i][1] - muA) * rsA * g2[col+1] + b2[col+1];
            *(float2*)(out + grA + col) = oa;
            float2 xb = *(const float2*)(g_x1 + grB + col);
            float2 ob;
            ob.x = xb.x + (zr[i][2] - muB) * rsB * g2[col]   + b2[col];
            ob.y = xb.y + (zr[i][3] - muB) * rsB * g2[col+1] + b2[col+1];
            *(float2*)(out + grB + col) = ob;
        }
}

// ---------------- launch ----------------
extern "C" void kernel_launch(void* const* d_in, const int* in_sizes, int n_in,
                              void* d_out, int out_size) {
    const float* x        = (const float*)d_in[0];
    const float* feat     = (const float*)d_in[1];
    const float* attn_mask= (const float*)d_in[2];
    const int*   rel_index= (const int*)  d_in[3];
    const float* rel_tab  = (const float*)d_in[4];
    const float* q_w      = (const float*)d_in[5];
    const float* q_b      = (const float*)d_in[6];
    const float* kv_w     = (const float*)d_in[7];
    const float* kv_b     = (const float*)d_in[8];
    const float* proj_w   = (const float*)d_in[9];
    const float* proj_b   = (const float*)d_in[10];
    const float* merge_w  = (const float*)d_in[11];
    const float* n1g      = (const float*)d_in[12];
    const float* n1b      = (const float*)d_in[13];
    const float* n2g      = (const float*)d_in[14];
    const float* n2b      = (const float*)d_in[15];
    const float* fc1_w    = (const float*)d_in[16];
    const float* fc1_b    = (const float*)d_in[17];
    const float* fc2_w    = (const float*)d_in[18];
    const float* fc2_b    = (const float*)d_in[19];
    float* out = (float*)d_out;

    cudaFuncSetAttribute(k_qkv_tc,       cudaFuncAttributeMaxDynamicSharedMemorySize, QKV_SMEM);
    cudaFuncSetAttribute(k_attn_tc,      cudaFuncAttributeMaxDynamicSharedMemorySize, ATTN_SMEM);
    cudaFuncSetAttribute(k_projmerge_tc, cudaFuncAttributeMaxDynamicSharedMemorySize, PM_SMEM);
    cudaFuncSetAttribute(k_mlp_tc,       cudaFuncAttributeMaxDynamicSharedMemorySize, MLP_SMEM);

    k_transpose<<<dim3(2048, 6, 8), dim3(32, 8)>>>(x, feat);
    k_bias<<<96, 256>>>(rel_index, rel_tab);
    k_wsplit<<<(WTOT + 255) / 256, 256>>>(q_w, kv_w, proj_w, merge_w, fc1_w, fc2_w);
    k_qkv_tc<<<2048, 512, QKV_SMEM>>>(q_b, kv_b);
    k_attn_tc<<<NWIN * NHEAD, 128, ATTN_SMEM>>>(attn_mask);
    k_projmerge_tc<<<2048, 512, PM_SMEM>>>(proj_b, n1g, n1b);
    k_mlp_tc<<<2048, 512, MLP_SMEM>>>(fc1_b, fc2_b, n2g, n2b, out);
}

// round 10
// speedup vs baseline: 2.2147x; 2.2147x over previous
#include <cuda_runtime.h>
#include <cuda_bf16.h>
#include <cstdint>

// ---------------- problem constants ----------------
#define Hh 256
#define Ww 256
#define Bb 4
#define Cc 192
#define NHEAD 6
#define NWIN 4096
#define NTOK 64
#define TOKALL (Bb*Hh*Ww)
#define WINELEM (NTOK*Cc)

// weight-split offsets (elements)
#define OQ  0
#define OKV 36864
#define OP  110592
#define OM  147456
#define OF1 184320
#define OF2 331776
#define WTOT 479232

// ---------------- device scratch ----------------
__device__ float g_xt[(size_t)TOKALL * Cc];
__device__ float g_ft[(size_t)TOKALL * Cc];
__device__ float g_q [(size_t)NWIN * WINELEM];
__device__ float g_k [(size_t)NWIN * WINELEM];
__device__ float g_v [(size_t)NWIN * WINELEM];
__device__ float g_o [(size_t)NWIN * WINELEM];
__device__ float g_x1[(size_t)TOKALL * Cc];
__device__ float g_bias[NHEAD * NTOK * NTOK];
__device__ __align__(16) __nv_bfloat16 g_wh[WTOT];
__device__ __align__(16) __nv_bfloat16 g_wl[WTOT];

// ---------------- helpers ----------------
__device__ __forceinline__ float gelu_fast(float x) {
    float z = x * 0.7071067811865475f;
    float az = fabsf(z);
    float t = __fdividef(1.0f, fmaf(0.3275911f, az, 1.0f));
    float p = t * (0.254829592f + t * (-0.284496736f + t * (1.421413741f +
              t * (-1.453152027f + t * 1.061405429f))));
    float e = __expf(-az * az);
    float erfv = 1.0f - p * e;
    erfv = copysignf(erfv, z);
    return 0.5f * x * (1.0f + erfv);
}

__device__ __forceinline__ uint32_t smem_u32(const void* p) {
    uint32_t a;
    asm("{ .reg .u64 t; cvta.to.shared.u64 t, %1; cvt.u32.u64 %0, t; }" : "=r"(a) : "l"(p));
    return a;
}

__device__ __forceinline__ void split2(float v0, float v1, uint32_t& hp, uint32_t& lp) {
    __nv_bfloat16 h0 = __float2bfloat16(v0);
    __nv_bfloat16 h1 = __float2bfloat16(v1);
    __nv_bfloat16 l0 = __float2bfloat16(v0 - __bfloat162float(h0));
    __nv_bfloat16 l1 = __float2bfloat16(v1 - __bfloat162float(h1));
    hp = (uint32_t)__bfloat16_as_ushort(h0) | ((uint32_t)__bfloat16_as_ushort(h1) << 16);
    lp = (uint32_t)__bfloat16_as_ushort(l0) | ((uint32_t)__bfloat16_as_ushort(l1) << 16);
}

__device__ __forceinline__ void ldsm_x4(uint32_t (&r)[4], uint32_t a) {
    asm volatile("ldmatrix.sync.aligned.m8n8.x4.shared.b16 {%0,%1,%2,%3}, [%4];"
        : "=r"(r[0]), "=r"(r[1]), "=r"(r[2]), "=r"(r[3]) : "r"(a));
}

__device__ __forceinline__ void mma16816(float (&c)[4], const uint32_t (&a)[4],
                                         uint32_t b0, uint32_t b1) {
    asm volatile("mma.sync.aligned.m16n8k16.row.col.f32.bf16.bf16.f32 "
        "{%0,%1,%2,%3}, {%4,%5,%6,%7}, {%8,%9}, {%0,%1,%2,%3};"
        : "+f"(c[0]), "+f"(c[1]), "+f"(c[2]), "+f"(c[3])
        : "r"(a[0]), "r"(a[1]), "r"(a[2]), "r"(a[3]), "r"(b0), "r"(b1));
}

// R7 warp GEMM (original ordering; used by attn + mlp)
template<int KS, int NT2, int AS, int WS>
__device__ __forceinline__ void wgemm(uint32_t aH, uint32_t aL,
                                      uint32_t wH, uint32_t wL,
                                      float (*c)[4], int lane) {
    const uint32_t aoff = (uint32_t)(((lane & 15) * AS + ((lane >> 4) << 3)) * 2);
    const uint32_t woff = (uint32_t)(((((lane >> 4) << 3) + (lane & 7)) * WS + (lane & 8)) * 2);
    aH += aoff; aL += aoff; wH += woff; wL += woff;
    #pragma unroll
    for (int ks = 0; ks < KS; ++ks) {
        uint32_t ah[4], al[4];
        ldsm_x4(ah, aH + ks * 32);
        ldsm_x4(al, aL + ks * 32);
        #pragma unroll
        for (int p = 0; p < NT2; ++p) {
            uint32_t bh[4], bl[4];
            ldsm_x4(bh, wH + p * (16 * WS * 2) + ks * 32);
            ldsm_x4(bl, wL + p * (16 * WS * 2) + ks * 32);
            mma16816(c[2*p],   ah, bh[0], bh[1]);
            mma16816(c[2*p],   al, bh[0], bh[1]);
            mma16816(c[2*p],   ah, bl[0], bl[1]);
            mma16816(c[2*p+1], ah, bh[2], bh[3]);
            mma16816(c[2*p+1], al, bh[2], bh[3]);
            mma16816(c[2*p+1], ah, bl[2], bl[3]);
        }
    }
}

// v2 warp GEMM: M2 m-tiles x NT2 n-tiles (32x48 when M2=2,NT2=3). Accumulator
// reuse distance = 2*M2 within each term group; per-acc FP order unchanged.
template<int KS, int M2, int NT2, int AS, int WS>
__device__ __forceinline__ void wgemm2(uint32_t aH, uint32_t aL,
                                       uint32_t wH, uint32_t wL,
                                       float (*c)[4], int lane) {
    const uint32_t aoff = (uint32_t)(((lane & 15) * AS + ((lane >> 4) << 3)) * 2);
    const uint32_t woff = (uint32_t)(((((lane >> 4) << 3) + (lane & 7)) * WS + (lane & 8)) * 2);
    aH += aoff; aL += aoff; wH += woff; wL += woff;
    #pragma unroll
    for (int ks = 0; ks < KS; ++ks) {
        uint32_t ah[M2][4], al[M2][4];
        #pragma unroll
        for (int m = 0; m < M2; ++m) {
            ldsm_x4(ah[m], aH + m * (16 * AS * 2) + ks * 32);
            ldsm_x4(al[m], aL + m * (16 * AS * 2) + ks * 32);
        }
        #pragma unroll
        for (int p = 0; p < NT2; ++p) {
            uint32_t bh[4], bl[4];
            ldsm_x4(bh, wH + p * (16 * WS * 2) + ks * 32);
            ldsm_x4(bl, wL + p * (16 * WS * 2) + ks * 32);
            #pragma unroll
            for (int m = 0; m < M2; ++m) {
                mma16816(c[m*2*NT2 + p*2],     ah[m], bh[0], bh[1]);
                mma16816(c[m*2*NT2 + p*2 + 1], ah[m], bh[2], bh[3]);
            }
            #pragma unroll
            for (int m = 0; m < M2; ++m) {
                mma16816(c[m*2*NT2 + p*2],     al[m], bh[0], bh[1]);
                mma16816(c[m*2*NT2 + p*2 + 1], al[m], bh[2], bh[3]);
            }
            #pragma unroll
            for (int m = 0; m < M2; ++m) {
                mma16816(c[m*2*NT2 + p*2],     ah[m], bl[0], bl[1]);
                mma16816(c[m*2*NT2 + p*2 + 1], ah[m], bl[2], bl[3]);
            }
        }
    }
}

// ---------------- cp.async helpers ----------------
__device__ __forceinline__ void cp16(uint32_t d, const void* s) {
    asm volatile("cp.async.cg.shared.global [%0], [%1], 16;" :: "r"(d), "l"(s) : "memory");
}
__device__ __forceinline__ void cp_commit() {
    asm volatile("cp.async.commit_group;" ::: "memory");
}
__device__ __forceinline__ void cp_wait0() {
    asm volatile("cp.async.wait_group 0;" ::: "memory");
}

__device__ __forceinline__ void cpstageW(uint32_t dh, uint32_t dl,
        const __nv_bfloat16* sh, const __nv_bfloat16* sl,
        int rows, int ku4, int srck, int koff, int dstride, int tid) {
    int tot = rows * ku4;
    for (int i = tid; i < tot; i += 512) {
        int r = i / ku4, q = i - r * ku4;
        size_t s = (size_t)r * srck + koff + q * 8;
        uint32_t d = (uint32_t)(r * dstride + q * 8) * 2;
        cp16(dh + d, sh + s);
        cp16(dl + d, sl + s);
    }
    cp_commit();
}

__device__ __forceinline__ void stage_linear(char* dh, char* dl, const float* src, int tid) {
    for (int i = tid; i < 128 * 96; i += 512) {
        int r = i / 96, cp = (i - r * 96) * 2;
        float2 v = *(const float2*)(src + (size_t)r * 192 + cp);
        uint32_t hp, lp; split2(v.x, v.y, hp, lp);
        size_t d = ((size_t)r * 200 + cp) * 2;
        *(uint32_t*)(dh + d) = hp;
        *(uint32_t*)(dl + d) = lp;
    }
}

__device__ __forceinline__ void stage_gather(char* dh, char* dl, const float* src,
                                             int w0, int tid) {
    for (int i = tid; i < 128 * 96; i += 512) {
        int r = i / 96, cp = (i - r * 96) * 2;
        int win = w0 + (r >> 6);
        int b = win >> 10, wlr = win & 1023, wh = wlr >> 5, ww = wlr & 31;
        int n = r & 63, ii = n >> 3, jj = n & 7;
        int hh = (wh * 8 + ii + 4) & 255, wp = (ww * 8 + jj + 4) & 255;
        size_t off = (((size_t)b * 256 + hh) * 256 + wp) * 192 + cp;
        float2 v = *(const float2*)(src + off);
        uint32_t hp, lp; split2(v.x, v.y, hp, lp);
        size_t d = ((size_t)r * 200 + cp) * 2;
        *(uint32_t*)(dh + d) = hp;
        *(uint32_t*)(dl + d) = lp;
    }
}

// ---------------- kernel 0: NCHW -> NHWC ----------------
__global__ void k_transpose(const float* __restrict__ x, const float* __restrict__ f) {
    __shared__ float tile[32][33];
    int b = blockIdx.z >> 1;
    const float* src = (blockIdx.z & 1) ? f : x;
    float* dst = (blockIdx.z & 1) ? g_ft : g_xt;
    int hw0 = blockIdx.x * 32;
    int c0 = blockIdx.y * 32;
    #pragma unroll
    for (int i = threadIdx.y; i < 32; i += 8)
        tile[i][threadIdx.x] =
            src[((size_t)b * Cc + c0 + i) * (Hh * Ww) + hw0 + threadIdx.x];
    __syncthreads();
    #pragma unroll
    for (int i = threadIdx.y; i < 32; i += 8)
        dst[((size_t)b * (Hh * Ww) + hw0 + i) * Cc + c0 + threadIdx.x] =
            tile[threadIdx.x][i];
}

// ---------------- kernel 1: expand relative-position bias ----------------
__global__ void k_bias(const int* __restrict__ rel_index, const float* __restrict__ table) {
    int idx = blockIdx.x * blockDim.x + threadIdx.x;
    if (idx < NHEAD * NTOK * NTOK) {
        int h = idx / (NTOK * NTOK);
        int nm = idx % (NTOK * NTOK);
        g_bias[idx] = table[rel_index[nm] * NHEAD + h];
    }
}

// ---------------- kernel 1b: split ALL weights to bf16 hi/lo ----------------
__global__ void k_wsplit(const float* __restrict__ q_w, const float* __restrict__ kv_w,
                         const float* __restrict__ proj_w, const float* __restrict__ merge_w,
                         const float* __restrict__ fc1_w, const float* __restrict__ fc2_w) {
    int i = blockIdx.x * 256 + threadIdx.x;
    if (i >= WTOT) return;
    float v;
    if (i < OKV)       v = q_w[i];
    else if (i < OP)   v = kv_w[i - OKV];
    else if (i < OM)   v = proj_w[i - OP];
    else if (i < OF1)  v = merge_w[i - OM];
    else if (i < OF2)  v = fc1_w[i - OF1];
    else               v = fc2_w[i - OF2];
    __nv_bfloat16 h = __float2bfloat16(v);
    g_wh[i] = h;
    g_wl[i] = __float2bfloat16(v - __bfloat162float(h));
}

// ---------------- kernel 2: QKV (512 thr, 32x48 warp tiles, 192-col phases) ----------------
// smem: Ahi 0 Alo 51200 | WB0 hi 102400 lo 130048 | WB1 hi 157696 lo 185344 (end 212992)
#define QKV_SMEM 212992
__global__ void __launch_bounds__(512, 1)
k_qkv_tc(const float* __restrict__ q_b, const float* __restrict__ kv_b) {
    extern __shared__ char smc[];
    const uint32_t sb = smem_u32(smc);
    char* A_HI = smc; char* A_LO = smc + 51200;
    const uint32_t WBh[2] = {sb + 102400, sb + 157696};
    const uint32_t WBl[2] = {sb + 130048, sb + 185344};
    int tid = threadIdx.x, wid = tid >> 5, lane = tid & 31;
    int rb = wid & 3, cb = wid >> 2;
    int gid = lane >> 2, tig = lane & 3;
    size_t tok0 = (size_t)blockIdx.x * 128;
    int w0 = blockIdx.x * 2;
    const uint32_t aW  = sb + (uint32_t)(rb * 12800);           // 32 rows * 400B
    const uint32_t aWl = sb + 51200 + (uint32_t)(rb * 12800);
    const uint32_t wcb = (uint32_t)(cb * 6912);                 // 48 rows * 144B
    const float scale = 0.17677669529663687f;

    cpstageW(WBh[0], WBl[0], g_wh + OQ, g_wl + OQ, 192, 8, 192, 0, 72, tid);
    stage_gather(A_HI, A_LO, g_xt, w0, tid);

    float c[12][4];
    #pragma unroll
    for (int i = 0; i < 12; ++i) { c[i][0]=c[i][1]=c[i][2]=c[i][3]=0.f; }

    for (int t = 0; t < 9; ++t) {
        cp_wait0();
        __syncthreads();
        if (t < 8) {
            int tn = t + 1, g = tn / 3, kt = tn % 3;
            size_t off = (g == 0) ? OQ : (g == 1) ? OKV : OKV + 36864;
            cpstageW(WBh[tn & 1], WBl[tn & 1], g_wh + off, g_wl + off,
                     192, 8, 192, kt * 64, 72, tid);
        }
        if (t == 3) {
            stage_gather(A_HI, A_LO, g_ft, w0, tid);
            __syncthreads();
        }
        int kt = t % 3;
        wgemm2<4, 2, 3, 200, 72>(aW + kt * 128, aWl + kt * 128,
                                 WBh[t & 1] + wcb, WBl[t & 1] + wcb, c, lane);
        if (kt == 2) {
            int g = t / 3;
            float* dst = (g == 0) ? g_q : (g == 1) ? g_k : g_v;
            const float* bias = (g == 0) ? q_b : (g == 1) ? kv_b : kv_b + 192;
            float sc = (g == 0) ? scale : 1.f;
            #pragma unroll
            for (int m = 0; m < 2; ++m) {
                size_t rA = tok0 + rb * 32 + m * 16 + gid;
                #pragma unroll
                for (int p = 0; p < 3; ++p)
                    #pragma unroll
                    for (int hh = 0; hh < 2; ++hh) {
                        int col = cb * 48 + p * 16 + hh * 8 + 2 * tig;
                        int i = m * 6 + p * 2 + hh;
                        *(float2*)(dst + rA * 192 + col) =
                            make_float2((c[i][0] + bias[col]) * sc, (c[i][1] + bias[col+1]) * sc);
                        *(float2*)(dst + (rA + 8) * 192 + col) =
                            make_float2((c[i][2] + bias[col]) * sc, (c[i][3] + bias[col+1]) * sc);
                    }
            }
            #pragma unroll
            for (int i = 0; i < 12; ++i) { c[i][0]=c[i][1]=c[i][2]=c[i][3]=0.f; }
        }
    }
}

// ---------------- kernel 3: windowed attention (R7 version) ----------------
#define ATTN_SMEM 48128
__global__ void __launch_bounds__(128)
k_attn_tc(const float* __restrict__ mask) {
    extern __shared__ char smc[];
    const uint32_t sb = smem_u32(smc);
    char* c_QHI = smc;           char* c_QLO = smc + 5120;
    char* c_KHI = smc + 10240;   char* c_KLO = smc + 15360;
    char* c_VTH = smc + 20480;   char* c_VTL = smc + 25088;
    char* c_PHI = smc + 29696;   char* c_PLO = smc + 38912;
    int bx = blockIdx.x;
    int wi = bx & 4095;
    int h = bx >> 12;
    int wl = wi & 1023;
    int tid = threadIdx.x, wid = tid >> 5, lane = tid & 31;
    int gid = lane >> 2, tig = lane & 3;
    const size_t base = (size_t)wi * WINELEM + h * 32;

    for (int i = tid; i < 1024; i += 128) {
        int n = i >> 4, dp = (i & 15) * 2;
        float2 q2 = *(const float2*)(g_q + base + n * 192 + dp);
        float2 k2 = *(const float2*)(g_k + base + n * 192 + dp);
        uint32_t hp, lp;
        split2(q2.x, q2.y, hp, lp);
        *(uint32_t*)(c_QHI + (n * 40 + dp) * 2) = hp;
        *(uint32_t*)(c_QLO + (n * 40 + dp) * 2) = lp;
        split2(k2.x, k2.y, hp, lp);
        *(uint32_t*)(c_KHI + (n * 40 + dp) * 2) = hp;
        *(uint32_t*)(c_KLO + (n * 40 + dp) * 2) = lp;
        int key = i & 63, dq = (i >> 6) * 2;
        float2 v2 = *(const float2*)(g_v + base + key * 192 + dq);
        __nv_bfloat16 vh0 = __float2bfloat16(v2.x), vh1 = __float2bfloat16(v2.y);
        __nv_bfloat16 vl0 = __float2bfloat16(v2.x - __bfloat162float(vh0));
        __nv_bfloat16 vl1 = __float2bfloat16(v2.y - __bfloat162float(vh1));
        *(__nv_bfloat16*)(c_VTH + (dq * 72 + key) * 2) = vh0;
        *(__nv_bfloat16*)(c_VTH + ((dq + 1) * 72 + key) * 2) = vh1;
        *(__nv_bfloat16*)(c_VTL + (dq * 72 + key) * 2) = vl0;
        *(__nv_bfloat16*)(c_VTL + ((dq + 1) * 72 + key) * 2) = vl1;
    }
    __syncthreads();

    float c[8][4];
    #pragma unroll
    for (int i = 0; i < 8; ++i) { c[i][0]=c[i][1]=c[i][2]=c[i][3]=0.f; }
    wgemm<2, 4, 40, 40>(sb + (uint32_t)(wid * 1280), sb + 5120 + (uint32_t)(wid * 1280),
                        sb + 10240, sb + 15360, c, lane);

    int rA = wid * 16 + gid, rB = rA + 8;
    const float* bg = g_bias + h * 4096;
    const float* mg = mask + (size_t)wl * 4096;
    float vA[16], vB[16];
    #pragma unroll
    for (int nt = 0; nt < 8; ++nt) {
        int col = nt * 8 + 2 * tig;
        float2 b0 = *(const float2*)(bg + rA * 64 + col);
        float2 m0 = *(const float2*)(mg + rA * 64 + col);
        vA[2*nt]   = c[nt][0] + b0.x + m0.x;
        vA[2*nt+1] = c[nt][1] + b0.y + m0.y;
        float2 b1 = *(const float2*)(bg + rB * 64 + col);
        float2 m1 = *(const float2*)(mg + rB * 64 + col);
        vB[2*nt]   = c[nt][2] + b1.x + m1.x;
        vB[2*nt+1] = c[nt][3] + b1.y + m1.y;
    }
    float mxA = -1e30f, mxB = -1e30f;
    #pragma unroll
    for (int j = 0; j < 16; ++j) { mxA = fmaxf(mxA, vA[j]); mxB = fmaxf(mxB, vB[j]); }
    mxA = fmaxf(mxA, __shfl_xor_sync(0xffffffffu, mxA, 1));
    mxA = fmaxf(mxA, __shfl_xor_sync(0xffffffffu, mxA, 2));
    mxB = fmaxf(mxB, __shfl_xor_sync(0xffffffffu, mxB, 1));
    mxB = fmaxf(mxB, __shfl_xor_sync(0xffffffffu, mxB, 2));
    float sA = 0.f, sB = 0.f;
    #pragma unroll
    for (int j = 0; j < 16; ++j) {
        vA[j] = __expf(vA[j] - mxA); sA += vA[j];
        vB[j] = __expf(vB[j] - mxB); sB += vB[j];
    }
    sA += __shfl_xor_sync(0xffffffffu, sA, 1);
    sA += __shfl_xor_sync(0xffffffffu, sA, 2);
    sB += __shfl_xor_sync(0xffffffffu, sB, 1);
    sB += __shfl_xor_sync(0xffffffffu, sB, 2);
    float invA = 1.f / sA, invB = 1.f / sB;
    #pragma unroll
    for (int nt = 0; nt < 8; ++nt) {
        int col = nt * 8 + 2 * tig;
        uint32_t hp, lp;
        split2(vA[2*nt] * invA, vA[2*nt+1] * invA, hp, lp);
        *(uint32_t*)(c_PHI + (rA * 72 + col) * 2) = hp;
        *(uint32_t*)(c_PLO + (rA * 72 + col) * 2) = lp;
        split2(vB[2*nt] * invB, vB[2*nt+1] * invB, hp, lp);
        *(uint32_t*)(c_PHI + (rB * 72 + col) * 2) = hp;
        *(uint32_t*)(c_PLO + (rB * 72 + col) * 2) = lp;
    }
    __syncwarp();

    float o[4][4];
    #pragma unroll
    for (int i = 0; i < 4; ++i) { o[i][0]=o[i][1]=o[i][2]=o[i][3]=0.f; }
    wgemm<4, 2, 72, 72>(sb + 29696 + (uint32_t)(wid * 2304), sb + 38912 + (uint32_t)(wid * 2304),
                        sb + 20480, sb + 25088, o, lane);

    #pragma unroll
    for (int nt = 0; nt < 4; ++nt) {
        int col = nt * 8 + 2 * tig;
        *(float2*)(g_o + base + (size_t)rA * 192 + col) = make_float2(o[nt][0], o[nt][1]);
        *(float2*)(g_o + base + (size_t)rB * 192 + col) = make_float2(o[nt][2], o[nt][3]);
    }
}

// ---------------- kernel 4: proj -> merge -> LN -> residual (32x48 tiles) ----------------
#define PM_SMEM 212992
__global__ void __launch_bounds__(512, 1)
k_projmerge_tc(const float* __restrict__ proj_b,
               const float* __restrict__ g1, const float* __restrict__ b1) {
    extern __shared__ char smc[];
    const uint32_t sb = smem_u32(smc);
    char* A_HI = smc; char* A_LO = smc + 51200;
    const uint32_t WBh[2] = {sb + 102400, sb + 157696};
    const uint32_t WBl[2] = {sb + 130048, sb + 185344};
    int tid = threadIdx.x, wid = tid >> 5, lane = tid & 31;
    int rb = wid & 3, cb = wid >> 2;
    int gid = lane >> 2, tig = lane & 3;
    size_t tok0 = (size_t)blockIdx.x * 128;
    const uint32_t aW  = sb + (uint32_t)(rb * 12800);
    const uint32_t aWl = sb + 51200 + (uint32_t)(rb * 12800);
    const uint32_t wcb = (uint32_t)(cb * 6912);

    cpstageW(WBh[0], WBl[0], g_wh + OP, g_wl + OP, 192, 8, 192, 0, 72, tid);
    stage_linear(A_HI, A_LO, g_o + tok0 * 192, tid);

    float c[12][4];
    #pragma unroll
    for (int i = 0; i < 12; ++i) { c[i][0]=c[i][1]=c[i][2]=c[i][3]=0.f; }

    for (int t = 0; t < 6; ++t) {
        cp_wait0();
        __syncthreads();
        if (t < 5) {
            int tn = t + 1, kt = tn % 3;
            size_t off = (tn < 3) ? OP : OM;
            cpstageW(WBh[tn & 1], WBl[tn & 1], g_wh + off, g_wl + off,
                     192, 8, 192, kt * 64, 72, tid);
        }
        if (t == 3) {
            // A <- split(Y = proj result + bias); each warp writes its rows x cols
            #pragma unroll
            for (int m = 0; m < 2; ++m) {
                int lr = rb * 32 + m * 16 + gid;
                #pragma unroll
                for (int p = 0; p < 3; ++p)
                    #pragma unroll
                    for (int hh = 0; hh < 2; ++hh) {
                        int col = cb * 48 + p * 16 + hh * 8 + 2 * tig;
                        int i = m * 6 + p * 2 + hh;
                        uint32_t hp, lp;
                        split2(c[i][0] + proj_b[col], c[i][1] + proj_b[col+1], hp, lp);
                        size_t dA = ((size_t)lr * 200 + col) * 2;
                        *(uint32_t*)(A_HI + dA) = hp; *(uint32_t*)(A_LO + dA) = lp;
                        split2(c[i][2] + proj_b[col], c[i][3] + proj_b[col+1], hp, lp);
                        size_t dB = ((size_t)(lr + 8) * 200 + col) * 2;
                        *(uint32_t*)(A_HI + dB) = hp; *(uint32_t*)(A_LO + dB) = lp;
                    }
            }
            __syncthreads();
            #pragma unroll
            for (int i = 0; i < 12; ++i) { c[i][0]=c[i][1]=c[i][2]=c[i][3]=0.f; }
        }
        int kt = t % 3;
        wgemm2<4, 2, 3, 200, 72>(aW + kt * 128, aWl + kt * 128,
                                 WBh[t & 1] + wcb, WBl[t & 1] + wcb, c, lane);
    }

    // LN over rows: quad-shuffle (cols within cb), then cross-cb via smem
    float s[2][2] = {{0,0},{0,0}}, q[2][2] = {{0,0},{0,0}};
    #pragma unroll
    for (int m = 0; m < 2; ++m)
        #pragma unroll
        for (int p = 0; p < 3; ++p)
            #pragma unroll
            for (int hh = 0; hh < 2; ++hh) {
                int i = m * 6 + p * 2 + hh;
                s[m][0] += c[i][0] + c[i][1];
                q[m][0] += c[i][0]*c[i][0] + c[i][1]*c[i][1];
                s[m][1] += c[i][2] + c[i][3];
                q[m][1] += c[i][2]*c[i][2] + c[i][3]*c[i][3];
            }
    #pragma unroll
    for (int d = 1; d <= 2; d <<= 1)
        #pragma unroll
        for (int m = 0; m < 2; ++m)
            #pragma unroll
            for (int hh = 0; hh < 2; ++hh) {
                s[m][hh] += __shfl_xor_sync(0xffffffffu, s[m][hh], d);
                q[m][hh] += __shfl_xor_sync(0xffffffffu, q[m][hh], d);
            }
    float2* red = (float2*)(smc + 102400);   // [cb][row], WB0 dead after t=4
    if (tig == 0)
        #pragma unroll
        for (int m = 0; m < 2; ++m)
            #pragma unroll
            for (int hh = 0; hh < 2; ++hh)
                red[cb * 128 + rb * 32 + m * 16 + hh * 8 + gid] = make_float2(s[m][hh], q[m][hh]);
    __syncthreads();
    float mu[2][2], rs[2][2];
    #pragma unroll
    for (int m = 0; m < 2; ++m)
        #pragma unroll
        for (int hh = 0; hh < 2; ++hh) {
            int row = rb * 32 + m * 16 + hh * 8 + gid;
            float ss = 0.f, qq = 0.f;
            #pragma unroll
            for (int b = 0; b < 4; ++b) {
                float2 pr = red[b * 128 + row];
                ss += pr.x; qq += pr.y;
            }
            float m_ = ss * (1.f/192.f);
            mu[m][hh] = m_;
            rs[m][hh] = rsqrtf(qq * (1.f/192.f) - m_*m_ + 1e-5f);
        }

    auto rowoff = [&](int lr) -> size_t {
        int win = blockIdx.x * 2 + (lr >> 6);
        int b = win >> 10, wlr = win & 1023, wh = wlr >> 5, ww = wlr & 31;
        int n = lr & 63, ii = n >> 3, jj = n & 7;
        int hf = (wh * 8 + ii + 4) & 255, wf = (ww * 8 + jj + 4) & 255;
        return (((size_t)b * 256 + hf) * 256 + wf) * 192;
    };

    #pragma unroll
    for (int m = 0; m < 2; ++m) {
        int lr = rb * 32 + m * 16 + gid;
        size_t roA = rowoff(lr), roB = rowoff(lr + 8);
        #pragma unroll
        for (int p = 0; p < 3; ++p)
            #pragma unroll
            for (int hh = 0; hh < 2; ++hh) {
                int col = cb * 48 + p * 16 + hh * 8 + 2 * tig;
                int i = m * 6 + p * 2 + hh;
                float2 xa = *(const float2*)(g_xt + roA + col);
                float2 za;
                za.x = xa.x + (c[i][0] - mu[m][0]) * rs[m][0] * g1[col]   + b1[col];
                za.y = xa.y + (c[i][1] - mu[m][0]) * rs[m][0] * g1[col+1] + b1[col+1];
                *(float2*)(g_x1 + roA + col) = za;
                float2 xb = *(const float2*)(g_xt + roB + col);
                float2 zb;
                zb.x = xb.x + (c[i][2] - mu[m][1]) * rs[m][1] * g1[col]   + b1[col];
                zb.y = xb.y + (c[i][3] - mu[m][1]) * rs[m][1] * g1[col+1] + b1[col+1];
                *(float2*)(g_x1 + roB + col) = zb;
            }
    }
}

// ---------------- kernel 5: MLP + LN + residual (R7 version) ----------------
#define MLP_SMEM 194560
__global__ void __launch_bounds__(512, 1)
k_mlp_tc(const float* __restrict__ fc1_b, const float* __restrict__ fc2_b,
         const float* __restrict__ g2, const float* __restrict__ b2,
         float* __restrict__ out) {
    extern __shared__ char smc[];
    const uint32_t sb = smem_u32(smc);
    char* A_HI = smc; char* A_LO = smc + 51200;
    char* H_HI = smc + 102400; char* H_LO = smc + 120832;
    const uint32_t WBh[2] = {sb + 139264, sb + 166912};
    const uint32_t WBl[2] = {sb + 153088, sb + 180736};
    int tid = threadIdx.x, wid = tid >> 5, lane = tid & 31;
    int rb = wid & 7, ch = wid >> 3;
    int gid = lane >> 2, tig = lane & 3;
    size_t tok0 = (size_t)blockIdx.x * 128;
    const uint32_t aW  = sb + (uint32_t)(rb * 6400);
    const uint32_t aWl = sb + 51200 + (uint32_t)(rb * 6400);
    const uint32_t hW  = sb + 102400 + (uint32_t)(rb * 16 * 144);
    const uint32_t hWl = sb + 120832 + (uint32_t)(rb * 16 * 144);
    const uint32_t w1ch = (uint32_t)(ch * 6656);
    const uint32_t w2ch = (uint32_t)(ch * 6912);
    int lrA = rb * 16 + gid, lrB = lrA + 8;

    cpstageW(WBh[0], WBl[0], g_wh + OF1, g_wl + OF1, 64, 12, 192, 0, 104, tid);
    stage_linear(A_HI, A_LO, g_x1 + tok0 * 192, tid);

    float cf2[12][4];
    #pragma unroll
    for (int i = 0; i < 12; ++i) { cf2[i][0]=cf2[i][1]=cf2[i][2]=cf2[i][3]=0.f; }
    float c1[4][4];

    for (int pidx = 0; pidx < 48; ++pidx) {
        int ck = pidx >> 2, ph = pidx & 3;
        cp_wait0();
        __syncthreads();
        int np = pidx + 1, nck = np >> 2, nph = np & 3;
        if (nck < 12) {
            int par = np & 1;
            if (nph < 2)
                cpstageW(WBh[par], WBl[par],
                         g_wh + OF1 + (size_t)nck * 64 * 192,
                         g_wl + OF1 + (size_t)nck * 64 * 192,
                         64, 12, 192, nph * 96, 104, tid);
            else
                cpstageW(WBh[par], WBl[par],
                         g_wh + OF2 + (size_t)(nph - 2) * 96 * 768,
                         g_wl + OF2 + (size_t)(nph - 2) * 96 * 768,
                         96, 8, 768, nck * 64, 72, tid);
        }
        int par = pidx & 1;
        if (ph < 2) {
            if (ph == 0) {
                #pragma unroll
                for (int i = 0; i < 4; ++i) { c1[i][0]=c1[i][1]=c1[i][2]=c1[i][3]=0.f; }
            }
            wgemm<6, 2, 200, 104>(aW + ph * 192, aWl + ph * 192,
                                  WBh[par] + w1ch, WBl[par] + w1ch, c1, lane);
            if (ph == 1) {
                #pragma unroll
                for (int nt = 0; nt < 4; ++nt) {
                    int col = ch * 32 + nt * 8 + 2 * tig;
                    int bc = ck * 64 + col;
                    uint32_t hp, lp;
                    split2(gelu_fast(c1[nt][0] + fc1_b[bc]),
                           gelu_fast(c1[nt][1] + fc1_b[bc+1]), hp, lp);
                    size_t dA = ((size_t)lrA * 72 + col) * 2;
                    *(uint32_t*)(H_HI + dA) = hp; *(uint32_t*)(H_LO + dA) = lp;
                    split2(gelu_fast(c1[nt][2] + fc1_b[bc]),
                           gelu_fast(c1[nt][3] + fc1_b[bc+1]), hp, lp);
                    size_t dB = ((size_t)lrB * 72 + col) * 2;
                    *(uint32_t*)(H_HI + dB) = hp; *(uint32_t*)(H_LO + dB) = lp;
                }
            }
        } else {
            wgemm<4, 3, 72, 72>(hW, hWl, WBh[par] + w2ch, WBl[par] + w2ch,
                                cf2 + (ph - 2) * 6, lane);
        }
    }

    float sA = 0.f, qA = 0.f, sB = 0.f, qB = 0.f;
    float zr[12][4];
    #pragma unroll
    for (int p = 0; p < 2; ++p)
        #pragma unroll
        for (int nt = 0; nt < 6; ++nt) {
            int col = p * 96 + ch * 48 + nt * 8 + 2 * tig;
            int i = p * 6 + nt;
            zr[i][0] = cf2[i][0] + fc2_b[col];
            zr[i][1] = cf2[i][1] + fc2_b[col+1];
            zr[i][2] = cf2[i][2] + fc2_b[col];
            zr[i][3] = cf2[i][3] + fc2_b[col+1];
            sA += zr[i][0] + zr[i][1]; qA += zr[i][0]*zr[i][0] + zr[i][1]*zr[i][1];
            sB += zr[i][2] + zr[i][3]; qB += zr[i][2]*zr[i][2] + zr[i][3]*zr[i][3];
        }
    #pragma unroll
    for (int d = 1; d <= 2; d <<= 1) {
        sA += __shfl_xor_sync(0xffffffffu, sA, d);
        qA += __shfl_xor_sync(0xffffffffu, qA, d);
        sB += __shfl_xor_sync(0xffffffffu, sB, d);
        qB += __shfl_xor_sync(0xffffffffu, qB, d);
    }
    float2* red = (float2*)(smc + 139264);
    __syncthreads();
    if (tig == 0) {
        red[ch * 128 + lrA] = make_float2(sA, qA);
        red[ch * 128 + lrB] = make_float2(sB, qB);
    }
    __syncthreads();
    float2 pA0 = red[lrA], pA1 = red[128 + lrA];
    float2 pB0 = red[lrB], pB1 = red[128 + lrB];
    float muA = (pA0.x + pA1.x) * (1.f/192.f);
    float rsA = rsqrtf((pA0.y + pA1.y) * (1.f/192.f) - muA*muA + 1e-5f);
    float muB = (pB0.x + pB1.x) * (1.f/192.f);
    float rsB = rsqrtf((pB0.y + pB1.y) * (1.f/192.f) - muB*muB + 1e-5f);

    size_t grA = (tok0 + lrA) * 192, grB = (tok0 + lrB) * 192;
    #pragma unroll
    for (int p = 0; p < 2; ++p)
        #pragma unroll
        for (int nt = 0; nt < 6; ++nt) {
            int col = p * 96 + ch * 48 + nt * 8 + 2 * tig;
            int i = p * 6 + nt;
            float2 xa = *(const float2*)(g_x1 + grA + col);
            float2 oa;
            oa.x = xa.x + (zr[i][0] - muA) * rsA * g2[col]   + b2[col];
            oa.y = xa.y + (zr[i][1] - muA) * rsA * g2[col+1] + b2[col+1];
            *(float2*)(out + grA + col) = oa;
            float2 xb = *(const float2*)(g_x1 + grB + col);
            float2 ob;
            ob.x = xb.x + (zr[i][2] - muB) * rsB * g2[col]   + b2[col];
            ob.y = xb.y + (zr[i][3] - muB) * rsB * g2[col+1] + b2[col+1];
            *(float2*)(out + grB + col) = ob;
        }
}

// ---------------- launch ----------------
extern "C" void kernel_launch(void* const* d_in, const int* in_sizes, int n_in,
                              void* d_out, int out_size) {
    const float* x        = (const float*)d_in[0];
    const float* feat     = (const float*)d_in[1];
    const float* attn_mask= (const float*)d_in[2];
    const int*   rel_index= (const int*)  d_in[3];
    const float* rel_tab  = (const float*)d_in[4];
    const float* q_w      = (const float*)d_in[5];
    const float* q_b      = (const float*)d_in[6];
    const float* kv_w     = (const float*)d_in[7];
    const float* kv_b     = (const float*)d_in[8];
    const float* proj_w   = (const float*)d_in[9];
    const float* proj_b   = (const float*)d_in[10];
    const float* merge_w  = (const float*)d_in[11];
    const float* n1g      = (const float*)d_in[12];
    const float* n1b      = (const float*)d_in[13];
    const float* n2g      = (const float*)d_in[14];
    const float* n2b      = (const float*)d_in[15];
    const float* fc1_w    = (const float*)d_in[16];
    const float* fc1_b    = (const float*)d_in[17];
    const float* fc2_w    = (const float*)d_in[18];
    const float* fc2_b    = (const float*)d_in[19];
    float* out = (float*)d_out;

    cudaFuncSetAttribute(k_qkv_tc,       cudaFuncAttributeMaxDynamicSharedMemorySize, QKV_SMEM);
    cudaFuncSetAttribute(k_attn_tc,      cudaFuncAttributeMaxDynamicSharedMemorySize, ATTN_SMEM);
    cudaFuncSetAttribute(k_projmerge_tc, cudaFuncAttributeMaxDynamicSharedMemorySize, PM_SMEM);
    cudaFuncSetAttribute(k_mlp_tc,       cudaFuncAttributeMaxDynamicSharedMemorySize, MLP_SMEM);

    k_transpose<<<dim3(2048, 6, 8), dim3(32, 8)>>>(x, feat);
    k_bias<<<96, 256>>>(rel_index, rel_tab);
    k_wsplit<<<(WTOT + 255) / 256, 256>>>(q_w, kv_w, proj_w, merge_w, fc1_w, fc2_w);
    k_qkv_tc<<<2048, 512, QKV_SMEM>>>(q_b, kv_b);
    k_attn_tc<<<NWIN * NHEAD, 128, ATTN_SMEM>>>(attn_mask);
    k_projmerge_tc<<<2048, 512, PM_SMEM>>>(proj_b, n1g, n1b);
    k_mlp_tc<<<2048, 512, MLP_SMEM>>>(fc1_b, fc2_b, n2g, n2b, out);
}

// round 11
// speedup vs baseline: 2.2184x; 1.0017x over previous
#include <cuda_runtime.h>
#include <cuda_bf16.h>
#include <cstdint>

// ---------------- problem constants ----------------
#define Hh 256
#define Ww 256
#define Bb 4
#define Cc 192
#define NHEAD 6
#define NWIN 4096
#define NTOK 64
#define TOKALL (Bb*Hh*Ww)
#define WINELEM (NTOK*Cc)

// weight-split offsets (elements)
#define OQ  0
#define OKV 36864
#define OP  110592
#define OM  147456
#define OF1 184320
#define OF2 331776
#define WTOT 479232

// ---------------- device scratch ----------------
__device__ float g_xt[(size_t)TOKALL * Cc];
__device__ float g_ft[(size_t)TOKALL * Cc];
__device__ float g_q [(size_t)NWIN * WINELEM];
__device__ float g_k [(size_t)NWIN * WINELEM];
__device__ float g_v [(size_t)NWIN * WINELEM];
__device__ float g_o [(size_t)NWIN * WINELEM];
__device__ float g_x1[(size_t)TOKALL * Cc];
__device__ float g_bias[NHEAD * NTOK * NTOK];
__device__ __align__(16) __nv_bfloat16 g_wh[WTOT];
__device__ __align__(16) __nv_bfloat16 g_wl[WTOT];

// ---------------- helpers ----------------
__device__ __forceinline__ float gelu_fast(float x) {
    float z = x * 0.7071067811865475f;
    float az = fabsf(z);
    float t = __fdividef(1.0f, fmaf(0.3275911f, az, 1.0f));
    float p = t * (0.254829592f + t * (-0.284496736f + t * (1.421413741f +
              t * (-1.453152027f + t * 1.061405429f))));
    float e = __expf(-az * az);
    float erfv = 1.0f - p * e;
    erfv = copysignf(erfv, z);
    return 0.5f * x * (1.0f + erfv);
}

__device__ __forceinline__ uint32_t smem_u32(const void* p) {
    uint32_t a;
    asm("{ .reg .u64 t; cvta.to.shared.u64 t, %1; cvt.u32.u64 %0, t; }" : "=r"(a) : "l"(p));
    return a;
}

__device__ __forceinline__ void split2(float v0, float v1, uint32_t& hp, uint32_t& lp) {
    __nv_bfloat16 h0 = __float2bfloat16(v0);
    __nv_bfloat16 h1 = __float2bfloat16(v1);
    __nv_bfloat16 l0 = __float2bfloat16(v0 - __bfloat162float(h0));
    __nv_bfloat16 l1 = __float2bfloat16(v1 - __bfloat162float(h1));
    hp = (uint32_t)__bfloat16_as_ushort(h0) | ((uint32_t)__bfloat16_as_ushort(h1) << 16);
    lp = (uint32_t)__bfloat16_as_ushort(l0) | ((uint32_t)__bfloat16_as_ushort(l1) << 16);
}

__device__ __forceinline__ void ldsm_x4(uint32_t (&r)[4], uint32_t a) {
    asm volatile("ldmatrix.sync.aligned.m8n8.x4.shared.b16 {%0,%1,%2,%3}, [%4];"
        : "=r"(r[0]), "=r"(r[1]), "=r"(r[2]), "=r"(r[3]) : "r"(a));
}

__device__ __forceinline__ void mma16816(float (&c)[4], const uint32_t (&a)[4],
                                         uint32_t b0, uint32_t b1) {
    asm volatile("mma.sync.aligned.m16n8k16.row.col.f32.bf16.bf16.f32 "
        "{%0,%1,%2,%3}, {%4,%5,%6,%7}, {%8,%9}, {%0,%1,%2,%3};"
        : "+f"(c[0]), "+f"(c[1]), "+f"(c[2]), "+f"(c[3])
        : "r"(a[0]), "r"(a[1]), "r"(a[2]), "r"(a[3]), "r"(b0), "r"(b1));
}

// R7 warp GEMM (used by attn)
template<int KS, int NT2, int AS, int WS>
__device__ __forceinline__ void wgemm(uint32_t aH, uint32_t aL,
                                      uint32_t wH, uint32_t wL,
                                      float (*c)[4], int lane) {
    const uint32_t aoff = (uint32_t)(((lane & 15) * AS + ((lane >> 4) << 3)) * 2);
    const uint32_t woff = (uint32_t)(((((lane >> 4) << 3) + (lane & 7)) * WS + (lane & 8)) * 2);
    aH += aoff; aL += aoff; wH += woff; wL += woff;
    #pragma unroll
    for (int ks = 0; ks < KS; ++ks) {
        uint32_t ah[4], al[4];
        ldsm_x4(ah, aH + ks * 32);
        ldsm_x4(al, aL + ks * 32);
        #pragma unroll
        for (int p = 0; p < NT2; ++p) {
            uint32_t bh[4], bl[4];
            ldsm_x4(bh, wH + p * (16 * WS * 2) + ks * 32);
            ldsm_x4(bl, wL + p * (16 * WS * 2) + ks * 32);
            mma16816(c[2*p],   ah, bh[0], bh[1]);
            mma16816(c[2*p],   al, bh[0], bh[1]);
            mma16816(c[2*p],   ah, bl[0], bl[1]);
            mma16816(c[2*p+1], ah, bh[2], bh[3]);
            mma16816(c[2*p+1], al, bh[2], bh[3]);
            mma16816(c[2*p+1], ah, bl[2], bl[3]);
        }
    }
}

// v2 warp GEMM: M2 m-tiles x NT2 n-tiles (32x48 when M2=2,NT2=3)
template<int KS, int M2, int NT2, int AS, int WS>
__device__ __forceinline__ void wgemm2(uint32_t aH, uint32_t aL,
                                       uint32_t wH, uint32_t wL,
                                       float (*c)[4], int lane) {
    const uint32_t aoff = (uint32_t)(((lane & 15) * AS + ((lane >> 4) << 3)) * 2);
    const uint32_t woff = (uint32_t)(((((lane >> 4) << 3) + (lane & 7)) * WS + (lane & 8)) * 2);
    aH += aoff; aL += aoff; wH += woff; wL += woff;
    #pragma unroll
    for (int ks = 0; ks < KS; ++ks) {
        uint32_t ah[M2][4], al[M2][4];
        #pragma unroll
        for (int m = 0; m < M2; ++m) {
            ldsm_x4(ah[m], aH + m * (16 * AS * 2) + ks * 32);
            ldsm_x4(al[m], aL + m * (16 * AS * 2) + ks * 32);
        }
        #pragma unroll
        for (int p = 0; p < NT2; ++p) {
            uint32_t bh[4], bl[4];
            ldsm_x4(bh, wH + p * (16 * WS * 2) + ks * 32);
            ldsm_x4(bl, wL + p * (16 * WS * 2) + ks * 32);
            #pragma unroll
            for (int m = 0; m < M2; ++m) {
                mma16816(c[m*2*NT2 + p*2],     ah[m], bh[0], bh[1]);
                mma16816(c[m*2*NT2 + p*2 + 1], ah[m], bh[2], bh[3]);
            }
            #pragma unroll
            for (int m = 0; m < M2; ++m) {
                mma16816(c[m*2*NT2 + p*2],     al[m], bh[0], bh[1]);
                mma16816(c[m*2*NT2 + p*2 + 1], al[m], bh[2], bh[3]);
            }
            #pragma unroll
            for (int m = 0; m < M2; ++m) {
                mma16816(c[m*2*NT2 + p*2],     ah[m], bl[0], bl[1]);
                mma16816(c[m*2*NT2 + p*2 + 1], ah[m], bl[2], bl[3]);
            }
        }
    }
}

// ---------------- cp.async helpers ----------------
__device__ __forceinline__ void cp16(uint32_t d, const void* s) {
    asm volatile("cp.async.cg.shared.global [%0], [%1], 16;" :: "r"(d), "l"(s) : "memory");
}
__device__ __forceinline__ void cp_commit() {
    asm volatile("cp.async.commit_group;" ::: "memory");
}
__device__ __forceinline__ void cp_wait0() {
    asm volatile("cp.async.wait_group 0;" ::: "memory");
}

template<int NTHR>
__device__ __forceinline__ void cpstageW(uint32_t dh, uint32_t dl,
        const __nv_bfloat16* sh, const __nv_bfloat16* sl,
        int rows, int ku4, int srck, int koff, int dstride, int tid) {
    int tot = rows * ku4;
    for (int i = tid; i < tot; i += NTHR) {
        int r = i / ku4, q = i - r * ku4;
        size_t s = (size_t)r * srck + koff + q * 8;
        uint32_t d = (uint32_t)(r * dstride + q * 8) * 2;
        cp16(dh + d, sh + s);
        cp16(dl + d, sl + s);
    }
    cp_commit();
}

template<int NROWS, int NTHR>
__device__ __forceinline__ void stage_linear(char* dh, char* dl, const float* src, int tid) {
    for (int i = tid; i < NROWS * 96; i += NTHR) {
        int r = i / 96, cp = (i - r * 96) * 2;
        float2 v = *(const float2*)(src + (size_t)r * 192 + cp);
        uint32_t hp, lp; split2(v.x, v.y, hp, lp);
        size_t d = ((size_t)r * 200 + cp) * 2;
        *(uint32_t*)(dh + d) = hp;
        *(uint32_t*)(dl + d) = lp;
    }
}

__device__ __forceinline__ void stage_gather(char* dh, char* dl, const float* src,
                                             int w0, int tid) {
    for (int i = tid; i < 128 * 96; i += 512) {
        int r = i / 96, cp = (i - r * 96) * 2;
        int win = w0 + (r >> 6);
        int b = win >> 10, wlr = win & 1023, wh = wlr >> 5, ww = wlr & 31;
        int n = r & 63, ii = n >> 3, jj = n & 7;
        int hh = (wh * 8 + ii + 4) & 255, wp = (ww * 8 + jj + 4) & 255;
        size_t off = (((size_t)b * 256 + hh) * 256 + wp) * 192 + cp;
        float2 v = *(const float2*)(src + off);
        uint32_t hp, lp; split2(v.x, v.y, hp, lp);
        size_t d = ((size_t)r * 200 + cp) * 2;
        *(uint32_t*)(dh + d) = hp;
        *(uint32_t*)(dl + d) = lp;
    }
}

// ---------------- kernel 0: NCHW -> NHWC ----------------
__global__ void k_transpose(const float* __restrict__ x, const float* __restrict__ f) {
    __shared__ float tile[32][33];
    int b = blockIdx.z >> 1;
    const float* src = (blockIdx.z & 1) ? f : x;
    float* dst = (blockIdx.z & 1) ? g_ft : g_xt;
    int hw0 = blockIdx.x * 32;
    int c0 = blockIdx.y * 32;
    #pragma unroll
    for (int i = threadIdx.y; i < 32; i += 8)
        tile[i][threadIdx.x] =
            src[((size_t)b * Cc + c0 + i) * (Hh * Ww) + hw0 + threadIdx.x];
    __syncthreads();
    #pragma unroll
    for (int i = threadIdx.y; i < 32; i += 8)
        dst[((size_t)b * (Hh * Ww) + hw0 + i) * Cc + c0 + threadIdx.x] =
            tile[threadIdx.x][i];
}

// ---------------- kernel 1: expand relative-position bias ----------------
__global__ void k_bias(const int* __restrict__ rel_index, const float* __restrict__ table) {
    int idx = blockIdx.x * blockDim.x + threadIdx.x;
    if (idx < NHEAD * NTOK * NTOK) {
        int h = idx / (NTOK * NTOK);
        int nm = idx % (NTOK * NTOK);
        g_bias[idx] = table[rel_index[nm] * NHEAD + h];
    }
}

// ---------------- kernel 1b: split ALL weights to bf16 hi/lo ----------------
__global__ void k_wsplit(const float* __restrict__ q_w, const float* __restrict__ kv_w,
                         const float* __restrict__ proj_w, const float* __restrict__ merge_w,
                         const float* __restrict__ fc1_w, const float* __restrict__ fc2_w) {
    int i = blockIdx.x * 256 + threadIdx.x;
    if (i >= WTOT) return;
    float v;
    if (i < OKV)       v = q_w[i];
    else if (i < OP)   v = kv_w[i - OKV];
    else if (i < OM)   v = proj_w[i - OP];
    else if (i < OF1)  v = merge_w[i - OM];
    else if (i < OF2)  v = fc1_w[i - OF1];
    else               v = fc2_w[i - OF2];
    __nv_bfloat16 h = __float2bfloat16(v);
    g_wh[i] = h;
    g_wl[i] = __float2bfloat16(v - __bfloat162float(h));
}

// ---------------- kernel 2: QKV (R9 winner, unchanged) ----------------
#define QKV_SMEM 212992
__global__ void __launch_bounds__(512, 1)
k_qkv_tc(const float* __restrict__ q_b, const float* __restrict__ kv_b) {
    extern __shared__ char smc[];
    const uint32_t sb = smem_u32(smc);
    char* A_HI = smc; char* A_LO = smc + 51200;
    const uint32_t WBh[2] = {sb + 102400, sb + 157696};
    const uint32_t WBl[2] = {sb + 130048, sb + 185344};
    int tid = threadIdx.x, wid = tid >> 5, lane = tid & 31;
    int rb = wid & 3, cb = wid >> 2;
    int gid = lane >> 2, tig = lane & 3;
    size_t tok0 = (size_t)blockIdx.x * 128;
    int w0 = blockIdx.x * 2;
    const uint32_t aW  = sb + (uint32_t)(rb * 12800);
    const uint32_t aWl = sb + 51200 + (uint32_t)(rb * 12800);
    const uint32_t wcb = (uint32_t)(cb * 6912);
    const float scale = 0.17677669529663687f;

    cpstageW<512>(WBh[0], WBl[0], g_wh + OQ, g_wl + OQ, 192, 8, 192, 0, 72, tid);
    stage_gather(A_HI, A_LO, g_xt, w0, tid);

    float c[12][4];
    #pragma unroll
    for (int i = 0; i < 12; ++i) { c[i][0]=c[i][1]=c[i][2]=c[i][3]=0.f; }

    for (int t = 0; t < 9; ++t) {
        cp_wait0();
        __syncthreads();
        if (t < 8) {
            int tn = t + 1, g = tn / 3, kt = tn % 3;
            size_t off = (g == 0) ? OQ : (g == 1) ? OKV : OKV + 36864;
            cpstageW<512>(WBh[tn & 1], WBl[tn & 1], g_wh + off, g_wl + off,
                          192, 8, 192, kt * 64, 72, tid);
        }
        if (t == 3) {
            stage_gather(A_HI, A_LO, g_ft, w0, tid);
            __syncthreads();
        }
        int kt = t % 3;
        wgemm2<4, 2, 3, 200, 72>(aW + kt * 128, aWl + kt * 128,
                                 WBh[t & 1] + wcb, WBl[t & 1] + wcb, c, lane);
        if (kt == 2) {
            int g = t / 3;
            float* dst = (g == 0) ? g_q : (g == 1) ? g_k : g_v;
            const float* bias = (g == 0) ? q_b : (g == 1) ? kv_b : kv_b + 192;
            float sc = (g == 0) ? scale : 1.f;
            #pragma unroll
            for (int m = 0; m < 2; ++m) {
                size_t rA = tok0 + rb * 32 + m * 16 + gid;
                #pragma unroll
                for (int p = 0; p < 3; ++p)
                    #pragma unroll
                    for (int hh = 0; hh < 2; ++hh) {
                        int col = cb * 48 + p * 16 + hh * 8 + 2 * tig;
                        int i = m * 6 + p * 2 + hh;
                        *(float2*)(dst + rA * 192 + col) =
                            make_float2((c[i][0] + bias[col]) * sc, (c[i][1] + bias[col+1]) * sc);
                        *(float2*)(dst + (rA + 8) * 192 + col) =
                            make_float2((c[i][2] + bias[col]) * sc, (c[i][3] + bias[col+1]) * sc);
                    }
            }
            #pragma unroll
            for (int i = 0; i < 12; ++i) { c[i][0]=c[i][1]=c[i][2]=c[i][3]=0.f; }
        }
    }
}

// ---------------- kernel 3: windowed attention (unchanged) ----------------
#define ATTN_SMEM 48128
__global__ void __launch_bounds__(128)
k_attn_tc(const float* __restrict__ mask) {
    extern __shared__ char smc[];
    const uint32_t sb = smem_u32(smc);
    char* c_QHI = smc;           char* c_QLO = smc + 5120;
    char* c_KHI = smc + 10240;   char* c_KLO = smc + 15360;
    char* c_VTH = smc + 20480;   char* c_VTL = smc + 25088;
    char* c_PHI = smc + 29696;   char* c_PLO = smc + 38912;
    int bx = blockIdx.x;
    int wi = bx & 4095;
    int h = bx >> 12;
    int wl = wi & 1023;
    int tid = threadIdx.x, wid = tid >> 5, lane = tid & 31;
    int gid = lane >> 2, tig = lane & 3;
    const size_t base = (size_t)wi * WINELEM + h * 32;

    for (int i = tid; i < 1024; i += 128) {
        int n = i >> 4, dp = (i & 15) * 2;
        float2 q2 = *(const float2*)(g_q + base + n * 192 + dp);
        float2 k2 = *(const float2*)(g_k + base + n * 192 + dp);
        uint32_t hp, lp;
        split2(q2.x, q2.y, hp, lp);
        *(uint32_t*)(c_QHI + (n * 40 + dp) * 2) = hp;
        *(uint32_t*)(c_QLO + (n * 40 + dp) * 2) = lp;
        split2(k2.x, k2.y, hp, lp);
        *(uint32_t*)(c_KHI + (n * 40 + dp) * 2) = hp;
        *(uint32_t*)(c_KLO + (n * 40 + dp) * 2) = lp;
        int key = i & 63, dq = (i >> 6) * 2;
        float2 v2 = *(const float2*)(g_v + base + key * 192 + dq);
        __nv_bfloat16 vh0 = __float2bfloat16(v2.x), vh1 = __float2bfloat16(v2.y);
        __nv_bfloat16 vl0 = __float2bfloat16(v2.x - __bfloat162float(vh0));
        __nv_bfloat16 vl1 = __float2bfloat16(v2.y - __bfloat162float(vh1));
        *(__nv_bfloat16*)(c_VTH + (dq * 72 + key) * 2) = vh0;
        *(__nv_bfloat16*)(c_VTH + ((dq + 1) * 72 + key) * 2) = vh1;
        *(__nv_bfloat16*)(c_VTL + (dq * 72 + key) * 2) = vl0;
        *(__nv_bfloat16*)(c_VTL + ((dq + 1) * 72 + key) * 2) = vl1;
    }
    __syncthreads();

    float c[8][4];
    #pragma unroll
    for (int i = 0; i < 8; ++i) { c[i][0]=c[i][1]=c[i][2]=c[i][3]=0.f; }
    wgemm<2, 4, 40, 40>(sb + (uint32_t)(wid * 1280), sb + 5120 + (uint32_t)(wid * 1280),
                        sb + 10240, sb + 15360, c, lane);

    int rA = wid * 16 + gid, rB = rA + 8;
    const float* bg = g_bias + h * 4096;
    const float* mg = mask + (size_t)wl * 4096;
    float vA[16], vB[16];
    #pragma unroll
    for (int nt = 0; nt < 8; ++nt) {
        int col = nt * 8 + 2 * tig;
        float2 b0 = *(const float2*)(bg + rA * 64 + col);
        float2 m0 = *(const float2*)(mg + rA * 64 + col);
        vA[2*nt]   = c[nt][0] + b0.x + m0.x;
        vA[2*nt+1] = c[nt][1] + b0.y + m0.y;
        float2 b1 = *(const float2*)(bg + rB * 64 + col);
        float2 m1 = *(const float2*)(mg + rB * 64 + col);
        vB[2*nt]   = c[nt][2] + b1.x + m1.x;
        vB[2*nt+1] = c[nt][3] + b1.y + m1.y;
    }
    float mxA = -1e30f, mxB = -1e30f;
    #pragma unroll
    for (int j = 0; j < 16; ++j) { mxA = fmaxf(mxA, vA[j]); mxB = fmaxf(mxB, vB[j]); }
    mxA = fmaxf(mxA, __shfl_xor_sync(0xffffffffu, mxA, 1));
    mxA = fmaxf(mxA, __shfl_xor_sync(0xffffffffu, mxA, 2));
    mxB = fmaxf(mxB, __shfl_xor_sync(0xffffffffu, mxB, 1));
    mxB = fmaxf(mxB, __shfl_xor_sync(0xffffffffu, mxB, 2));
    float sA = 0.f, sB = 0.f;
    #pragma unroll
    for (int j = 0; j < 16; ++j) {
        vA[j] = __expf(vA[j] - mxA); sA += vA[j];
        vB[j] = __expf(vB[j] - mxB); sB += vB[j];
    }
    sA += __shfl_xor_sync(0xffffffffu, sA, 1);
    sA += __shfl_xor_sync(0xffffffffu, sA, 2);
    sB += __shfl_xor_sync(0xffffffffu, sB, 1);
    sB += __shfl_xor_sync(0xffffffffu, sB, 2);
    float invA = 1.f / sA, invB = 1.f / sB;
    #pragma unroll
    for (int nt = 0; nt < 8; ++nt) {
        int col = nt * 8 + 2 * tig;
        uint32_t hp, lp;
        split2(vA[2*nt] * invA, vA[2*nt+1] * invA, hp, lp);
        *(uint32_t*)(c_PHI + (rA * 72 + col) * 2) = hp;
        *(uint32_t*)(c_PLO + (rA * 72 + col) * 2) = lp;
        split2(vB[2*nt] * invB, vB[2*nt+1] * invB, hp, lp);
        *(uint32_t*)(c_PHI + (rB * 72 + col) * 2) = hp;
        *(uint32_t*)(c_PLO + (rB * 72 + col) * 2) = lp;
    }
    __syncwarp();

    float o[4][4];
    #pragma unroll
    for (int i = 0; i < 4; ++i) { o[i][0]=o[i][1]=o[i][2]=o[i][3]=0.f; }
    wgemm<4, 2, 72, 72>(sb + 29696 + (uint32_t)(wid * 2304), sb + 38912 + (uint32_t)(wid * 2304),
                        sb + 20480, sb + 25088, o, lane);

    #pragma unroll
    for (int nt = 0; nt < 4; ++nt) {
        int col = nt * 8 + 2 * tig;
        *(float2*)(g_o + base + (size_t)rA * 192 + col) = make_float2(o[nt][0], o[nt][1]);
        *(float2*)(g_o + base + (size_t)rB * 192 + col) = make_float2(o[nt][2], o[nt][3]);
    }
}

// ---------------- kernel 4: proj -> merge -> LN -> residual (R9 winner, unchanged) ----------------
#define PM_SMEM 212992
__global__ void __launch_bounds__(512, 1)
k_projmerge_tc(const float* __restrict__ proj_b,
               const float* __restrict__ g1, const float* __restrict__ b1) {
    extern __shared__ char smc[];
    const uint32_t sb = smem_u32(smc);
    char* A_HI = smc; char* A_LO = smc + 51200;
    const uint32_t WBh[2] = {sb + 102400, sb + 157696};
    const uint32_t WBl[2] = {sb + 130048, sb + 185344};
    int tid = threadIdx.x, wid = tid >> 5, lane = tid & 31;
    int rb = wid & 3, cb = wid >> 2;
    int gid = lane >> 2, tig = lane & 3;
    size_t tok0 = (size_t)blockIdx.x * 128;
    const uint32_t aW  = sb + (uint32_t)(rb * 12800);
    const uint32_t aWl = sb + 51200 + (uint32_t)(rb * 12800);
    const uint32_t wcb = (uint32_t)(cb * 6912);

    cpstageW<512>(WBh[0], WBl[0], g_wh + OP, g_wl + OP, 192, 8, 192, 0, 72, tid);
    stage_linear<128, 512>(A_HI, A_LO, g_o + tok0 * 192, tid);

    float c[12][4];
    #pragma unroll
    for (int i = 0; i < 12; ++i) { c[i][0]=c[i][1]=c[i][2]=c[i][3]=0.f; }

    for (int t = 0; t < 6; ++t) {
        cp_wait0();
        __syncthreads();
        if (t < 5) {
            int tn = t + 1, kt = tn % 3;
            size_t off = (tn < 3) ? OP : OM;
            cpstageW<512>(WBh[tn & 1], WBl[tn & 1], g_wh + off, g_wl + off,
                          192, 8, 192, kt * 64, 72, tid);
        }
        if (t == 3) {
            #pragma unroll
            for (int m = 0; m < 2; ++m) {
                int lr = rb * 32 + m * 16 + gid;
                #pragma unroll
                for (int p = 0; p < 3; ++p)
                    #pragma unroll
                    for (int hh = 0; hh < 2; ++hh) {
                        int col = cb * 48 + p * 16 + hh * 8 + 2 * tig;
                        int i = m * 6 + p * 2 + hh;
                        uint32_t hp, lp;
                        split2(c[i][0] + proj_b[col], c[i][1] + proj_b[col+1], hp, lp);
                        size_t dA = ((size_t)lr * 200 + col) * 2;
                        *(uint32_t*)(A_HI + dA) = hp; *(uint32_t*)(A_LO + dA) = lp;
                        split2(c[i][2] + proj_b[col], c[i][3] + proj_b[col+1], hp, lp);
                        size_t dB = ((size_t)(lr + 8) * 200 + col) * 2;
                        *(uint32_t*)(A_HI + dB) = hp; *(uint32_t*)(A_LO + dB) = lp;
                    }
            }
            __syncthreads();
            #pragma unroll
            for (int i = 0; i < 12; ++i) { c[i][0]=c[i][1]=c[i][2]=c[i][3]=0.f; }
        }
        int kt = t % 3;
        wgemm2<4, 2, 3, 200, 72>(aW + kt * 128, aWl + kt * 128,
                                 WBh[t & 1] + wcb, WBl[t & 1] + wcb, c, lane);
    }

    float s[2][2] = {{0,0},{0,0}}, q[2][2] = {{0,0},{0,0}};
    #pragma unroll
    for (int m = 0; m < 2; ++m)
        #pragma unroll
        for (int p = 0; p < 3; ++p)
            #pragma unroll
            for (int hh = 0; hh < 2; ++hh) {
                int i = m * 6 + p * 2 + hh;
                s[m][0] += c[i][0] + c[i][1];
                q[m][0] += c[i][0]*c[i][0] + c[i][1]*c[i][1];
                s[m][1] += c[i][2] + c[i][3];
                q[m][1] += c[i][2]*c[i][2] + c[i][3]*c[i][3];
            }
    #pragma unroll
    for (int d = 1; d <= 2; d <<= 1)
        #pragma unroll
        for (int m = 0; m < 2; ++m)
            #pragma unroll
            for (int hh = 0; hh < 2; ++hh) {
                s[m][hh] += __shfl_xor_sync(0xffffffffu, s[m][hh], d);
                q[m][hh] += __shfl_xor_sync(0xffffffffu, q[m][hh], d);
            }
    float2* red = (float2*)(smc + 102400);
    if (tig == 0)
        #pragma unroll
        for (int m = 0; m < 2; ++m)
            #pragma unroll
            for (int hh = 0; hh < 2; ++hh)
                red[cb * 128 + rb * 32 + m * 16 + hh * 8 + gid] = make_float2(s[m][hh], q[m][hh]);
    __syncthreads();
    float mu[2][2], rs[2][2];
    #pragma unroll
    for (int m = 0; m < 2; ++m)
        #pragma unroll
        for (int hh = 0; hh < 2; ++hh) {
            int row = rb * 32 + m * 16 + hh * 8 + gid;
            float ss = 0.f, qq = 0.f;
            #pragma unroll
            for (int b = 0; b < 4; ++b) {
                float2 pr = red[b * 128 + row];
                ss += pr.x; qq += pr.y;
            }
            float m_ = ss * (1.f/192.f);
            mu[m][hh] = m_;
            rs[m][hh] = rsqrtf(qq * (1.f/192.f) - m_*m_ + 1e-5f);
        }

    auto rowoff = [&](int lr) -> size_t {
        int win = blockIdx.x * 2 + (lr >> 6);
        int b = win >> 10, wlr = win & 1023, wh = wlr >> 5, ww = wlr & 31;
        int n = lr & 63, ii = n >> 3, jj = n & 7;
        int hf = (wh * 8 + ii + 4) & 255, wf = (ww * 8 + jj + 4) & 255;
        return (((size_t)b * 256 + hf) * 256 + wf) * 192;
    };

    #pragma unroll
    for (int m = 0; m < 2; ++m) {
        int lr = rb * 32 + m * 16 + gid;
        size_t roA = rowoff(lr), roB = rowoff(lr + 8);
        #pragma unroll
        for (int p = 0; p < 3; ++p)
            #pragma unroll
            for (int hh = 0; hh < 2; ++hh) {
                int col = cb * 48 + p * 16 + hh * 8 + 2 * tig;
                int i = m * 6 + p * 2 + hh;
                float2 xa = *(const float2*)(g_xt + roA + col);
                float2 za;
                za.x = xa.x + (c[i][0] - mu[m][0]) * rs[m][0] * g1[col]   + b1[col];
                za.y = xa.y + (c[i][1] - mu[m][0]) * rs[m][0] * g1[col+1] + b1[col+1];
                *(float2*)(g_x1 + roA + col) = za;
                float2 xb = *(const float2*)(g_xt + roB + col);
                float2 zb;
                zb.x = xb.x + (c[i][2] - mu[m][1]) * rs[m][1] * g1[col]   + b1[col];
                zb.y = xb.y + (c[i][3] - mu[m][1]) * rs[m][1] * g1[col+1] + b1[col+1];
                *(float2*)(g_x1 + roB + col) = zb;
            }
    }
}

// ---------------- kernel 5: MLP (64 tokens/CTA, 256 thr, 32x48 tiles) ----------------
// smem: Ahi 0 Alo 25600 | Hhi 51200 Hlo 76800 |
//       WB0 hi 102400 lo 130048 | WB1 hi 157696 lo 185344  -> 212992
#define MLP_SMEM 212992
__global__ void __launch_bounds__(256, 1)
k_mlp_tc(const float* __restrict__ fc1_b, const float* __restrict__ fc2_b,
         const float* __restrict__ g2, const float* __restrict__ b2,
         float* __restrict__ out) {
    extern __shared__ char smc[];
    const uint32_t sb = smem_u32(smc);
    char* A_HI = smc;          char* A_LO = smc + 25600;
    char* H_HI = smc + 51200;  char* H_LO = smc + 76800;
    const uint32_t WBh[2] = {sb + 102400, sb + 157696};
    const uint32_t WBl[2] = {sb + 130048, sb + 185344};
    int tid = threadIdx.x, wid = tid >> 5, lane = tid & 31;
    int rb = wid & 1, cb = wid >> 1;              // 2 rb x 4 cb
    int gid = lane >> 2, tig = lane & 3;
    size_t tok0 = (size_t)blockIdx.x * 64;
    const uint32_t aW  = sb + (uint32_t)(rb * 12800);          // 32 rows * 400B
    const uint32_t aWl = sb + 25600 + (uint32_t)(rb * 12800);
    const uint32_t hWb = sb + 51200 + (uint32_t)(rb * 12800);
    const uint32_t hWl = sb + 76800 + (uint32_t)(rb * 12800);
    const uint32_t wcb = (uint32_t)(cb * 6912);                // 48 rows * 144B

    cpstageW<256>(WBh[0], WBl[0], g_wh + OF1, g_wl + OF1, 192, 8, 192, 0, 72, tid);
    stage_linear<64, 256>(A_HI, A_LO, g_x1 + tok0 * 192, tid);

    float c[12][4], cf2[12][4];
    #pragma unroll
    for (int i = 0; i < 12; ++i) { c[i][0]=c[i][1]=c[i][2]=c[i][3]=0.f;
                                   cf2[i][0]=cf2[i][1]=cf2[i][2]=cf2[i][3]=0.f; }

    for (int t = 0; t < 24; ++t) {
        int g = t / 6, s = t % 6;
        cp_wait0();
        __syncthreads();
        if (t < 23) {
            int tn = t + 1, ng = tn / 6, ns = tn % 6;
            if (ns < 3)
                cpstageW<256>(WBh[tn & 1], WBl[tn & 1],
                              g_wh + OF1 + (size_t)ng * 192 * 192,
                              g_wl + OF1 + (size_t)ng * 192 * 192,
                              192, 8, 192, ns * 64, 72, tid);
            else
                cpstageW<256>(WBh[tn & 1], WBl[tn & 1],
                              g_wh + OF2, g_wl + OF2,
                              192, 8, 768, ng * 192 + (ns - 3) * 64, 72, tid);
        }
        if (s < 3) {
            // fc1 k-third s
            wgemm2<4, 2, 3, 200, 72>(aW + s * 128, aWl + s * 128,
                                     WBh[t & 1] + wcb, WBl[t & 1] + wcb, c, lane);
            if (s == 2) {
                // H = split(gelu(c + b1)), then clear c
                #pragma unroll
                for (int m = 0; m < 2; ++m) {
                    int lr = rb * 32 + m * 16 + gid;
                    #pragma unroll
                    for (int p = 0; p < 3; ++p)
                        #pragma unroll
                        for (int hh = 0; hh < 2; ++hh) {
                            int col = cb * 48 + p * 16 + hh * 8 + 2 * tig;
                            int bc = g * 192 + col;
                            int i = m * 6 + p * 2 + hh;
                            uint32_t hp, lp;
                            split2(gelu_fast(c[i][0] + fc1_b[bc]),
                                   gelu_fast(c[i][1] + fc1_b[bc+1]), hp, lp);
                            size_t dA = ((size_t)lr * 200 + col) * 2;
                            *(uint32_t*)(H_HI + dA) = hp; *(uint32_t*)(H_LO + dA) = lp;
                            split2(gelu_fast(c[i][2] + fc1_b[bc]),
                                   gelu_fast(c[i][3] + fc1_b[bc+1]), hp, lp);
                            size_t dB = ((size_t)(lr + 8) * 200 + col) * 2;
                            *(uint32_t*)(H_HI + dB) = hp; *(uint32_t*)(H_LO + dB) = lp;
                        }
                }
                #pragma unroll
                for (int i = 0; i < 12; ++i) { c[i][0]=c[i][1]=c[i][2]=c[i][3]=0.f; }
            }
        } else {
            // fc2 k-chunk (s-3) of this group's 192 hidden dims
            int kc = s - 3;
            wgemm2<4, 2, 3, 200, 72>(hWb + kc * 128, hWl + kc * 128,
                                     WBh[t & 1] + wcb, WBl[t & 1] + wcb, cf2, lane);
        }
    }

    // LN + residual epilogue (rows 64; cross-cb reduce via smem)
    float s2[2][2] = {{0,0},{0,0}}, q2[2][2] = {{0,0},{0,0}};
    #pragma unroll
    for (int m = 0; m < 2; ++m)
        #pragma unroll
        for (int p = 0; p < 3; ++p)
            #pragma unroll
            for (int hh = 0; hh < 2; ++hh) {
                int col = cb * 48 + p * 16 + hh * 8 + 2 * tig;
                int i = m * 6 + p * 2 + hh;
                float z0 = cf2[i][0] + fc2_b[col];
                float z1 = cf2[i][1] + fc2_b[col+1];
                float z2 = cf2[i][2] + fc2_b[col];
                float z3 = cf2[i][3] + fc2_b[col+1];
                s2[m][0] += z0 + z1; q2[m][0] += z0*z0 + z1*z1;
                s2[m][1] += z2 + z3; q2[m][1] += z2*z2 + z3*z3;
            }
    #pragma unroll
    for (int d = 1; d <= 2; d <<= 1)
        #pragma unroll
        for (int m = 0; m < 2; ++m)
            #pragma unroll
            for (int hh = 0; hh < 2; ++hh) {
                s2[m][hh] += __shfl_xor_sync(0xffffffffu, s2[m][hh], d);
                q2[m][hh] += __shfl_xor_sync(0xffffffffu, q2[m][hh], d);
            }
    float2* red = (float2*)(smc + 102400);   // W buffers dead
    __syncthreads();
    if (tig == 0)
        #pragma unroll
        for (int m = 0; m < 2; ++m)
            #pragma unroll
            for (int hh = 0; hh < 2; ++hh)
                red[cb * 64 + rb * 32 + m * 16 + hh * 8 + gid] = make_float2(s2[m][hh], q2[m][hh]);
    __syncthreads();
    float mu[2][2], rs[2][2];
    #pragma unroll
    for (int m = 0; m < 2; ++m)
        #pragma unroll
        for (int hh = 0; hh < 2; ++hh) {
            int row = rb * 32 + m * 16 + hh * 8 + gid;
            float ss = 0.f, qq = 0.f;
            #pragma unroll
            for (int b = 0; b < 4; ++b) {
                float2 pr = red[b * 64 + row];
                ss += pr.x; qq += pr.y;
            }
            float m_ = ss * (1.f/192.f);
            mu[m][hh] = m_;
            rs[m][hh] = rsqrtf(qq * (1.f/192.f) - m_*m_ + 1e-5f);
        }

    #pragma unroll
    for (int m = 0; m < 2; ++m) {
        size_t grA = (tok0 + rb * 32 + m * 16 + gid) * 192;
        size_t grB = grA + 8 * 192;
        #pragma unroll
        for (int p = 0; p < 3; ++p)
            #pragma unroll
            for (int hh = 0; hh < 2; ++hh) {
                int col = cb * 48 + p * 16 + hh * 8 + 2 * tig;
                int i = m * 6 + p * 2 + hh;
                float z0 = cf2[i][0] + fc2_b[col];
                float z1 = cf2[i][1] + fc2_b[col+1];
                float z2 = cf2[i][2] + fc2_b[col];
                float z3 = cf2[i][3] + fc2_b[col+1];
                float2 xa = *(const float2*)(g_x1 + grA + col);
                float2 oa;
                oa.x = xa.x + (z0 - mu[m][0]) * rs[m][0] * g2[col]   + b2[col];
                oa.y = xa.y + (z1 - mu[m][0]) * rs[m][0] * g2[col+1] + b2[col+1];
                *(float2*)(out + grA + col) = oa;
                float2 xb = *(const float2*)(g_x1 + grB + col);
                float2 ob;
                ob.x = xb.x + (z2 - mu[m][1]) * rs[m][1] * g2[col]   + b2[col];
                ob.y = xb.y + (z3 - mu[m][1]) * rs[m][1] * g2[col+1] + b2[col+1];
                *(float2*)(out + grB + col) = ob;
            }
    }
}

// ---------------- launch ----------------
extern "C" void kernel_launch(void* const* d_in, const int* in_sizes, int n_in,
                              void* d_out, int out_size) {
    const float* x        = (const float*)d_in[0];
    const float* feat     = (const float*)d_in[1];
    const float* attn_mask= (const float*)d_in[2];
    const int*   rel_index= (const int*)  d_in[3];
    const float* rel_tab  = (const float*)d_in[4];
    const float* q_w      = (const float*)d_in[5];
    const float* q_b      = (const float*)d_in[6];
    const float* kv_w     = (const float*)d_in[7];
    const float* kv_b     = (const float*)d_in[8];
    const float* proj_w   = (const float*)d_in[9];
    const float* proj_b   = (const float*)d_in[10];
    const float* merge_w  = (const float*)d_in[11];
    const float* n1g      = (const float*)d_in[12];
    const float* n1b      = (const float*)d_in[13];
    const float* n2g      = (const float*)d_in[14];
    const float* n2b      = (const float*)d_in[15];
    const float* fc1_w    = (const float*)d_in[16];
    const float* fc1_b    = (const float*)d_in[17];
    const float* fc2_w    = (const float*)d_in[18];
    const float* fc2_b    = (const float*)d_in[19];
    float* out = (float*)d_out;

    cudaFuncSetAttribute(k_qkv_tc,       cudaFuncAttributeMaxDynamicSharedMemorySize, QKV_SMEM);
    cudaFuncSetAttribute(k_attn_tc,      cudaFuncAttributeMaxDynamicSharedMemorySize, ATTN_SMEM);
    cudaFuncSetAttribute(k_projmerge_tc, cudaFuncAttributeMaxDynamicSharedMemorySize, PM_SMEM);
    cudaFuncSetAttribute(k_mlp_tc,       cudaFuncAttributeMaxDynamicSharedMemorySize, MLP_SMEM);

    k_transpose<<<dim3(2048, 6, 8), dim3(32, 8)>>>(x, feat);
    k_bias<<<96, 256>>>(rel_index, rel_tab);
    k_wsplit<<<(WTOT + 255) / 256, 256>>>(q_w, kv_w, proj_w, merge_w, fc1_w, fc2_w);
    k_qkv_tc<<<2048, 512, QKV_SMEM>>>(q_b, kv_b);
    k_attn_tc<<<NWIN * NHEAD, 128, ATTN_SMEM>>>(attn_mask);
    k_projmerge_tc<<<2048, 512, PM_SMEM>>>(proj_b, n1g, n1b);
    k_mlp_tc<<<TOKALL / 64, 256, MLP_SMEM>>>(fc1_b, fc2_b, n2g, n2b, out);
}

// round 12
// speedup vs baseline: 2.2530x; 1.0156x over previous
#include <cuda_runtime.h>
#include <cuda_bf16.h>
#include <cstdint>

// ---------------- problem constants ----------------
#define Hh 256
#define Ww 256
#define Bb 4
#define Cc 192
#define NHEAD 6
#define NWIN 4096
#define NTOK 64
#define TOKALL (Bb*Hh*Ww)
#define WINELEM (NTOK*Cc)

// weight-split offsets (elements)
#define OQ  0
#define OKV 36864
#define OP  110592
#define OM  147456
#define OF1 184320
#define OF2 331776
#define WTOT 479232

// ---------------- device scratch ----------------
__device__ float g_xt[(size_t)TOKALL * Cc];
__device__ float g_ft[(size_t)TOKALL * Cc];
__device__ float g_x1[(size_t)TOKALL * Cc];
__device__ float g_bm[(size_t)1024 * 6 * 4096];            // bias+mask combined
__device__ __align__(16) __nv_bfloat16 g_wh[WTOT];
__device__ __align__(16) __nv_bfloat16 g_wl[WTOT];
// pre-split activation planes
__device__ __align__(16) __nv_bfloat16 g_qh[(size_t)NWIN * WINELEM];
__device__ __align__(16) __nv_bfloat16 g_ql[(size_t)NWIN * WINELEM];
__device__ __align__(16) __nv_bfloat16 g_kh[(size_t)NWIN * WINELEM];
__device__ __align__(16) __nv_bfloat16 g_kl[(size_t)NWIN * WINELEM];
__device__ __align__(16) __nv_bfloat16 g_vth[(size_t)NWIN * 13824];  // [win][head][32][72]
__device__ __align__(16) __nv_bfloat16 g_vtl[(size_t)NWIN * 13824];
__device__ __align__(16) __nv_bfloat16 g_oh[(size_t)TOKALL * Cc];
__device__ __align__(16) __nv_bfloat16 g_ol[(size_t)TOKALL * Cc];

// ---------------- helpers ----------------
__device__ __forceinline__ float gelu_fast(float x) {
    float z = x * 0.7071067811865475f;
    float az = fabsf(z);
    float t = __fdividef(1.0f, fmaf(0.3275911f, az, 1.0f));
    float p = t * (0.254829592f + t * (-0.284496736f + t * (1.421413741f +
              t * (-1.453152027f + t * 1.061405429f))));
    float e = __expf(-az * az);
    float erfv = 1.0f - p * e;
    erfv = copysignf(erfv, z);
    return 0.5f * x * (1.0f + erfv);
}

__device__ __forceinline__ uint32_t smem_u32(const void* p) {
    uint32_t a;
    asm("{ .reg .u64 t; cvta.to.shared.u64 t, %1; cvt.u32.u64 %0, t; }" : "=r"(a) : "l"(p));
    return a;
}

__device__ __forceinline__ void split2(float v0, float v1, uint32_t& hp, uint32_t& lp) {
    __nv_bfloat16 h0 = __float2bfloat16(v0);
    __nv_bfloat16 h1 = __float2bfloat16(v1);
    __nv_bfloat16 l0 = __float2bfloat16(v0 - __bfloat162float(h0));
    __nv_bfloat16 l1 = __float2bfloat16(v1 - __bfloat162float(h1));
    hp = (uint32_t)__bfloat16_as_ushort(h0) | ((uint32_t)__bfloat16_as_ushort(h1) << 16);
    lp = (uint32_t)__bfloat16_as_ushort(l0) | ((uint32_t)__bfloat16_as_ushort(l1) << 16);
}

__device__ __forceinline__ void ldsm_x4(uint32_t (&r)[4], uint32_t a) {
    asm volatile("ldmatrix.sync.aligned.m8n8.x4.shared.b16 {%0,%1,%2,%3}, [%4];"
        : "=r"(r[0]), "=r"(r[1]), "=r"(r[2]), "=r"(r[3]) : "r"(a));
}

__device__ __forceinline__ void mma16816(float (&c)[4], const uint32_t (&a)[4],
                                         uint32_t b0, uint32_t b1) {
    asm volatile("mma.sync.aligned.m16n8k16.row.col.f32.bf16.bf16.f32 "
        "{%0,%1,%2,%3}, {%4,%5,%6,%7}, {%8,%9}, {%0,%1,%2,%3};"
        : "+f"(c[0]), "+f"(c[1]), "+f"(c[2]), "+f"(c[3])
        : "r"(a[0]), "r"(a[1]), "r"(a[2]), "r"(a[3]), "r"(b0), "r"(b1));
}

// R7 warp GEMM (used by attn + mlp)
template<int KS, int NT2, int AS, int WS>
__device__ __forceinline__ void wgemm(uint32_t aH, uint32_t aL,
                                      uint32_t wH, uint32_t wL,
                                      float (*c)[4], int lane) {
    const uint32_t aoff = (uint32_t)(((lane & 15) * AS + ((lane >> 4) << 3)) * 2);
    const uint32_t woff = (uint32_t)(((((lane >> 4) << 3) + (lane & 7)) * WS + (lane & 8)) * 2);
    aH += aoff; aL += aoff; wH += woff; wL += woff;
    #pragma unroll
    for (int ks = 0; ks < KS; ++ks) {
        uint32_t ah[4], al[4];
        ldsm_x4(ah, aH + ks * 32);
        ldsm_x4(al, aL + ks * 32);
        #pragma unroll
        for (int p = 0; p < NT2; ++p) {
            uint32_t bh[4], bl[4];
            ldsm_x4(bh, wH + p * (16 * WS * 2) + ks * 32);
            ldsm_x4(bl, wL + p * (16 * WS * 2) + ks * 32);
            mma16816(c[2*p],   ah, bh[0], bh[1]);
            mma16816(c[2*p],   al, bh[0], bh[1]);
            mma16816(c[2*p],   ah, bl[0], bl[1]);
            mma16816(c[2*p+1], ah, bh[2], bh[3]);
            mma16816(c[2*p+1], al, bh[2], bh[3]);
            mma16816(c[2*p+1], ah, bl[2], bl[3]);
        }
    }
}

// v2 warp GEMM: M2 m-tiles x NT2 n-tiles (32x48 when M2=2,NT2=3)
template<int KS, int M2, int NT2, int AS, int WS>
__device__ __forceinline__ void wgemm2(uint32_t aH, uint32_t aL,
                                       uint32_t wH, uint32_t wL,
                                       float (*c)[4], int lane) {
    const uint32_t aoff = (uint32_t)(((lane & 15) * AS + ((lane >> 4) << 3)) * 2);
    const uint32_t woff = (uint32_t)(((((lane >> 4) << 3) + (lane & 7)) * WS + (lane & 8)) * 2);
    aH += aoff; aL += aoff; wH += woff; wL += woff;
    #pragma unroll
    for (int ks = 0; ks < KS; ++ks) {
        uint32_t ah[M2][4], al[M2][4];
        #pragma unroll
        for (int m = 0; m < M2; ++m) {
            ldsm_x4(ah[m], aH + m * (16 * AS * 2) + ks * 32);
            ldsm_x4(al[m], aL + m * (16 * AS * 2) + ks * 32);
        }
        #pragma unroll
        for (int p = 0; p < NT2; ++p) {
            uint32_t bh[4], bl[4];
            ldsm_x4(bh, wH + p * (16 * WS * 2) + ks * 32);
            ldsm_x4(bl, wL + p * (16 * WS * 2) + ks * 32);
            #pragma unroll
            for (int m = 0; m < M2; ++m) {
                mma16816(c[m*2*NT2 + p*2],     ah[m], bh[0], bh[1]);
                mma16816(c[m*2*NT2 + p*2 + 1], ah[m], bh[2], bh[3]);
            }
            #pragma unroll
            for (int m = 0; m < M2; ++m) {
                mma16816(c[m*2*NT2 + p*2],     al[m], bh[0], bh[1]);
                mma16816(c[m*2*NT2 + p*2 + 1], al[m], bh[2], bh[3]);
            }
            #pragma unroll
            for (int m = 0; m < M2; ++m) {
                mma16816(c[m*2*NT2 + p*2],     ah[m], bl[0], bl[1]);
                mma16816(c[m*2*NT2 + p*2 + 1], ah[m], bl[2], bl[3]);
            }
        }
    }
}

// ---------------- cp.async helpers ----------------
__device__ __forceinline__ void cp16(uint32_t d, const void* s) {
    asm volatile("cp.async.cg.shared.global [%0], [%1], 16;" :: "r"(d), "l"(s) : "memory");
}
__device__ __forceinline__ void cp_commit() {
    asm volatile("cp.async.commit_group;" ::: "memory");
}
__device__ __forceinline__ void cp_wait0() {
    asm volatile("cp.async.wait_group 0;" ::: "memory");
}

template<int NTHR>
__device__ __forceinline__ void cpstageW(uint32_t dh, uint32_t dl,
        const __nv_bfloat16* sh, const __nv_bfloat16* sl,
        int rows, int ku4, int srck, int koff, int dstride, int tid) {
    int tot = rows * ku4;
    for (int i = tid; i < tot; i += NTHR) {
        int r = i / ku4, q = i - r * ku4;
        size_t s = (size_t)r * srck + koff + q * 8;
        uint32_t d = (uint32_t)(r * dstride + q * 8) * 2;
        cp16(dh + d, sh + s);
        cp16(dl + d, sl + s);
    }
    cp_commit();
}

template<int NROWS, int NTHR>
__device__ __forceinline__ void stage_linear(char* dh, char* dl, const float* src, int tid) {
    for (int i = tid; i < NROWS * 96; i += NTHR) {
        int r = i / 96, cp = (i - r * 96) * 2;
        float2 v = *(const float2*)(src + (size_t)r * 192 + cp);
        uint32_t hp, lp; split2(v.x, v.y, hp, lp);
        size_t d = ((size_t)r * 200 + cp) * 2;
        *(uint32_t*)(dh + d) = hp;
        *(uint32_t*)(dl + d) = lp;
    }
}

__device__ __forceinline__ void stage_gather(char* dh, char* dl, const float* src,
                                             int w0, int tid) {
    for (int i = tid; i < 128 * 96; i += 512) {
        int r = i / 96, cp = (i - r * 96) * 2;
        int win = w0 + (r >> 6);
        int b = win >> 10, wlr = win & 1023, wh = wlr >> 5, ww = wlr & 31;
        int n = r & 63, ii = n >> 3, jj = n & 7;
        int hh = (wh * 8 + ii + 4) & 255, wp = (ww * 8 + jj + 4) & 255;
        size_t off = (((size_t)b * 256 + hh) * 256 + wp) * 192 + cp;
        float2 v = *(const float2*)(src + off);
        uint32_t hp, lp; split2(v.x, v.y, hp, lp);
        size_t d = ((size_t)r * 200 + cp) * 2;
        *(uint32_t*)(dh + d) = hp;
        *(uint32_t*)(dl + d) = lp;
    }
}

// ---------------- kernel 0: NCHW -> NHWC ----------------
__global__ void k_transpose(const float* __restrict__ x, const float* __restrict__ f) {
    __shared__ float tile[32][33];
    int b = blockIdx.z >> 1;
    const float* src = (blockIdx.z & 1) ? f : x;
    float* dst = (blockIdx.z & 1) ? g_ft : g_xt;
    int hw0 = blockIdx.x * 32;
    int c0 = blockIdx.y * 32;
    #pragma unroll
    for (int i = threadIdx.y; i < 32; i += 8)
        tile[i][threadIdx.x] =
            src[((size_t)b * Cc + c0 + i) * (Hh * Ww) + hw0 + threadIdx.x];
    __syncthreads();
    #pragma unroll
    for (int i = threadIdx.y; i < 32; i += 8)
        dst[((size_t)b * (Hh * Ww) + hw0 + i) * Cc + c0 + threadIdx.x] =
            tile[threadIdx.x][i];
}

// ---------------- kernel 1: combined rel-bias + shift mask ----------------
__global__ void k_biasmask(const int* __restrict__ rel_index, const float* __restrict__ table,
                           const float* __restrict__ mask) {
    size_t idx = (size_t)blockIdx.x * 256 + threadIdx.x;
    if (idx < (size_t)1024 * 6 * 4096) {
        int nm = (int)(idx & 4095);
        int h = (int)((idx >> 12) % 6);
        size_t wl = idx / 24576;
        g_bm[idx] = table[rel_index[nm] * 6 + h] + mask[wl * 4096 + nm];
    }
}

// ---------------- kernel 1b: split ALL weights to bf16 hi/lo ----------------
__global__ void k_wsplit(const float* __restrict__ q_w, const float* __restrict__ kv_w,
                         const float* __restrict__ proj_w, const float* __restrict__ merge_w,
                         const float* __restrict__ fc1_w, const float* __restrict__ fc2_w) {
    int i = blockIdx.x * 256 + threadIdx.x;
    if (i >= WTOT) return;
    float v;
    if (i < OKV)       v = q_w[i];
    else if (i < OP)   v = kv_w[i - OKV];
    else if (i < OM)   v = proj_w[i - OP];
    else if (i < OF1)  v = merge_w[i - OM];
    else if (i < OF2)  v = fc1_w[i - OF1];
    else               v = fc2_w[i - OF2];
    __nv_bfloat16 h = __float2bfloat16(v);
    g_wh[i] = h;
    g_wl[i] = __float2bfloat16(v - __bfloat162float(h));
}

// ---------------- kernel 2: QKV -> pre-split planes ----------------
#define QKV_SMEM 212992
__global__ void __launch_bounds__(512, 1)
k_qkv_tc(const float* __restrict__ q_b, const float* __restrict__ kv_b) {
    extern __shared__ char smc[];
    const uint32_t sb = smem_u32(smc);
    char* A_HI = smc; char* A_LO = smc + 51200;
    const uint32_t WBh[2] = {sb + 102400, sb + 157696};
    const uint32_t WBl[2] = {sb + 130048, sb + 185344};
    int tid = threadIdx.x, wid = tid >> 5, lane = tid & 31;
    int rb = wid & 3, cb = wid >> 2;
    int gid = lane >> 2, tig = lane & 3;
    int w0 = blockIdx.x * 2;
    const uint32_t aW  = sb + (uint32_t)(rb * 12800);
    const uint32_t aWl = sb + 51200 + (uint32_t)(rb * 12800);
    const uint32_t wcb = (uint32_t)(cb * 6912);
    const float scale = 0.17677669529663687f;

    cpstageW<512>(WBh[0], WBl[0], g_wh + OQ, g_wl + OQ, 192, 8, 192, 0, 72, tid);
    stage_gather(A_HI, A_LO, g_xt, w0, tid);

    float c[12][4];
    #pragma unroll
    for (int i = 0; i < 12; ++i) { c[i][0]=c[i][1]=c[i][2]=c[i][3]=0.f; }

    for (int t = 0; t < 9; ++t) {
        cp_wait0();
        __syncthreads();
        if (t < 8) {
            int tn = t + 1, g = tn / 3, kt = tn % 3;
            size_t off = (g == 0) ? OQ : (g == 1) ? OKV : OKV + 36864;
            cpstageW<512>(WBh[tn & 1], WBl[tn & 1], g_wh + off, g_wl + off,
                          192, 8, 192, kt * 64, 72, tid);
        }
        if (t == 3) {
            stage_gather(A_HI, A_LO, g_ft, w0, tid);
            __syncthreads();
        }
        int kt = t % 3;
        wgemm2<4, 2, 3, 200, 72>(aW + kt * 128, aWl + kt * 128,
                                 WBh[t & 1] + wcb, WBl[t & 1] + wcb, c, lane);
        if (kt == 2) {
            int g = t / 3;
            if (g < 2) {
                __nv_bfloat16* dh = g ? g_kh : g_qh;
                __nv_bfloat16* dl = g ? g_kl : g_ql;
                const float* bias = g ? kv_b : q_b;
                float sc = g ? 1.f : scale;
                #pragma unroll
                for (int m = 0; m < 2; ++m) {
                    int tokA = rb * 32 + m * 16 + gid;
                    int tokB = tokA + 8;
                    #pragma unroll
                    for (int p = 0; p < 3; ++p)
                        #pragma unroll
                        for (int hh = 0; hh < 2; ++hh) {
                            int col = cb * 48 + p * 16 + hh * 8 + 2 * tig;
                            int i = m * 6 + p * 2 + hh;
                            int hd = col >> 5, dd = col & 31;
                            uint32_t hp, lp;
                            size_t offA = (size_t)(w0 + (tokA >> 6)) * 12288
                                        + hd * 2048 + (tokA & 63) * 32 + dd;
                            split2((c[i][0] + bias[col]) * sc,
                                   (c[i][1] + bias[col+1]) * sc, hp, lp);
                            *(uint32_t*)(dh + offA) = hp;
                            *(uint32_t*)(dl + offA) = lp;
                            size_t offB = (size_t)(w0 + (tokB >> 6)) * 12288
                                        + hd * 2048 + (tokB & 63) * 32 + dd;
                            split2((c[i][2] + bias[col]) * sc,
                                   (c[i][3] + bias[col+1]) * sc, hp, lp);
                            *(uint32_t*)(dh + offB) = hp;
                            *(uint32_t*)(dl + offB) = lp;
                        }
                }
            } else {
                // V: write transposed split planes [win][head][32 d][72]
                #pragma unroll
                for (int m = 0; m < 2; ++m) {
                    int tokA = rb * 32 + m * 16 + gid;
                    int tokB = tokA + 8;
                    #pragma unroll
                    for (int p = 0; p < 3; ++p)
                        #pragma unroll
                        for (int hh = 0; hh < 2; ++hh) {
                            int col = cb * 48 + p * 16 + hh * 8 + 2 * tig;
                            int i = m * 6 + p * 2 + hh;
                            int hd = col >> 5, dd = col & 31;
                            float b0 = kv_b[192 + col], b1 = kv_b[192 + col + 1];
                            size_t baseA = (size_t)(w0 + (tokA >> 6)) * 13824 + hd * 2304;
                            int keyA = tokA & 63;
                            float v0 = c[i][0] + b0, v1 = c[i][1] + b1;
                            __nv_bfloat16 h0 = __float2bfloat16(v0);
                            __nv_bfloat16 h1 = __float2bfloat16(v1);
                            g_vth[baseA + dd * 72 + keyA] = h0;
                            g_vth[baseA + (dd + 1) * 72 + keyA] = h1;
                            g_vtl[baseA + dd * 72 + keyA] =
                                __float2bfloat16(v0 - __bfloat162float(h0));
                            g_vtl[baseA + (dd + 1) * 72 + keyA] =
                                __float2bfloat16(v1 - __bfloat162float(h1));
                            size_t baseB = (size_t)(w0 + (tokB >> 6)) * 13824 + hd * 2304;
                            int keyB = tokB & 63;
                            float v2 = c[i][2] + b0, v3 = c[i][3] + b1;
                            __nv_bfloat16 h2 = __float2bfloat16(v2);
                            __nv_bfloat16 h3 = __float2bfloat16(v3);
                            g_vth[baseB + dd * 72 + keyB] = h2;
                            g_vth[baseB + (dd + 1) * 72 + keyB] = h3;
                            g_vtl[baseB + dd * 72 + keyB] =
                                __float2bfloat16(v2 - __bfloat162float(h2));
                            g_vtl[baseB + (dd + 1) * 72 + keyB] =
                                __float2bfloat16(v3 - __bfloat162float(h3));
                        }
                }
            }
            #pragma unroll
            for (int i = 0; i < 12; ++i) { c[i][0]=c[i][1]=c[i][2]=c[i][3]=0.f; }
        }
    }
}

// ---------------- kernel 3: windowed attention (cp.async staged) ----------------
#define ATTN_SMEM 48128
__global__ void __launch_bounds__(128)
k_attn_tc() {
    extern __shared__ char smc[];
    const uint32_t sb = smem_u32(smc);
    char* c_PHI = smc + 29696;   char* c_PLO = smc + 38912;
    const uint32_t sQH = sb, sQL = sb + 5120, sKH = sb + 10240, sKL = sb + 15360;
    const uint32_t sVH = sb + 20480, sVL = sb + 25088;
    int bx = blockIdx.x;
    int wi = bx & 4095;
    int h = bx >> 12;
    int wl = wi & 1023;
    int tid = threadIdx.x, wid = tid >> 5, lane = tid & 31;
    int gid = lane >> 2, tig = lane & 3;

    // cp.async staging: Q/K 64x32 bf16 planes -> stride 40 elems (80B rows)
    const __nv_bfloat16* qh = g_qh + (size_t)wi * 12288 + h * 2048;
    const __nv_bfloat16* ql = g_ql + (size_t)wi * 12288 + h * 2048;
    const __nv_bfloat16* kh = g_kh + (size_t)wi * 12288 + h * 2048;
    const __nv_bfloat16* kl = g_kl + (size_t)wi * 12288 + h * 2048;
    for (int i = tid; i < 256; i += 128) {
        int r = i >> 2, q4 = i & 3;
        uint32_t d = (uint32_t)(r * 80 + q4 * 16);
        const size_t s = (size_t)r * 32 + q4 * 8;
        cp16(sQH + d, qh + s);
        cp16(sQL + d, ql + s);
        cp16(sKH + d, kh + s);
        cp16(sKL + d, kl + s);
    }
    // V^T 32x72 planes -> stride 72 (144B rows, 9 chunks)
    const __nv_bfloat16* vth = g_vth + (size_t)wi * 13824 + h * 2304;
    const __nv_bfloat16* vtl = g_vtl + (size_t)wi * 13824 + h * 2304;
    for (int i = tid; i < 288; i += 128) {
        int r = i / 9, q9 = i - r * 9;
        uint32_t d = (uint32_t)(r * 144 + q9 * 16);
        const size_t s = (size_t)r * 72 + q9 * 8;
        cp16(sVH + d, vth + s);
        cp16(sVL + d, vtl + s);
    }
    cp_commit();
    cp_wait0();
    __syncthreads();

    float c[8][4];
    #pragma unroll
    for (int i = 0; i < 8; ++i) { c[i][0]=c[i][1]=c[i][2]=c[i][3]=0.f; }
    wgemm<2, 4, 40, 40>(sQH + (uint32_t)(wid * 1280), sQL + (uint32_t)(wid * 1280),
                        sKH, sKL, c, lane);

    int rA = wid * 16 + gid, rB = rA + 8;
    const float* bm = g_bm + ((size_t)wl * 6 + h) * 4096;
    float vA[16], vB[16];
    #pragma unroll
    for (int nt = 0; nt < 8; ++nt) {
        int col = nt * 8 + 2 * tig;
        float2 m0 = *(const float2*)(bm + rA * 64 + col);
        vA[2*nt]   = c[nt][0] + m0.x;
        vA[2*nt+1] = c[nt][1] + m0.y;
        float2 m1 = *(const float2*)(bm + rB * 64 + col);
        vB[2*nt]   = c[nt][2] + m1.x;
        vB[2*nt+1] = c[nt][3] + m1.y;
    }
    float mxA = -1e30f, mxB = -1e30f;
    #pragma unroll
    for (int j = 0; j < 16; ++j) { mxA = fmaxf(mxA, vA[j]); mxB = fmaxf(mxB, vB[j]); }
    mxA = fmaxf(mxA, __shfl_xor_sync(0xffffffffu, mxA, 1));
    mxA = fmaxf(mxA, __shfl_xor_sync(0xffffffffu, mxA, 2));
    mxB = fmaxf(mxB, __shfl_xor_sync(0xffffffffu, mxB, 1));
    mxB = fmaxf(mxB, __shfl_xor_sync(0xffffffffu, mxB, 2));
    float sA = 0.f, sB = 0.f;
    #pragma unroll
    for (int j = 0; j < 16; ++j) {
        vA[j] = __expf(vA[j] - mxA); sA += vA[j];
        vB[j] = __expf(vB[j] - mxB); sB += vB[j];
    }
    sA += __shfl_xor_sync(0xffffffffu, sA, 1);
    sA += __shfl_xor_sync(0xffffffffu, sA, 2);
    sB += __shfl_xor_sync(0xffffffffu, sB, 1);
    sB += __shfl_xor_sync(0xffffffffu, sB, 2);
    float invA = 1.f / sA, invB = 1.f / sB;
    #pragma unroll
    for (int nt = 0; nt < 8; ++nt) {
        int col = nt * 8 + 2 * tig;
        uint32_t hp, lp;
        split2(vA[2*nt] * invA, vA[2*nt+1] * invA, hp, lp);
        *(uint32_t*)(c_PHI + (rA * 72 + col) * 2) = hp;
        *(uint32_t*)(c_PLO + (rA * 72 + col) * 2) = lp;
        split2(vB[2*nt] * invB, vB[2*nt+1] * invB, hp, lp);
        *(uint32_t*)(c_PHI + (rB * 72 + col) * 2) = hp;
        *(uint32_t*)(c_PLO + (rB * 72 + col) * 2) = lp;
    }
    __syncwarp();

    float o[4][4];
    #pragma unroll
    for (int i = 0; i < 4; ++i) { o[i][0]=o[i][1]=o[i][2]=o[i][3]=0.f; }
    wgemm<4, 2, 72, 72>(sb + 29696 + (uint32_t)(wid * 2304), sb + 38912 + (uint32_t)(wid * 2304),
                        sVH, sVL, o, lane);

    // epilogue: write o as split planes, dense [token][192]
    #pragma unroll
    for (int nt = 0; nt < 4; ++nt) {
        int col = nt * 8 + 2 * tig;
        size_t gA = ((size_t)wi * 64 + rA) * 192 + h * 32 + col;
        size_t gB = ((size_t)wi * 64 + rB) * 192 + h * 32 + col;
        uint32_t hp, lp;
        split2(o[nt][0], o[nt][1], hp, lp);
        *(uint32_t*)(g_oh + gA) = hp;
        *(uint32_t*)(g_ol + gA) = lp;
        split2(o[nt][2], o[nt][3], hp, lp);
        *(uint32_t*)(g_oh + gB) = hp;
        *(uint32_t*)(g_ol + gB) = lp;
    }
}

// ---------------- kernel 4: proj -> merge -> LN -> residual ----------------
#define PM_SMEM 212992
__global__ void __launch_bounds__(512, 1)
k_projmerge_tc(const float* __restrict__ proj_b,
               const float* __restrict__ g1, const float* __restrict__ b1) {
    extern __shared__ char smc[];
    const uint32_t sb = smem_u32(smc);
    char* A_HI = smc; char* A_LO = smc + 51200;
    const uint32_t WBh[2] = {sb + 102400, sb + 157696};
    const uint32_t WBl[2] = {sb + 130048, sb + 185344};
    int tid = threadIdx.x, wid = tid >> 5, lane = tid & 31;
    int rb = wid & 3, cb = wid >> 2;
    int gid = lane >> 2, tig = lane & 3;
    size_t tok0 = (size_t)blockIdx.x * 128;
    const uint32_t aW  = sb + (uint32_t)(rb * 12800);
    const uint32_t aWl = sb + 51200 + (uint32_t)(rb * 12800);
    const uint32_t wcb = (uint32_t)(cb * 6912);

    cpstageW<512>(WBh[0], WBl[0], g_wh + OP, g_wl + OP, 192, 8, 192, 0, 72, tid);
    // stage A from pre-split o planes via cp.async (stride 200 dest)
    {
        const uint32_t aHI = sb, aLO = sb + 51200;
        for (int i = tid; i < 3072; i += 512) {
            int r = i / 24, q = i - r * 24;
            uint32_t d = (uint32_t)(r * 400 + q * 16);
            size_t s = (tok0 + r) * 192 + q * 8;
            cp16(aHI + d, g_oh + s);
            cp16(aLO + d, g_ol + s);
        }
        cp_commit();
    }

    float c[12][4];
    #pragma unroll
    for (int i = 0; i < 12; ++i) { c[i][0]=c[i][1]=c[i][2]=c[i][3]=0.f; }

    for (int t = 0; t < 6; ++t) {
        cp_wait0();
        __syncthreads();
        if (t < 5) {
            int tn = t + 1, kt = tn % 3;
            size_t off = (tn < 3) ? OP : OM;
            cpstageW<512>(WBh[tn & 1], WBl[tn & 1], g_wh + off, g_wl + off,
                          192, 8, 192, kt * 64, 72, tid);
        }
        if (t == 3) {
            #pragma unroll
            for (int m = 0; m < 2; ++m) {
                int lr = rb * 32 + m * 16 + gid;
                #pragma unroll
                for (int p = 0; p < 3; ++p)
                    #pragma unroll
                    for (int hh = 0; hh < 2; ++hh) {
                        int col = cb * 48 + p * 16 + hh * 8 + 2 * tig;
                        int i = m * 6 + p * 2 + hh;
                        uint32_t hp, lp;
                        split2(c[i][0] + proj_b[col], c[i][1] + proj_b[col+1], hp, lp);
                        size_t dA = ((size_t)lr * 200 + col) * 2;
                        *(uint32_t*)(A_HI + dA) = hp; *(uint32_t*)(A_LO + dA) = lp;
                        split2(c[i][2] + proj_b[col], c[i][3] + proj_b[col+1], hp, lp);
                        size_t dB = ((size_t)(lr + 8) * 200 + col) * 2;
                        *(uint32_t*)(A_HI + dB) = hp; *(uint32_t*)(A_LO + dB) = lp;
                    }
            }
            __syncthreads();
            #pragma unroll
            for (int i = 0; i < 12; ++i) { c[i][0]=c[i][1]=c[i][2]=c[i][3]=0.f; }
        }
        int kt = t % 3;
        wgemm2<4, 2, 3, 200, 72>(aW + kt * 128, aWl + kt * 128,
                                 WBh[t & 1] + wcb, WBl[t & 1] + wcb, c, lane);
    }

    float s[2][2] = {{0,0},{0,0}}, q[2][2] = {{0,0},{0,0}};
    #pragma unroll
    for (int m = 0; m < 2; ++m)
        #pragma unroll
        for (int p = 0; p < 3; ++p)
            #pragma unroll
            for (int hh = 0; hh < 2; ++hh) {
                int i = m * 6 + p * 2 + hh;
                s[m][0] += c[i][0] + c[i][1];
                q[m][0] += c[i][0]*c[i][0] + c[i][1]*c[i][1];
                s[m][1] += c[i][2] + c[i][3];
                q[m][1] += c[i][2]*c[i][2] + c[i][3]*c[i][3];
            }
    #pragma unroll
    for (int d = 1; d <= 2; d <<= 1)
        #pragma unroll
        for (int m = 0; m < 2; ++m)
            #pragma unroll
            for (int hh = 0; hh < 2; ++hh) {
                s[m][hh] += __shfl_xor_sync(0xffffffffu, s[m][hh], d);
                q[m][hh] += __shfl_xor_sync(0xffffffffu, q[m][hh], d);
            }
    float2* red = (float2*)(smc + 102400);
    if (tig == 0)
        #pragma unroll
        for (int m = 0; m < 2; ++m)
            #pragma unroll
            for (int hh = 0; hh < 2; ++hh)
                red[cb * 128 + rb * 32 + m * 16 + hh * 8 + gid] = make_float2(s[m][hh], q[m][hh]);
    __syncthreads();
    float mu[2][2], rs[2][2];
    #pragma unroll
    for (int m = 0; m < 2; ++m)
        #pragma unroll
        for (int hh = 0; hh < 2; ++hh) {
            int row = rb * 32 + m * 16 + hh * 8 + gid;
            float ss = 0.f, qq = 0.f;
            #pragma unroll
            for (int b = 0; b < 4; ++b) {
                float2 pr = red[b * 128 + row];
                ss += pr.x; qq += pr.y;
            }
            float m_ = ss * (1.f/192.f);
            mu[m][hh] = m_;
            rs[m][hh] = rsqrtf(qq * (1.f/192.f) - m_*m_ + 1e-5f);
        }

    auto rowoff = [&](int lr) -> size_t {
        int win = blockIdx.x * 2 + (lr >> 6);
        int b = win >> 10, wlr = win & 1023, wh = wlr >> 5, ww = wlr & 31;
        int n = lr & 63, ii = n >> 3, jj = n & 7;
        int hf = (wh * 8 + ii + 4) & 255, wf = (ww * 8 + jj + 4) & 255;
        return (((size_t)b * 256 + hf) * 256 + wf) * 192;
    };

    #pragma unroll
    for (int m = 0; m < 2; ++m) {
        int lr = rb * 32 + m * 16 + gid;
        size_t roA = rowoff(lr), roB = rowoff(lr + 8);
        #pragma unroll
        for (int p = 0; p < 3; ++p)
            #pragma unroll
            for (int hh = 0; hh < 2; ++hh) {
                int col = cb * 48 + p * 16 + hh * 8 + 2 * tig;
                int i = m * 6 + p * 2 + hh;
                float2 xa = *(const float2*)(g_xt + roA + col);
                float2 za;
                za.x = xa.x + (c[i][0] - mu[m][0]) * rs[m][0] * g1[col]   + b1[col];
                za.y = xa.y + (c[i][1] - mu[m][0]) * rs[m][0] * g1[col+1] + b1[col+1];
                *(float2*)(g_x1 + roA + col) = za;
                float2 xb = *(const float2*)(g_xt + roB + col);
                float2 zb;
                zb.x = xb.x + (c[i][2] - mu[m][1]) * rs[m][1] * g1[col]   + b1[col];
                zb.y = xb.y + (c[i][3] - mu[m][1]) * rs[m][1] * g1[col+1] + b1[col+1];
                *(float2*)(g_x1 + roB + col) = zb;
            }
    }
}

// ---------------- kernel 5: MLP (unchanged from R10) ----------------
#define MLP_SMEM 212992
__global__ void __launch_bounds__(256, 1)
k_mlp_tc(const float* __restrict__ fc1_b, const float* __restrict__ fc2_b,
         const float* __restrict__ g2, const float* __restrict__ b2,
         float* __restrict__ out) {
    extern __shared__ char smc[];
    const uint32_t sb = smem_u32(smc);
    char* A_HI = smc;          char* A_LO = smc + 25600;
    char* H_HI = smc + 51200;  char* H_LO = smc + 76800;
    const uint32_t WBh[2] = {sb + 102400, sb + 157696};
    const uint32_t WBl[2] = {sb + 130048, sb + 185344};
    int tid = threadIdx.x, wid = tid >> 5, lane = tid & 31;
    int rb = wid & 1, cb = wid >> 1;
    int gid = lane >> 2, tig = lane & 3;
    size_t tok0 = (size_t)blockIdx.x * 64;
    const uint32_t aW  = sb + (uint32_t)(rb * 12800);
    const uint32_t aWl = sb + 25600 + (uint32_t)(rb * 12800);
    const uint32_t hWb = sb + 51200 + (uint32_t)(rb * 12800);
    const uint32_t hWl = sb + 76800 + (uint32_t)(rb * 12800);
    const uint32_t wcb = (uint32_t)(cb * 6912);

    cpstageW<256>(WBh[0], WBl[0], g_wh + OF1, g_wl + OF1, 192, 8, 192, 0, 72, tid);
    stage_linear<64, 256>(A_HI, A_LO, g_x1 + tok0 * 192, tid);

    float c[12][4], cf2[12][4];
    #pragma unroll
    for (int i = 0; i < 12; ++i) { c[i][0]=c[i][1]=c[i][2]=c[i][3]=0.f;
                                   cf2[i][0]=cf2[i][1]=cf2[i][2]=cf2[i][3]=0.f; }

    for (int t = 0; t < 24; ++t) {
        int g = t / 6, s = t % 6;
        cp_wait0();
        __syncthreads();
        if (t < 23) {
            int tn = t + 1, ng = tn / 6, ns = tn % 6;
            if (ns < 3)
                cpstageW<256>(WBh[tn & 1], WBl[tn & 1],
                              g_wh + OF1 + (size_t)ng * 192 * 192,
                              g_wl + OF1 + (size_t)ng * 192 * 192,
                              192, 8, 192, ns * 64, 72, tid);
            else
                cpstageW<256>(WBh[tn & 1], WBl[tn & 1],
                              g_wh + OF2, g_wl + OF2,
                              192, 8, 768, ng * 192 + (ns - 3) * 64, 72, tid);
        }
        if (s < 3) {
            wgemm2<4, 2, 3, 200, 72>(aW + s * 128, aWl + s * 128,
                                     WBh[t & 1] + wcb, WBl[t & 1] + wcb, c, lane);
            if (s == 2) {
                #pragma unroll
                for (int m = 0; m < 2; ++m) {
                    int lr = rb * 32 + m * 16 + gid;
                    #pragma unroll
                    for (int p = 0; p < 3; ++p)
                        #pragma unroll
                        for (int hh = 0; hh < 2; ++hh) {
                            int col = cb * 48 + p * 16 + hh * 8 + 2 * tig;
                            int bc = g * 192 + col;
                            int i = m * 6 + p * 2 + hh;
                            uint32_t hp, lp;
                            split2(gelu_fast(c[i][0] + fc1_b[bc]),
                                   gelu_fast(c[i][1] + fc1_b[bc+1]), hp, lp);
                            size_t dA = ((size_t)lr * 200 + col) * 2;
                            *(uint32_t*)(H_HI + dA) = hp; *(uint32_t*)(H_LO + dA) = lp;
                            split2(gelu_fast(c[i][2] + fc1_b[bc]),
                                   gelu_fast(c[i][3] + fc1_b[bc+1]), hp, lp);
                            size_t dB = ((size_t)(lr + 8) * 200 + col) * 2;
                            *(uint32_t*)(H_HI + dB) = hp; *(uint32_t*)(H_LO + dB) = lp;
                        }
                }
                #pragma unroll
                for (int i = 0; i < 12; ++i) { c[i][0]=c[i][1]=c[i][2]=c[i][3]=0.f; }
            }
        } else {
            int kc = s - 3;
            wgemm2<4, 2, 3, 200, 72>(hWb + kc * 128, hWl + kc * 128,
                                     WBh[t & 1] + wcb, WBl[t & 1] + wcb, cf2, lane);
        }
    }

    float s2[2][2] = {{0,0},{0,0}}, q2[2][2] = {{0,0},{0,0}};
    #pragma unroll
    for (int m = 0; m < 2; ++m)
        #pragma unroll
        for (int p = 0; p < 3; ++p)
            #pragma unroll
            for (int hh = 0; hh < 2; ++hh) {
                int col = cb * 48 + p * 16 + hh * 8 + 2 * tig;
                int i = m * 6 + p * 2 + hh;
                float z0 = cf2[i][0] + fc2_b[col];
                float z1 = cf2[i][1] + fc2_b[col+1];
                float z2 = cf2[i][2] + fc2_b[col];
                float z3 = cf2[i][3] + fc2_b[col+1];
                s2[m][0] += z0 + z1; q2[m][0] += z0*z0 + z1*z1;
                s2[m][1] += z2 + z3; q2[m][1] += z2*z2 + z3*z3;
            }
    #pragma unroll
    for (int d = 1; d <= 2; d <<= 1)
        #pragma unroll
        for (int m = 0; m < 2; ++m)
            #pragma unroll
            for (int hh = 0; hh < 2; ++hh) {
                s2[m][hh] += __shfl_xor_sync(0xffffffffu, s2[m][hh], d);
                q2[m][hh] += __shfl_xor_sync(0xffffffffu, q2[m][hh], d);
            }
    float2* red = (float2*)(smc + 102400);
    __syncthreads();
    if (tig == 0)
        #pragma unroll
        for (int m = 0; m < 2; ++m)
            #pragma unroll
            for (int hh = 0; hh < 2; ++hh)
                red[cb * 64 + rb * 32 + m * 16 + hh * 8 + gid] = make_float2(s2[m][hh], q2[m][hh]);
    __syncthreads();
    float mu[2][2], rs[2][2];
    #pragma unroll
    for (int m = 0; m < 2; ++m)
        #pragma unroll
        for (int hh = 0; hh < 2; ++hh) {
            int row = rb * 32 + m * 16 + hh * 8 + gid;
            float ss = 0.f, qq = 0.f;
            #pragma unroll
            for (int b = 0; b < 4; ++b) {
                float2 pr = red[b * 64 + row];
                ss += pr.x; qq += pr.y;
            }
            float m_ = ss * (1.f/192.f);
            mu[m][hh] = m_;
            rs[m][hh] = rsqrtf(qq * (1.f/192.f) - m_*m_ + 1e-5f);
        }

    #pragma unroll
    for (int m = 0; m < 2; ++m) {
        size_t grA = (tok0 + rb * 32 + m * 16 + gid) * 192;
        size_t grB = grA + 8 * 192;
        #pragma unroll
        for (int p = 0; p < 3; ++p)
            #pragma unroll
            for (int hh = 0; hh < 2; ++hh) {
                int col = cb * 48 + p * 16 + hh * 8 + 2 * tig;
                int i = m * 6 + p * 2 + hh;
                float z0 = cf2[i][0] + fc2_b[col];
                float z1 = cf2[i][1] + fc2_b[col+1];
                float z2 = cf2[i][2] + fc2_b[col];
                float z3 = cf2[i][3] + fc2_b[col+1];
                float2 xa = *(const float2*)(g_x1 + grA + col);
                float2 oa;
                oa.x = xa.x + (z0 - mu[m][0]) * rs[m][0] * g2[col]   + b2[col];
                oa.y = xa.y + (z1 - mu[m][0]) * rs[m][0] * g2[col+1] + b2[col+1];
                *(float2*)(out + grA + col) = oa;
                float2 xb = *(const float2*)(g_x1 + grB + col);
                float2 ob;
                ob.x = xb.x + (z2 - mu[m][1]) * rs[m][1] * g2[col]   + b2[col];
                ob.y = xb.y + (z3 - mu[m][1]) * rs[m][1] * g2[col+1] + b2[col+1];
                *(float2*)(out + grB + col) = ob;
            }
    }
}

// ---------------- launch ----------------
extern "C" void kernel_launch(void* const* d_in, const int* in_sizes, int n_in,
                              void* d_out, int out_size) {
    const float* x        = (const float*)d_in[0];
    const float* feat     = (const float*)d_in[1];
    const float* attn_mask= (const float*)d_in[2];
    const int*   rel_index= (const int*)  d_in[3];
    const float* rel_tab  = (const float*)d_in[4];
    const float* q_w      = (const float*)d_in[5];
    const float* q_b      = (const float*)d_in[6];
    const float* kv_w     = (const float*)d_in[7];
    const float* kv_b     = (const float*)d_in[8];
    const float* proj_w   = (const float*)d_in[9];
    const float* proj_b   = (const float*)d_in[10];
    const float* merge_w  = (const float*)d_in[11];
    const float* n1g      = (const float*)d_in[12];
    const float* n1b      = (const float*)d_in[13];
    const float* n2g      = (const float*)d_in[14];
    const float* n2b      = (const float*)d_in[15];
    const float* fc1_w    = (const float*)d_in[16];
    const float* fc1_b    = (const float*)d_in[17];
    const float* fc2_w    = (const float*)d_in[18];
    const float* fc2_b    = (const float*)d_in[19];
    float* out = (float*)d_out;

    cudaFuncSetAttribute(k_qkv_tc,       cudaFuncAttributeMaxDynamicSharedMemorySize, QKV_SMEM);
    cudaFuncSetAttribute(k_attn_tc,      cudaFuncAttributeMaxDynamicSharedMemorySize, ATTN_SMEM);
    cudaFuncSetAttribute(k_projmerge_tc, cudaFuncAttributeMaxDynamicSharedMemorySize, PM_SMEM);
    cudaFuncSetAttribute(k_mlp_tc,       cudaFuncAttributeMaxDynamicSharedMemorySize, MLP_SMEM);

    k_transpose<<<dim3(2048, 6, 8), dim3(32, 8)>>>(x, feat);
    k_biasmask<<<98304, 256>>>(rel_index, rel_tab, attn_mask);
    k_wsplit<<<(WTOT + 255) / 256, 256>>>(q_w, kv_w, proj_w, merge_w, fc1_w, fc2_w);
    k_qkv_tc<<<2048, 512, QKV_SMEM>>>(q_b, kv_b);
    k_attn_tc<<<NWIN * NHEAD, 128, ATTN_SMEM>>>();
    k_projmerge_tc<<<2048, 512, PM_SMEM>>>(proj_b, n1g, n1b);
    k_mlp_tc<<<TOKALL / 64, 256, MLP_SMEM>>>(fc1_b, fc2_b, n2g, n2b, out);
}

// round 13
// speedup vs baseline: 2.2615x; 1.0038x over previous
#include <cuda_runtime.h>
#include <cuda_bf16.h>
#include <cstdint>

// ---------------- problem constants ----------------
#define Hh 256
#define Ww 256
#define Bb 4
#define Cc 192
#define NHEAD 6
#define NWIN 4096
#define NTOK 64
#define TOKALL (Bb*Hh*Ww)
#define WINELEM (NTOK*Cc)

// weight-split offsets (elements)
#define OQ  0
#define OKV 36864
#define OP  110592
#define OM  147456
#define OF1 184320
#define OF2 331776
#define WTOT 479232

// ---------------- device scratch ----------------
__device__ float g_xt[(size_t)TOKALL * Cc];
__device__ float g_ft[(size_t)TOKALL * Cc];
__device__ float g_x1[(size_t)TOKALL * Cc];
__device__ float g_bm[(size_t)1024 * 6 * 4096];            // bias+mask combined
__device__ __align__(16) __nv_bfloat16 g_wh[WTOT];
__device__ __align__(16) __nv_bfloat16 g_wl[WTOT];
// pre-split activation planes
__device__ __align__(16) __nv_bfloat16 g_qh[(size_t)NWIN * WINELEM];
__device__ __align__(16) __nv_bfloat16 g_ql[(size_t)NWIN * WINELEM];
__device__ __align__(16) __nv_bfloat16 g_kh[(size_t)NWIN * WINELEM];
__device__ __align__(16) __nv_bfloat16 g_kl[(size_t)NWIN * WINELEM];
__device__ __align__(16) __nv_bfloat16 g_vth[(size_t)NWIN * 13824];  // [win][head][32][72]
__device__ __align__(16) __nv_bfloat16 g_vtl[(size_t)NWIN * 13824];
__device__ __align__(16) __nv_bfloat16 g_oh[(size_t)TOKALL * Cc];
__device__ __align__(16) __nv_bfloat16 g_ol[(size_t)TOKALL * Cc];

// ---------------- helpers ----------------
__device__ __forceinline__ float gelu_fast(float x) {
    float z = x * 0.7071067811865475f;
    float az = fabsf(z);
    float t = __fdividef(1.0f, fmaf(0.3275911f, az, 1.0f));
    float p = t * (0.254829592f + t * (-0.284496736f + t * (1.421413741f +
              t * (-1.453152027f + t * 1.061405429f))));
    float e = __expf(-az * az);
    float erfv = 1.0f - p * e;
    erfv = copysignf(erfv, z);
    return 0.5f * x * (1.0f + erfv);
}

__device__ __forceinline__ uint32_t smem_u32(const void* p) {
    uint32_t a;
    asm("{ .reg .u64 t; cvta.to.shared.u64 t, %1; cvt.u32.u64 %0, t; }" : "=r"(a) : "l"(p));
    return a;
}

__device__ __forceinline__ void split2(float v0, float v1, uint32_t& hp, uint32_t& lp) {
    __nv_bfloat16 h0 = __float2bfloat16(v0);
    __nv_bfloat16 h1 = __float2bfloat16(v1);
    __nv_bfloat16 l0 = __float2bfloat16(v0 - __bfloat162float(h0));
    __nv_bfloat16 l1 = __float2bfloat16(v1 - __bfloat162float(h1));
    hp = (uint32_t)__bfloat16_as_ushort(h0) | ((uint32_t)__bfloat16_as_ushort(h1) << 16);
    lp = (uint32_t)__bfloat16_as_ushort(l0) | ((uint32_t)__bfloat16_as_ushort(l1) << 16);
}

__device__ __forceinline__ void ldsm_x4(uint32_t (&r)[4], uint32_t a) {
    asm volatile("ldmatrix.sync.aligned.m8n8.x4.shared.b16 {%0,%1,%2,%3}, [%4];"
        : "=r"(r[0]), "=r"(r[1]), "=r"(r[2]), "=r"(r[3]) : "r"(a));
}

// non-volatile: let ptxas schedule/interleave the MMA stream
__device__ __forceinline__ void mma16816(float (&c)[4], const uint32_t (&a)[4],
                                         uint32_t b0, uint32_t b1) {
    asm("mma.sync.aligned.m16n8k16.row.col.f32.bf16.bf16.f32 "
        "{%0,%1,%2,%3}, {%4,%5,%6,%7}, {%8,%9}, {%0,%1,%2,%3};"
        : "+f"(c[0]), "+f"(c[1]), "+f"(c[2]), "+f"(c[3])
        : "r"(a[0]), "r"(a[1]), "r"(a[2]), "r"(a[3]), "r"(b0), "r"(b1));
}

// R7 warp GEMM (used by attn + mlp)
template<int KS, int NT2, int AS, int WS>
__device__ __forceinline__ void wgemm(uint32_t aH, uint32_t aL,
                                      uint32_t wH, uint32_t wL,
                                      float (*c)[4], int lane) {
    const uint32_t aoff = (uint32_t)(((lane & 15) * AS + ((lane >> 4) << 3)) * 2);
    const uint32_t woff = (uint32_t)(((((lane >> 4) << 3) + (lane & 7)) * WS + (lane & 8)) * 2);
    aH += aoff; aL += aoff; wH += woff; wL += woff;
    #pragma unroll
    for (int ks = 0; ks < KS; ++ks) {
        uint32_t ah[4], al[4];
        ldsm_x4(ah, aH + ks * 32);
        ldsm_x4(al, aL + ks * 32);
        #pragma unroll
        for (int p = 0; p < NT2; ++p) {
            uint32_t bh[4], bl[4];
            ldsm_x4(bh, wH + p * (16 * WS * 2) + ks * 32);
            ldsm_x4(bl, wL + p * (16 * WS * 2) + ks * 32);
            mma16816(c[2*p],   ah, bh[0], bh[1]);
            mma16816(c[2*p],   al, bh[0], bh[1]);
            mma16816(c[2*p],   ah, bl[0], bl[1]);
            mma16816(c[2*p+1], ah, bh[2], bh[3]);
            mma16816(c[2*p+1], al, bh[2], bh[3]);
            mma16816(c[2*p+1], ah, bl[2], bl[3]);
        }
    }
}

// v2 warp GEMM: M2 m-tiles x NT2 n-tiles (32x48 when M2=2,NT2=3)
template<int KS, int M2, int NT2, int AS, int WS>
__device__ __forceinline__ void wgemm2(uint32_t aH, uint32_t aL,
                                       uint32_t wH, uint32_t wL,
                                       float (*c)[4], int lane) {
    const uint32_t aoff = (uint32_t)(((lane & 15) * AS + ((lane >> 4) << 3)) * 2);
    const uint32_t woff = (uint32_t)(((((lane >> 4) << 3) + (lane & 7)) * WS + (lane & 8)) * 2);
    aH += aoff; aL += aoff; wH += woff; wL += woff;
    #pragma unroll
    for (int ks = 0; ks < KS; ++ks) {
        uint32_t ah[M2][4], al[M2][4];
        #pragma unroll
        for (int m = 0; m < M2; ++m) {
            ldsm_x4(ah[m], aH + m * (16 * AS * 2) + ks * 32);
            ldsm_x4(al[m], aL + m * (16 * AS * 2) + ks * 32);
        }
        #pragma unroll
        for (int p = 0; p < NT2; ++p) {
            uint32_t bh[4], bl[4];
            ldsm_x4(bh, wH + p * (16 * WS * 2) + ks * 32);
            ldsm_x4(bl, wL + p * (16 * WS * 2) + ks * 32);
            #pragma unroll
            for (int m = 0; m < M2; ++m) {
                mma16816(c[m*2*NT2 + p*2],     ah[m], bh[0], bh[1]);
                mma16816(c[m*2*NT2 + p*2 + 1], ah[m], bh[2], bh[3]);
            }
            #pragma unroll
            for (int m = 0; m < M2; ++m) {
                mma16816(c[m*2*NT2 + p*2],     al[m], bh[0], bh[1]);
                mma16816(c[m*2*NT2 + p*2 + 1], al[m], bh[2], bh[3]);
            }
            #pragma unroll
            for (int m = 0; m < M2; ++m) {
                mma16816(c[m*2*NT2 + p*2],     ah[m], bl[0], bl[1]);
                mma16816(c[m*2*NT2 + p*2 + 1], ah[m], bl[2], bl[3]);
            }
        }
    }
}

// ---------------- cp.async helpers ----------------
__device__ __forceinline__ void cp16(uint32_t d, const void* s) {
    asm volatile("cp.async.cg.shared.global [%0], [%1], 16;" :: "r"(d), "l"(s) : "memory");
}
__device__ __forceinline__ void cp_commit() {
    asm volatile("cp.async.commit_group;" ::: "memory");
}
__device__ __forceinline__ void cp_wait0() {
    asm volatile("cp.async.wait_group 0;" ::: "memory");
}

template<int NTHR>
__device__ __forceinline__ void cpstageW(uint32_t dh, uint32_t dl,
        const __nv_bfloat16* sh, const __nv_bfloat16* sl,
        int rows, int ku4, int srck, int koff, int dstride, int tid) {
    int tot = rows * ku4;
    for (int i = tid; i < tot; i += NTHR) {
        int r = i / ku4, q = i - r * ku4;
        size_t s = (size_t)r * srck + koff + q * 8;
        uint32_t d = (uint32_t)(r * dstride + q * 8) * 2;
        cp16(dh + d, sh + s);
        cp16(dl + d, sl + s);
    }
    cp_commit();
}

template<int NROWS, int NTHR>
__device__ __forceinline__ void stage_linear(char* dh, char* dl, const float* src, int tid) {
    for (int i = tid; i < NROWS * 96; i += NTHR) {
        int r = i / 96, cp = (i - r * 96) * 2;
        float2 v = *(const float2*)(src + (size_t)r * 192 + cp);
        uint32_t hp, lp; split2(v.x, v.y, hp, lp);
        size_t d = ((size_t)r * 200 + cp) * 2;
        *(uint32_t*)(dh + d) = hp;
        *(uint32_t*)(dl + d) = lp;
    }
}

__device__ __forceinline__ void stage_gather(char* dh, char* dl, const float* src,
                                             int w0, int tid) {
    for (int i = tid; i < 128 * 96; i += 512) {
        int r = i / 96, cp = (i - r * 96) * 2;
        int win = w0 + (r >> 6);
        int b = win >> 10, wlr = win & 1023, wh = wlr >> 5, ww = wlr & 31;
        int n = r & 63, ii = n >> 3, jj = n & 7;
        int hh = (wh * 8 + ii + 4) & 255, wp = (ww * 8 + jj + 4) & 255;
        size_t off = (((size_t)b * 256 + hh) * 256 + wp) * 192 + cp;
        float2 v = *(const float2*)(src + off);
        uint32_t hp, lp; split2(v.x, v.y, hp, lp);
        size_t d = ((size_t)r * 200 + cp) * 2;
        *(uint32_t*)(dh + d) = hp;
        *(uint32_t*)(dl + d) = lp;
    }
}

// ---------------- kernel 0: NCHW -> NHWC ----------------
__global__ void k_transpose(const float* __restrict__ x, const float* __restrict__ f) {
    __shared__ float tile[32][33];
    int b = blockIdx.z >> 1;
    const float* src = (blockIdx.z & 1) ? f : x;
    float* dst = (blockIdx.z & 1) ? g_ft : g_xt;
    int hw0 = blockIdx.x * 32;
    int c0 = blockIdx.y * 32;
    #pragma unroll
    for (int i = threadIdx.y; i < 32; i += 8)
        tile[i][threadIdx.x] =
            src[((size_t)b * Cc + c0 + i) * (Hh * Ww) + hw0 + threadIdx.x];
    __syncthreads();
    #pragma unroll
    for (int i = threadIdx.y; i < 32; i += 8)
        dst[((size_t)b * (Hh * Ww) + hw0 + i) * Cc + c0 + threadIdx.x] =
            tile[threadIdx.x][i];
}

// ---------------- kernel 1: combined rel-bias + shift mask ----------------
__global__ void k_biasmask(const int* __restrict__ rel_index, const float* __restrict__ table,
                           const float* __restrict__ mask) {
    size_t idx = (size_t)blockIdx.x * 256 + threadIdx.x;
    if (idx < (size_t)1024 * 6 * 4096) {
        int nm = (int)(idx & 4095);
        int h = (int)((idx >> 12) % 6);
        size_t wl = idx / 24576;
        g_bm[idx] = table[rel_index[nm] * 6 + h] + mask[wl * 4096 + nm];
    }
}

// ---------------- kernel 1b: split ALL weights to bf16 hi/lo ----------------
__global__ void k_wsplit(const float* __restrict__ q_w, const float* __restrict__ kv_w,
                         const float* __restrict__ proj_w, const float* __restrict__ merge_w,
                         const float* __restrict__ fc1_w, const float* __restrict__ fc2_w) {
    int i = blockIdx.x * 256 + threadIdx.x;
    if (i >= WTOT) return;
    float v;
    if (i < OKV)       v = q_w[i];
    else if (i < OP)   v = kv_w[i - OKV];
    else if (i < OM)   v = proj_w[i - OP];
    else if (i < OF1)  v = merge_w[i - OM];
    else if (i < OF2)  v = fc1_w[i - OF1];
    else               v = fc2_w[i - OF2];
    __nv_bfloat16 h = __float2bfloat16(v);
    g_wh[i] = h;
    g_wl[i] = __float2bfloat16(v - __bfloat162float(h));
}

// ---------------- kernel 2: QKV -> pre-split planes ----------------
#define QKV_SMEM 212992
__global__ void __launch_bounds__(512, 1)
k_qkv_tc(const float* __restrict__ q_b, const float* __restrict__ kv_b) {
    extern __shared__ char smc[];
    const uint32_t sb = smem_u32(smc);
    char* A_HI = smc; char* A_LO = smc + 51200;
    const uint32_t WBh[2] = {sb + 102400, sb + 157696};
    const uint32_t WBl[2] = {sb + 130048, sb + 185344};
    int tid = threadIdx.x, wid = tid >> 5, lane = tid & 31;
    int rb = wid & 3, cb = wid >> 2;
    int gid = lane >> 2, tig = lane & 3;
    int w0 = blockIdx.x * 2;
    const uint32_t aW  = sb + (uint32_t)(rb * 12800);
    const uint32_t aWl = sb + 51200 + (uint32_t)(rb * 12800);
    const uint32_t wcb = (uint32_t)(cb * 6912);
    const float scale = 0.17677669529663687f;

    cpstageW<512>(WBh[0], WBl[0], g_wh + OQ, g_wl + OQ, 192, 8, 192, 0, 72, tid);
    stage_gather(A_HI, A_LO, g_xt, w0, tid);

    float c[12][4];
    #pragma unroll
    for (int i = 0; i < 12; ++i) { c[i][0]=c[i][1]=c[i][2]=c[i][3]=0.f; }

    for (int t = 0; t < 9; ++t) {
        cp_wait0();
        __syncthreads();
        if (t < 8) {
            int tn = t + 1, g = tn / 3, kt = tn % 3;
            size_t off = (g == 0) ? OQ : (g == 1) ? OKV : OKV + 36864;
            cpstageW<512>(WBh[tn & 1], WBl[tn & 1], g_wh + off, g_wl + off,
                          192, 8, 192, kt * 64, 72, tid);
        }
        if (t == 3) {
            stage_gather(A_HI, A_LO, g_ft, w0, tid);
            __syncthreads();
        }
        int kt = t % 3;
        wgemm2<4, 2, 3, 200, 72>(aW + kt * 128, aWl + kt * 128,
                                 WBh[t & 1] + wcb, WBl[t & 1] + wcb, c, lane);
        if (kt == 2) {
            int g = t / 3;
            if (g < 2) {
                __nv_bfloat16* dh = g ? g_kh : g_qh;
                __nv_bfloat16* dl = g ? g_kl : g_ql;
                const float* bias = g ? kv_b : q_b;
                float sc = g ? 1.f : scale;
                #pragma unroll
                for (int m = 0; m < 2; ++m) {
                    int tokA = rb * 32 + m * 16 + gid;
                    int tokB = tokA + 8;
                    #pragma unroll
                    for (int p = 0; p < 3; ++p)
                        #pragma unroll
                        for (int hh = 0; hh < 2; ++hh) {
                            int col = cb * 48 + p * 16 + hh * 8 + 2 * tig;
                            int i = m * 6 + p * 2 + hh;
                            int hd = col >> 5, dd = col & 31;
                            uint32_t hp, lp;
                            size_t offA = (size_t)(w0 + (tokA >> 6)) * 12288
                                        + hd * 2048 + (tokA & 63) * 32 + dd;
                            split2((c[i][0] + bias[col]) * sc,
                                   (c[i][1] + bias[col+1]) * sc, hp, lp);
                            *(uint32_t*)(dh + offA) = hp;
                            *(uint32_t*)(dl + offA) = lp;
                            size_t offB = (size_t)(w0 + (tokB >> 6)) * 12288
                                        + hd * 2048 + (tokB & 63) * 32 + dd;
                            split2((c[i][2] + bias[col]) * sc,
                                   (c[i][3] + bias[col+1]) * sc, hp, lp);
                            *(uint32_t*)(dh + offB) = hp;
                            *(uint32_t*)(dl + offB) = lp;
                        }
                }
            } else {
                // V: scatter split V^T into smem (all smem dead after barrier),
                // then coalesced vector copy to global planes.
                __syncthreads();             // all warps done with A/WB0 reads
                char* TVH = smc;             // 55296 B (covers A_HI + part of A_LO)
                char* TVL = smc + 55296;     // 55296 B (rest of A + start of WB0)
                #pragma unroll
                for (int m = 0; m < 2; ++m) {
                    int tokA = rb * 32 + m * 16 + gid;
                    int tokB = tokA + 8;
                    #pragma unroll
                    for (int p = 0; p < 3; ++p)
                        #pragma unroll
                        for (int hh = 0; hh < 2; ++hh) {
                            int col = cb * 48 + p * 16 + hh * 8 + 2 * tig;
                            int i = m * 6 + p * 2 + hh;
                            int hd = col >> 5, dd = col & 31;
                            float b0 = kv_b[192 + col], b1 = kv_b[192 + col + 1];
                            {
                                int win = tokA >> 6, key = tokA & 63;
                                size_t base = (size_t)win * 13824 + hd * 2304;
                                float v0 = c[i][0] + b0, v1 = c[i][1] + b1;
                                __nv_bfloat16 h0 = __float2bfloat16(v0);
                                __nv_bfloat16 h1 = __float2bfloat16(v1);
                                *(__nv_bfloat16*)(TVH + (base + dd * 72 + key) * 2) = h0;
                                *(__nv_bfloat16*)(TVH + (base + (dd + 1) * 72 + key) * 2) = h1;
                                *(__nv_bfloat16*)(TVL + (base + dd * 72 + key) * 2) =
                                    __float2bfloat16(v0 - __bfloat162float(h0));
                                *(__nv_bfloat16*)(TVL + (base + (dd + 1) * 72 + key) * 2) =
                                    __float2bfloat16(v1 - __bfloat162float(h1));
                            }
                            {
                                int win = tokB >> 6, key = tokB & 63;
                                size_t base = (size_t)win * 13824 + hd * 2304;
                                float v2 = c[i][2] + b0, v3 = c[i][3] + b1;
                                __nv_bfloat16 h2 = __float2bfloat16(v2);
                                __nv_bfloat16 h3 = __float2bfloat16(v3);
                                *(__nv_bfloat16*)(TVH + (base + dd * 72 + key) * 2) = h2;
                                *(__nv_bfloat16*)(TVH + (base + (dd + 1) * 72 + key) * 2) = h3;
                                *(__nv_bfloat16*)(TVL + (base + dd * 72 + key) * 2) =
                                    __float2bfloat16(v2 - __bfloat162float(h2));
                                *(__nv_bfloat16*)(TVL + (base + (dd + 1) * 72 + key) * 2) =
                                    __float2bfloat16(v3 - __bfloat162float(h3));
                            }
                        }
                }
                __syncthreads();
                const uint4* shv = (const uint4*)TVH;
                const uint4* slv = (const uint4*)TVL;
                uint4* dh4 = (uint4*)(g_vth + (size_t)w0 * 13824);
                uint4* dl4 = (uint4*)(g_vtl + (size_t)w0 * 13824);
                for (int i = tid; i < 3456; i += 512) {
                    dh4[i] = shv[i];
                    dl4[i] = slv[i];
                }
            }
            #pragma unroll
            for (int i = 0; i < 12; ++i) { c[i][0]=c[i][1]=c[i][2]=c[i][3]=0.f; }
        }
    }
}

// ---------------- kernel 3: windowed attention (cp.async staged) ----------------
#define ATTN_SMEM 48128
__global__ void __launch_bounds__(128)
k_attn_tc() {
    extern __shared__ char smc[];
    const uint32_t sb = smem_u32(smc);
    char* c_PHI = smc + 29696;   char* c_PLO = smc + 38912;
    const uint32_t sQH = sb, sQL = sb + 5120, sKH = sb + 10240, sKL = sb + 15360;
    const uint32_t sVH = sb + 20480, sVL = sb + 25088;
    int bx = blockIdx.x;
    int wi = bx & 4095;
    int h = bx >> 12;
    int wl = wi & 1023;
    int tid = threadIdx.x, wid = tid >> 5, lane = tid & 31;
    int gid = lane >> 2, tig = lane & 3;

    const __nv_bfloat16* qh = g_qh + (size_t)wi * 12288 + h * 2048;
    const __nv_bfloat16* ql = g_ql + (size_t)wi * 12288 + h * 2048;
    const __nv_bfloat16* kh = g_kh + (size_t)wi * 12288 + h * 2048;
    const __nv_bfloat16* kl = g_kl + (size_t)wi * 12288 + h * 2048;
    for (int i = tid; i < 256; i += 128) {
        int r = i >> 2, q4 = i & 3;
        uint32_t d = (uint32_t)(r * 80 + q4 * 16);
        const size_t s = (size_t)r * 32 + q4 * 8;
        cp16(sQH + d, qh + s);
        cp16(sQL + d, ql + s);
        cp16(sKH + d, kh + s);
        cp16(sKL + d, kl + s);
    }
    const __nv_bfloat16* vth = g_vth + (size_t)wi * 13824 + h * 2304;
    const __nv_bfloat16* vtl = g_vtl + (size_t)wi * 13824 + h * 2304;
    for (int i = tid; i < 288; i += 128) {
        int r = i / 9, q9 = i - r * 9;
        uint32_t d = (uint32_t)(r * 144 + q9 * 16);
        const size_t s = (size_t)r * 72 + q9 * 8;
        cp16(sVH + d, vth + s);
        cp16(sVL + d, vtl + s);
    }
    cp_commit();
    cp_wait0();
    __syncthreads();

    float c[8][4];
    #pragma unroll
    for (int i = 0; i < 8; ++i) { c[i][0]=c[i][1]=c[i][2]=c[i][3]=0.f; }
    wgemm<2, 4, 40, 40>(sQH + (uint32_t)(wid * 1280), sQL + (uint32_t)(wid * 1280),
                        sKH, sKL, c, lane);

    int rA = wid * 16 + gid, rB = rA + 8;
    const float* bm = g_bm + ((size_t)wl * 6 + h) * 4096;
    float vA[16], vB[16];
    #pragma unroll
    for (int nt = 0; nt < 8; ++nt) {
        int col = nt * 8 + 2 * tig;
        float2 m0 = *(const float2*)(bm + rA * 64 + col);
        vA[2*nt]   = c[nt][0] + m0.x;
        vA[2*nt+1] = c[nt][1] + m0.y;
        float2 m1 = *(const float2*)(bm + rB * 64 + col);
        vB[2*nt]   = c[nt][2] + m1.x;
        vB[2*nt+1] = c[nt][3] + m1.y;
    }
    float mxA = -1e30f, mxB = -1e30f;
    #pragma unroll
    for (int j = 0; j < 16; ++j) { mxA = fmaxf(mxA, vA[j]); mxB = fmaxf(mxB, vB[j]); }
    mxA = fmaxf(mxA, __shfl_xor_sync(0xffffffffu, mxA, 1));
    mxA = fmaxf(mxA, __shfl_xor_sync(0xffffffffu, mxA, 2));
    mxB = fmaxf(mxB, __shfl_xor_sync(0xffffffffu, mxB, 1));
    mxB = fmaxf(mxB, __shfl_xor_sync(0xffffffffu, mxB, 2));
    float sA = 0.f, sB = 0.f;
    #pragma unroll
    for (int j = 0; j < 16; ++j) {
        vA[j] = __expf(vA[j] - mxA); sA += vA[j];
        vB[j] = __expf(vB[j] - mxB); sB += vB[j];
    }
    sA += __shfl_xor_sync(0xffffffffu, sA, 1);
    sA += __shfl_xor_sync(0xffffffffu, sA, 2);
    sB += __shfl_xor_sync(0xffffffffu, sB, 1);
    sB += __shfl_xor_sync(0xffffffffu, sB, 2);
    float invA = 1.f / sA, invB = 1.f / sB;
    #pragma unroll
    for (int nt = 0; nt < 8; ++nt) {
        int col = nt * 8 + 2 * tig;
        uint32_t hp, lp;
        split2(vA[2*nt] * invA, vA[2*nt+1] * invA, hp, lp);
        *(uint32_t*)(c_PHI + (rA * 72 + col) * 2) = hp;
        *(uint32_t*)(c_PLO + (rA * 72 + col) * 2) = lp;
        split2(vB[2*nt] * invB, vB[2*nt+1] * invB, hp, lp);
        *(uint32_t*)(c_PHI + (rB * 72 + col) * 2) = hp;
        *(uint32_t*)(c_PLO + (rB * 72 + col) * 2) = lp;
    }
    __syncwarp();

    float o[4][4];
    #pragma unroll
    for (int i = 0; i < 4; ++i) { o[i][0]=o[i][1]=o[i][2]=o[i][3]=0.f; }
    wgemm<4, 2, 72, 72>(sb + 29696 + (uint32_t)(wid * 2304), sb + 38912 + (uint32_t)(wid * 2304),
                        sVH, sVL, o, lane);

    #pragma unroll
    for (int nt = 0; nt < 4; ++nt) {
        int col = nt * 8 + 2 * tig;
        size_t gA = ((size_t)wi * 64 + rA) * 192 + h * 32 + col;
        size_t gB = ((size_t)wi * 64 + rB) * 192 + h * 32 + col;
        uint32_t hp, lp;
        split2(o[nt][0], o[nt][1], hp, lp);
        *(uint32_t*)(g_oh + gA) = hp;
        *(uint32_t*)(g_ol + gA) = lp;
        split2(o[nt][2], o[nt][3], hp, lp);
        *(uint32_t*)(g_oh + gB) = hp;
        *(uint32_t*)(g_ol + gB) = lp;
    }
}

// ---------------- kernel 4: proj -> merge -> LN -> residual ----------------
#define PM_SMEM 212992
__global__ void __launch_bounds__(512, 1)
k_projmerge_tc(const float* __restrict__ proj_b,
               const float* __restrict__ g1, const float* __restrict__ b1) {
    extern __shared__ char smc[];
    const uint32_t sb = smem_u32(smc);
    char* A_HI = smc; char* A_LO = smc + 51200;
    const uint32_t WBh[2] = {sb + 102400, sb + 157696};
    const uint32_t WBl[2] = {sb + 130048, sb + 185344};
    int tid = threadIdx.x, wid = tid >> 5, lane = tid & 31;
    int rb = wid & 3, cb = wid >> 2;
    int gid = lane >> 2, tig = lane & 3;
    size_t tok0 = (size_t)blockIdx.x * 128;
    const uint32_t aW  = sb + (uint32_t)(rb * 12800);
    const uint32_t aWl = sb + 51200 + (uint32_t)(rb * 12800);
    const uint32_t wcb = (uint32_t)(cb * 6912);

    cpstageW<512>(WBh[0], WBl[0], g_wh + OP, g_wl + OP, 192, 8, 192, 0, 72, tid);
    {
        const uint32_t aHI = sb, aLO = sb + 51200;
        for (int i = tid; i < 3072; i += 512) {
            int r = i / 24, q = i - r * 24;
            uint32_t d = (uint32_t)(r * 400 + q * 16);
            size_t s = (tok0 + r) * 192 + q * 8;
            cp16(aHI + d, g_oh + s);
            cp16(aLO + d, g_ol + s);
        }
        cp_commit();
    }

    float c[12][4];
    #pragma unroll
    for (int i = 0; i < 12; ++i) { c[i][0]=c[i][1]=c[i][2]=c[i][3]=0.f; }

    for (int t = 0; t < 6; ++t) {
        cp_wait0();
        __syncthreads();
        if (t < 5) {
            int tn = t + 1, kt = tn % 3;
            size_t off = (tn < 3) ? OP : OM;
            cpstageW<512>(WBh[tn & 1], WBl[tn & 1], g_wh + off, g_wl + off,
                          192, 8, 192, kt * 64, 72, tid);
        }
        if (t == 3) {
            #pragma unroll
            for (int m = 0; m < 2; ++m) {
                int lr = rb * 32 + m * 16 + gid;
                #pragma unroll
                for (int p = 0; p < 3; ++p)
                    #pragma unroll
                    for (int hh = 0; hh < 2; ++hh) {
                        int col = cb * 48 + p * 16 + hh * 8 + 2 * tig;
                        int i = m * 6 + p * 2 + hh;
                        uint32_t hp, lp;
                        split2(c[i][0] + proj_b[col], c[i][1] + proj_b[col+1], hp, lp);
                        size_t dA = ((size_t)lr * 200 + col) * 2;
                        *(uint32_t*)(A_HI + dA) = hp; *(uint32_t*)(A_LO + dA) = lp;
                        split2(c[i][2] + proj_b[col], c[i][3] + proj_b[col+1], hp, lp);
                        size_t dB = ((size_t)(lr + 8) * 200 + col) * 2;
                        *(uint32_t*)(A_HI + dB) = hp; *(uint32_t*)(A_LO + dB) = lp;
                    }
            }
            __syncthreads();
            #pragma unroll
            for (int i = 0; i < 12; ++i) { c[i][0]=c[i][1]=c[i][2]=c[i][3]=0.f; }
        }
        int kt = t % 3;
        wgemm2<4, 2, 3, 200, 72>(aW + kt * 128, aWl + kt * 128,
                                 WBh[t & 1] + wcb, WBl[t & 1] + wcb, c, lane);
    }

    float s[2][2] = {{0,0},{0,0}}, q[2][2] = {{0,0},{0,0}};
    #pragma unroll
    for (int m = 0; m < 2; ++m)
        #pragma unroll
        for (int p = 0; p < 3; ++p)
            #pragma unroll
            for (int hh = 0; hh < 2; ++hh) {
                int i = m * 6 + p * 2 + hh;
                s[m][0] += c[i][0] + c[i][1];
                q[m][0] += c[i][0]*c[i][0] + c[i][1]*c[i][1];
                s[m][1] += c[i][2] + c[i][3];
                q[m][1] += c[i][2]*c[i][2] + c[i][3]*c[i][3];
            }
    #pragma unroll
    for (int d = 1; d <= 2; d <<= 1)
        #pragma unroll
        for (int m = 0; m < 2; ++m)
            #pragma unroll
            for (int hh = 0; hh < 2; ++hh) {
                s[m][hh] += __shfl_xor_sync(0xffffffffu, s[m][hh], d);
                q[m][hh] += __shfl_xor_sync(0xffffffffu, q[m][hh], d);
            }
    float2* red = (float2*)(smc + 102400);
    if (tig == 0)
        #pragma unroll
        for (int m = 0; m < 2; ++m)
            #pragma unroll
            for (int hh = 0; hh < 2; ++hh)
                red[cb * 128 + rb * 32 + m * 16 + hh * 8 + gid] = make_float2(s[m][hh], q[m][hh]);
    __syncthreads();
    float mu[2][2], rs[2][2];
    #pragma unroll
    for (int m = 0; m < 2; ++m)
        #pragma unroll
        for (int hh = 0; hh < 2; ++hh) {
            int row = rb * 32 + m * 16 + hh * 8 + gid;
            float ss = 0.f, qq = 0.f;
            #pragma unroll
            for (int b = 0; b < 4; ++b) {
                float2 pr = red[b * 128 + row];
                ss += pr.x; qq += pr.y;
            }
            float m_ = ss * (1.f/192.f);
            mu[m][hh] = m_;
            rs[m][hh] = rsqrtf(qq * (1.f/192.f) - m_*m_ + 1e-5f);
        }

    auto rowoff = [&](int lr) -> size_t {
        int win = blockIdx.x * 2 + (lr >> 6);
        int b = win >> 10, wlr = win & 1023, wh = wlr >> 5, ww = wlr & 31;
        int n = lr & 63, ii = n >> 3, jj = n & 7;
        int hf = (wh * 8 + ii + 4) & 255, wf = (ww * 8 + jj + 4) & 255;
        return (((size_t)b * 256 + hf) * 256 + wf) * 192;
    };

    #pragma unroll
    for (int m = 0; m < 2; ++m) {
        int lr = rb * 32 + m * 16 + gid;
        size_t roA = rowoff(lr), roB = rowoff(lr + 8);
        #pragma unroll
        for (int p = 0; p < 3; ++p)
            #pragma unroll
            for (int hh = 0; hh < 2; ++hh) {
                int col = cb * 48 + p * 16 + hh * 8 + 2 * tig;
                int i = m * 6 + p * 2 + hh;
                float2 xa = *(const float2*)(g_xt + roA + col);
                float2 za;
                za.x = xa.x + (c[i][0] - mu[m][0]) * rs[m][0] * g1[col]   + b1[col];
                za.y = xa.y + (c[i][1] - mu[m][0]) * rs[m][0] * g1[col+1] + b1[col+1];
                *(float2*)(g_x1 + roA + col) = za;
                float2 xb = *(const float2*)(g_xt + roB + col);
                float2 zb;
                zb.x = xb.x + (c[i][2] - mu[m][1]) * rs[m][1] * g1[col]   + b1[col];
                zb.y = xb.y + (c[i][3] - mu[m][1]) * rs[m][1] * g1[col+1] + b1[col+1];
                *(float2*)(g_x1 + roB + col) = zb;
            }
    }
}

// ---------------- kernel 5: MLP (unchanged) ----------------
#define MLP_SMEM 212992
__global__ void __launch_bounds__(256, 1)
k_mlp_tc(const float* __restrict__ fc1_b, const float* __restrict__ fc2_b,
         const float* __restrict__ g2, const float* __restrict__ b2,
         float* __restrict__ out) {
    extern __shared__ char smc[];
    const uint32_t sb = smem_u32(smc);
    char* A_HI = smc;          char* A_LO = smc + 25600;
    char* H_HI = smc + 51200;  char* H_LO = smc + 76800;
    const uint32_t WBh[2] = {sb + 102400, sb + 157696};
    const uint32_t WBl[2] = {sb + 130048, sb + 185344};
    int tid = threadIdx.x, wid = tid >> 5, lane = tid & 31;
    int rb = wid & 1, cb = wid >> 1;
    int gid = lane >> 2, tig = lane & 3;
    size_t tok0 = (size_t)blockIdx.x * 64;
    const uint32_t aW  = sb + (uint32_t)(rb * 12800);
    const uint32_t aWl = sb + 25600 + (uint32_t)(rb * 12800);
    const uint32_t hWb = sb + 51200 + (uint32_t)(rb * 12800);
    const uint32_t hWl = sb + 76800 + (uint32_t)(rb * 12800);
    const uint32_t wcb = (uint32_t)(cb * 6912);

    cpstageW<256>(WBh[0], WBl[0], g_wh + OF1, g_wl + OF1, 192, 8, 192, 0, 72, tid);
    stage_linear<64, 256>(A_HI, A_LO, g_x1 + tok0 * 192, tid);

    float c[12][4], cf2[12][4];
    #pragma unroll
    for (int i = 0; i < 12; ++i) { c[i][0]=c[i][1]=c[i][2]=c[i][3]=0.f;
                                   cf2[i][0]=cf2[i][1]=cf2[i][2]=cf2[i][3]=0.f; }

    for (int t = 0; t < 24; ++t) {
        int g = t / 6, s = t % 6;
        cp_wait0();
        __syncthreads();
        if (t < 23) {
            int tn = t + 1, ng = tn / 6, ns = tn % 6;
            if (ns < 3)
                cpstageW<256>(WBh[tn & 1], WBl[tn & 1],
                              g_wh + OF1 + (size_t)ng * 192 * 192,
                              g_wl + OF1 + (size_t)ng * 192 * 192,
                              192, 8, 192, ns * 64, 72, tid);
            else
                cpstageW<256>(WBh[tn & 1], WBl[tn & 1],
                              g_wh + OF2, g_wl + OF2,
                              192, 8, 768, ng * 192 + (ns - 3) * 64, 72, tid);
        }
        if (s < 3) {
            wgemm2<4, 2, 3, 200, 72>(aW + s * 128, aWl + s * 128,
                                     WBh[t & 1] + wcb, WBl[t & 1] + wcb, c, lane);
            if (s == 2) {
                #pragma unroll
                for (int m = 0; m < 2; ++m) {
                    int lr = rb * 32 + m * 16 + gid;
                    #pragma unroll
                    for (int p = 0; p < 3; ++p)
                        #pragma unroll
                        for (int hh = 0; hh < 2; ++hh) {
                            int col = cb * 48 + p * 16 + hh * 8 + 2 * tig;
                            int bc = g * 192 + col;
                            int i = m * 6 + p * 2 + hh;
                            uint32_t hp, lp;
                            split2(gelu_fast(c[i][0] + fc1_b[bc]),
                                   gelu_fast(c[i][1] + fc1_b[bc+1]), hp, lp);
                            size_t dA = ((size_t)lr * 200 + col) * 2;
                            *(uint32_t*)(H_HI + dA) = hp; *(uint32_t*)(H_LO + dA) = lp;
                            split2(gelu_fast(c[i][2] + fc1_b[bc]),
                                   gelu_fast(c[i][3] + fc1_b[bc+1]), hp, lp);
                            size_t dB = ((size_t)(lr + 8) * 200 + col) * 2;
                            *(uint32_t*)(H_HI + dB) = hp; *(uint32_t*)(H_LO + dB) = lp;
                        }
                }
                #pragma unroll
                for (int i = 0; i < 12; ++i) { c[i][0]=c[i][1]=c[i][2]=c[i][3]=0.f; }
            }
        } else {
            int kc = s - 3;
            wgemm2<4, 2, 3, 200, 72>(hWb + kc * 128, hWl + kc * 128,
                                     WBh[t & 1] + wcb, WBl[t & 1] + wcb, cf2, lane);
        }
    }

    float s2[2][2] = {{0,0},{0,0}}, q2[2][2] = {{0,0},{0,0}};
    #pragma unroll
    for (int m = 0; m < 2; ++m)
        #pragma unroll
        for (int p = 0; p < 3; ++p)
            #pragma unroll
            for (int hh = 0; hh < 2; ++hh) {
                int col = cb * 48 + p * 16 + hh * 8 + 2 * tig;
                int i = m * 6 + p * 2 + hh;
                float z0 = cf2[i][0] + fc2_b[col];
                float z1 = cf2[i][1] + fc2_b[col+1];
                float z2 = cf2[i][2] + fc2_b[col];
                float z3 = cf2[i][3] + fc2_b[col+1];
                s2[m][0] += z0 + z1; q2[m][0] += z0*z0 + z1*z1;
                s2[m][1] += z2 + z3; q2[m][1] += z2*z2 + z3*z3;
            }
    #pragma unroll
    for (int d = 1; d <= 2; d <<= 1)
        #pragma unroll
        for (int m = 0; m < 2; ++m)
            #pragma unroll
            for (int hh = 0; hh < 2; ++hh) {
                s2[m][hh] += __shfl_xor_sync(0xffffffffu, s2[m][hh], d);
                q2[m][hh] += __shfl_xor_sync(0xffffffffu, q2[m][hh], d);
            }
    float2* red = (float2*)(smc + 102400);
    __syncthreads();
    if (tig == 0)
        #pragma unroll
        for (int m = 0; m < 2; ++m)
            #pragma unroll
            for (int hh = 0; hh < 2; ++hh)
                red[cb * 64 + rb * 32 + m * 16 + hh * 8 + gid] = make_float2(s2[m][hh], q2[m][hh]);
    __syncthreads();
    float mu[2][2], rs[2][2];
    #pragma unroll
    for (int m = 0; m < 2; ++m)
        #pragma unroll
        for (int hh = 0; hh < 2; ++hh) {
            int row = rb * 32 + m * 16 + hh * 8 + gid;
            float ss = 0.f, qq = 0.f;
            #pragma unroll
            for (int b = 0; b < 4; ++b) {
                float2 pr = red[b * 64 + row];
                ss += pr.x; qq += pr.y;
            }
            float m_ = ss * (1.f/192.f);
            mu[m][hh] = m_;
            rs[m][hh] = rsqrtf(qq * (1.f/192.f) - m_*m_ + 1e-5f);
        }

    #pragma unroll
    for (int m = 0; m < 2; ++m) {
        size_t grA = (tok0 + rb * 32 + m * 16 + gid) * 192;
        size_t grB = grA + 8 * 192;
        #pragma unroll
        for (int p = 0; p < 3; ++p)
            #pragma unroll
            for (int hh = 0; hh < 2; ++hh) {
                int col = cb * 48 + p * 16 + hh * 8 + 2 * tig;
                int i = m * 6 + p * 2 + hh;
                float z0 = cf2[i][0] + fc2_b[col];
                float z1 = cf2[i][1] + fc2_b[col+1];
                float z2 = cf2[i][2] + fc2_b[col];
                float z3 = cf2[i][3] + fc2_b[col+1];
                float2 xa = *(const float2*)(g_x1 + grA + col);
                float2 oa;
                oa.x = xa.x + (z0 - mu[m][0]) * rs[m][0] * g2[col]   + b2[col];
                oa.y = xa.y + (z1 - mu[m][0]) * rs[m][0] * g2[col+1] + b2[col+1];
                *(float2*)(out + grA + col) = oa;
                float2 xb = *(const float2*)(g_x1 + grB + col);
                float2 ob;
                ob.x = xb.x + (z2 - mu[m][1]) * rs[m][1] * g2[col]   + b2[col];
                ob.y = xb.y + (z3 - mu[m][1]) * rs[m][1] * g2[col+1] + b2[col+1];
                *(float2*)(out + grB + col) = ob;
            }
    }
}

// ---------------- launch ----------------
extern "C" void kernel_launch(void* const* d_in, const int* in_sizes, int n_in,
                              void* d_out, int out_size) {
    const float* x        = (const float*)d_in[0];
    const float* feat     = (const float*)d_in[1];
    const float* attn_mask= (const float*)d_in[2];
    const int*   rel_index= (const int*)  d_in[3];
    const float* rel_tab  = (const float*)d_in[4];
    const float* q_w      = (const float*)d_in[5];
    const float* q_b      = (const float*)d_in[6];
    const float* kv_w     = (const float*)d_in[7];
    const float* kv_b     = (const float*)d_in[8];
    const float* proj_w   = (const float*)d_in[9];
    const float* proj_b   = (const float*)d_in[10];
    const float* merge_w  = (const float*)d_in[11];
    const float* n1g      = (const float*)d_in[12];
    const float* n1b      = (const float*)d_in[13];
    const float* n2g      = (const float*)d_in[14];
    const float* n2b      = (const float*)d_in[15];
    const float* fc1_w    = (const float*)d_in[16];
    const float* fc1_b    = (const float*)d_in[17];
    const float* fc2_w    = (const float*)d_in[18];
    const float* fc2_b    = (const float*)d_in[19];
    float* out = (float*)d_out;

    cudaFuncSetAttribute(k_qkv_tc,       cudaFuncAttributeMaxDynamicSharedMemorySize, QKV_SMEM);
    cudaFuncSetAttribute(k_attn_tc,      cudaFuncAttributeMaxDynamicSharedMemorySize, ATTN_SMEM);
    cudaFuncSetAttribute(k_projmerge_tc, cudaFuncAttributeMaxDynamicSharedMemorySize, PM_SMEM);
    cudaFuncSetAttribute(k_mlp_tc,       cudaFuncAttributeMaxDynamicSharedMemorySize, MLP_SMEM);

    k_transpose<<<dim3(2048, 6, 8), dim3(32, 8)>>>(x, feat);
    k_biasmask<<<98304, 256>>>(rel_index, rel_tab, attn_mask);
    k_wsplit<<<(WTOT + 255) / 256, 256>>>(q_w, kv_w, proj_w, merge_w, fc1_w, fc2_w);
    k_qkv_tc<<<2048, 512, QKV_SMEM>>>(q_b, kv_b);
    k_attn_tc<<<NWIN * NHEAD, 128, ATTN_SMEM>>>();
    k_projmerge_tc<<<2048, 512, PM_SMEM>>>(proj_b, n1g, n1b);
    k_mlp_tc<<<TOKALL / 64, 256, MLP_SMEM>>>(fc1_b, fc2_b, n2g, n2b, out);
}